// round 1
// baseline (speedup 1.0000x reference)
#include <cuda_runtime.h>

#define T_IN 16
#define T_OUT 25
#define NB 4096
#define KN 32
#define NNBR (NB*KN)
#define ENC 64
#define DEC 128
#define DYN 32
#define EMB 32

// -------- scratch (no allocations allowed) --------
__device__ float g_scene_max[NB*ENC];   // 1 MB
__device__ float g_histe[NB*DYN];       // 0.5 MB
__device__ float g_pre[(size_t)NB*4*DEC]; // 8 MB: bih_d+bhh_d + enc@Wih_d.T

__device__ __forceinline__ float lrelu(float x){ return x >= 0.f ? x : 0.1f*x; }
__device__ __forceinline__ float sigf(float x){ return __fdividef(1.f, 1.f + __expf(-x)); }
__device__ __forceinline__ float tanh_fast(float x){ return 1.f - __fdividef(2.f, 1.f + __expf(2.f*x)); }

// ============================================================
// Kernel 1: neighbor MLP + segment max.  warp = 1 hero, lane = 1 neighbor.
// ============================================================
__global__ void nbr_kernel(const float* __restrict__ hist, const float* __restrict__ nbrs,
                           const float* __restrict__ Wnbr, const float* __restrict__ bnbr,
                           const int* __restrict__ seg)
{
    __shared__ float sW[ENC*32];
    __shared__ float sb[ENC];
    int tid = threadIdx.x;
    for (int i = tid; i < ENC*32; i += 256) sW[i] = Wnbr[i];
    if (tid < ENC) sb[tid] = bnbr[tid];
    __syncthreads();

    int warp = tid >> 5, lane = tid & 31;
    int b = blockIdx.x * 8 + warp;
    int n = b * KN + lane;
    int sgid = seg[n];

    float x[32];
#pragma unroll
    for (int t = 0; t < T_IN; ++t) {
        float2 hv = *(const float2*)(hist + ((size_t)t*NB + sgid)*2);
        float2 nv = *(const float2*)(nbrs + ((size_t)t*NNBR + n)*2);
        x[2*t]   = hv.x - nv.x;
        x[2*t+1] = hv.y - nv.y;
    }
#pragma unroll 4
    for (int g = 0; g < ENC; ++g) {
        float acc = sb[g];
        const float* w = sW + g*32;
#pragma unroll
        for (int k = 0; k < 32; ++k) acc = fmaf(w[k], x[k], acc);
        acc = lrelu(acc);
#pragma unroll
        for (int off = 16; off; off >>= 1)
            acc = fmaxf(acc, __shfl_xor_sync(0xffffffffu, acc, off));
        if (lane == 0) g_scene_max[b*ENC + g] = acc;
    }
}

// ============================================================
// Kernel 2: ego embedding + encoder LSTM (H=64) + hist_e projection.
// 256 threads = 4 heroes x 64 hidden units. Weights in padded smem.
// ============================================================
#define EPI 36   // 32 + pad (pad % 8 == 4 -> conflict-free LDS.128)
#define EPH 68   // 64 + pad
__global__ void enc_kernel(const float* __restrict__ hist,
                           const float* __restrict__ Wip, const float* __restrict__ bip,
                           const float* __restrict__ Wih, const float* __restrict__ Whh,
                           const float* __restrict__ bih, const float* __restrict__ bhh,
                           const float* __restrict__ Wdyn, const float* __restrict__ bdyn)
{
    extern __shared__ float sm[];
    float* sWih = sm;                       // [256][EPI]
    float* sWhh = sm + 256*EPI;             // [256][EPH]
    float* sb   = sWhh + 256*EPH;           // [256]
    float* sEmb = sb + 256;                 // [4][32]
    float* sH   = sEmb + 4*EMB;             // [4][64]

    int tid = threadIdx.x;
    for (int i = tid; i < 256*EMB; i += 256) sWih[(i>>5)*EPI + (i&31)] = Wih[i];
    for (int i = tid; i < 256*ENC; i += 256) sWhh[(i>>6)*EPH + (i&63)] = Whh[i];
    sb[tid] = bih[tid] + bhh[tid];
    sH[tid] = 0.f;                          // 4*64 == 256

    int hl = tid >> 6, j = tid & 63;
    int b = blockIdx.x*4 + hl;
    float wip0 = 0.f, wip1 = 0.f, bipj = 0.f;
    if (j < EMB) { wip0 = Wip[j*2]; wip1 = Wip[j*2+1]; bipj = bip[j]; }
    float c = 0.f;
    __syncthreads();

    for (int t = 0; t < T_IN; ++t) {
        if (j < EMB) {
            const float* hp = hist + ((size_t)t*NB + b)*2;
            sEmb[hl*EMB + j] = lrelu(fmaf(wip0, hp[0], fmaf(wip1, hp[1], bipj)));
        }
        __syncthreads();
        float acc[4];
#pragma unroll
        for (int g = 0; g < 4; ++g) {
            int row = g*ENC + j;
            float a = sb[row];
            const float4* wr = (const float4*)(sWih + row*EPI);
            const float4* er = (const float4*)(sEmb + hl*EMB);
#pragma unroll
            for (int kk = 0; kk < EMB/4; ++kk) {
                float4 w = wr[kk], e = er[kk];
                a = fmaf(w.x,e.x,a); a = fmaf(w.y,e.y,a);
                a = fmaf(w.z,e.z,a); a = fmaf(w.w,e.w,a);
            }
            const float4* wr2 = (const float4*)(sWhh + row*EPH);
            const float4* hr  = (const float4*)(sH + hl*ENC);
#pragma unroll
            for (int kk = 0; kk < ENC/4; ++kk) {
                float4 w = wr2[kk], h4 = hr[kk];
                a = fmaf(w.x,h4.x,a); a = fmaf(w.y,h4.y,a);
                a = fmaf(w.z,h4.z,a); a = fmaf(w.w,h4.w,a);
            }
            acc[g] = a;
        }
        float ig = sigf(acc[0]), fg = sigf(acc[1]);
        float gg = tanh_fast(acc[2]), og = sigf(acc[3]);
        c = fmaf(fg, c, ig*gg);
        float hnew = og * tanh_fast(c);
        __syncthreads();
        sH[hl*ENC + j] = hnew;
    }
    __syncthreads();
    if (j < DYN) {
        float a = __ldg(bdyn + j);
        const float4* wd = (const float4*)(Wdyn + j*ENC);
        const float4* hr = (const float4*)(sH + hl*ENC);
#pragma unroll
        for (int kk = 0; kk < ENC/4; ++kk) {
            float4 w = __ldg(wd+kk); float4 h4 = hr[kk];
            a = fmaf(w.x,h4.x,a); a = fmaf(w.y,h4.y,a);
            a = fmaf(w.z,h4.z,a); a = fmaf(w.w,h4.w,a);
        }
        g_histe[b*DYN + j] = lrelu(a);
    }
}

// ============================================================
// Kernel 3: scene projection + decoder-input precompute
//   pre[b][row] = bih_d[row]+bhh_d[row] + enc[b] . Wih_d[row]
// 512 threads, 16 heroes/block; thread = gate row, blocked over heroes.
// ============================================================
__global__ void mid_kernel(const float* __restrict__ Wdyn, const float* __restrict__ bdyn,
                           const float* __restrict__ Wih_d, const float* __restrict__ bih_d,
                           const float* __restrict__ bhh_d)
{
    __shared__ float sEnc[16][64];   // [0:32)=hist_e, [32:64)=scene
    __shared__ float sMax[16][64];
    int tid = threadIdx.x;
    int b0 = blockIdx.x * 16;
    for (int i = tid; i < 16*64; i += 512) sMax[i>>6][i&63] = g_scene_max[b0*ENC + i];
    for (int i = tid; i < 16*32; i += 512) sEnc[i>>5][i&31] = g_histe[b0*DYN + i];
    __syncthreads();
    {
        int hl = tid >> 5, j = tid & 31;
        float a = __ldg(bdyn + j);
        const float4* wd = (const float4*)(Wdyn + j*ENC);
#pragma unroll
        for (int kk = 0; kk < ENC/4; ++kk) {
            float4 w = __ldg(wd+kk);
            float4 m = *(const float4*)&sMax[hl][kk*4];
            a = fmaf(w.x,m.x,a); a = fmaf(w.y,m.y,a);
            a = fmaf(w.z,m.z,a); a = fmaf(w.w,m.w,a);
        }
        sEnc[hl][32 + j] = lrelu(a);
    }
    __syncthreads();
    int row = tid;
    float acc[16];
    float bsum = __ldg(bih_d + row) + __ldg(bhh_d + row);
#pragma unroll
    for (int hl = 0; hl < 16; ++hl) acc[hl] = bsum;
    const float4* w = (const float4*)(Wih_d + row*64);
#pragma unroll
    for (int kk = 0; kk < 16; ++kk) {
        float4 wv = __ldg(w + kk);
#pragma unroll
        for (int hl = 0; hl < 16; ++hl) {
            float4 e = *(const float4*)&sEnc[hl][kk*4];
            acc[hl] = fmaf(wv.x,e.x,acc[hl]); acc[hl] = fmaf(wv.y,e.y,acc[hl]);
            acc[hl] = fmaf(wv.z,e.z,acc[hl]); acc[hl] = fmaf(wv.w,e.w,acc[hl]);
        }
    }
#pragma unroll
    for (int hl = 0; hl < 16; ++hl)
        g_pre[(size_t)(b0+hl)*512 + row] = acc[hl];
}

// ============================================================
// Kernel 4: decoder LSTM (H=128, 25 steps) + output projection.
// 128 threads = hidden units; each thread handles 16 heroes (weight reuse 16x).
// Whh_d (256 KB) streamed from L1/L2; h + pre in smem.
// ============================================================
__global__ void __launch_bounds__(128) dec_kernel(const float* __restrict__ Whh,
                           const float* __restrict__ Wop, const float* __restrict__ bop,
                           float* __restrict__ out)
{
    __shared__ float sPre[16*512];   // 32 KB
    __shared__ float sH[16*DEC];     // 8 KB
    __shared__ float sWop[2*DEC];

    int tid = threadIdx.x;           // 0..127
    int b0 = blockIdx.x * 16;
    for (int i = tid; i < 16*512; i += 128) sPre[i] = g_pre[(size_t)b0*512 + i];
    for (int i = tid; i < 2*DEC; i += 128) sWop[i] = Wop[i];
    for (int i = tid; i < 16*DEC; i += 128) sH[i] = 0.f;
    float c[16];
#pragma unroll
    for (int hl = 0; hl < 16; ++hl) c[hl] = 0.f;

    const float4* w0 = (const float4*)(Whh + (size_t)(0*DEC + tid)*DEC);
    const float4* w1 = (const float4*)(Whh + (size_t)(1*DEC + tid)*DEC);
    const float4* w2 = (const float4*)(Whh + (size_t)(2*DEC + tid)*DEC);
    const float4* w3 = (const float4*)(Whh + (size_t)(3*DEC + tid)*DEC);
    __syncthreads();

    for (int t = 0; t < T_OUT; ++t) {
        float a0[16], a1[16], a2[16], a3[16];
#pragma unroll
        for (int hl = 0; hl < 16; ++hl) {
            a0[hl] = sPre[hl*512 + 0*DEC + tid];
            a1[hl] = sPre[hl*512 + 1*DEC + tid];
            a2[hl] = sPre[hl*512 + 2*DEC + tid];
            a3[hl] = sPre[hl*512 + 3*DEC + tid];
        }
#pragma unroll 2
        for (int kk = 0; kk < DEC/4; ++kk) {
            float4 v0 = __ldg(w0+kk), v1 = __ldg(w1+kk);
            float4 v2 = __ldg(w2+kk), v3 = __ldg(w3+kk);
#pragma unroll
            for (int hl = 0; hl < 16; ++hl) {
                float4 h4 = *(const float4*)(sH + hl*DEC + kk*4);
                a0[hl]=fmaf(v0.x,h4.x,a0[hl]); a0[hl]=fmaf(v0.y,h4.y,a0[hl]);
                a0[hl]=fmaf(v0.z,h4.z,a0[hl]); a0[hl]=fmaf(v0.w,h4.w,a0[hl]);
                a1[hl]=fmaf(v1.x,h4.x,a1[hl]); a1[hl]=fmaf(v1.y,h4.y,a1[hl]);
                a1[hl]=fmaf(v1.z,h4.z,a1[hl]); a1[hl]=fmaf(v1.w,h4.w,a1[hl]);
                a2[hl]=fmaf(v2.x,h4.x,a2[hl]); a2[hl]=fmaf(v2.y,h4.y,a2[hl]);
                a2[hl]=fmaf(v2.z,h4.z,a2[hl]); a2[hl]=fmaf(v2.w,h4.w,a2[hl]);
                a3[hl]=fmaf(v3.x,h4.x,a3[hl]); a3[hl]=fmaf(v3.y,h4.y,a3[hl]);
                a3[hl]=fmaf(v3.z,h4.z,a3[hl]); a3[hl]=fmaf(v3.w,h4.w,a3[hl]);
            }
        }
        __syncthreads();   // all reads of old sH done
#pragma unroll
        for (int hl = 0; hl < 16; ++hl) {
            float ig = sigf(a0[hl]), fg = sigf(a1[hl]);
            float gg = tanh_fast(a2[hl]), og = sigf(a3[hl]);
            c[hl] = fmaf(fg, c[hl], ig*gg);
            sH[hl*DEC + tid] = og * tanh_fast(c[hl]);
        }
        __syncthreads();   // new sH visible
        if (tid < 32) {
            int hl = tid >> 1, d = tid & 1;
            float a = __ldg(bop + d);
            const float4* wo = (const float4*)(sWop + d*DEC);
#pragma unroll
            for (int kk = 0; kk < DEC/4; ++kk) {
                float4 wv = wo[kk];
                float4 h4 = *(const float4*)(sH + hl*DEC + kk*4);
                a = fmaf(wv.x,h4.x,a); a = fmaf(wv.y,h4.y,a);
                a = fmaf(wv.z,h4.z,a); a = fmaf(wv.w,h4.w,a);
            }
            out[(size_t)t*NB*2 + (size_t)(b0+hl)*2 + d] = a;
        }
    }
}

// ============================================================
extern "C" void kernel_launch(void* const* d_in, const int* in_sizes, int n_in,
                              void* d_out, int out_size)
{
    const float* hist  = (const float*)d_in[0];
    const float* nbrs  = (const float*)d_in[1];
    const float* Wip   = (const float*)d_in[2];
    const float* bip   = (const float*)d_in[3];
    const float* Wih_e = (const float*)d_in[4];
    const float* Whh_e = (const float*)d_in[5];
    const float* bih_e = (const float*)d_in[6];
    const float* bhh_e = (const float*)d_in[7];
    const float* Wdyn  = (const float*)d_in[8];
    const float* bdyn  = (const float*)d_in[9];
    const float* Wnbr  = (const float*)d_in[10];
    const float* bnbr  = (const float*)d_in[11];
    const float* Wih_d = (const float*)d_in[12];
    const float* Whh_d = (const float*)d_in[13];
    const float* bih_d = (const float*)d_in[14];
    const float* bhh_d = (const float*)d_in[15];
    const float* Wop   = (const float*)d_in[16];
    const float* bop   = (const float*)d_in[17];
    const int*   seg   = (const int*)d_in[18];
    float* out = (float*)d_out;

    constexpr int ENC_SMEM = (256*EPI + 256*EPH + 256 + 4*EMB + 4*ENC) * (int)sizeof(float);
    cudaFuncSetAttribute(enc_kernel, cudaFuncAttributeMaxDynamicSharedMemorySize, ENC_SMEM);

    nbr_kernel<<<NB/8, 256>>>(hist, nbrs, Wnbr, bnbr, seg);
    enc_kernel<<<NB/4, 256, ENC_SMEM>>>(hist, Wip, bip, Wih_e, Whh_e, bih_e, bhh_e, Wdyn, bdyn);
    mid_kernel<<<NB/16, 512>>>(Wdyn, bdyn, Wih_d, bih_d, bhh_d);
    dec_kernel<<<NB/16, 128>>>(Whh_d, Wop, bop, out);
}

// round 2
// speedup vs baseline: 1.1974x; 1.1974x over previous
#include <cuda_runtime.h>

#define T_IN 16
#define T_OUT 25
#define NB 4096
#define KN 32
#define NNBR (NB*KN)
#define ENC 64
#define DEC 128
#define DYN 32
#define EMB 32
#define HL 8           // heroes per decoder block

typedef unsigned long long u64;

// -------- scratch (no allocations allowed) --------
__device__ float g_scene_max[NB*ENC];                 // 1 MB
__device__ float g_histe[NB*DYN];                     // 0.5 MB
__device__ __align__(16) float g_pre[(size_t)NB*4*DEC];   // 8 MB
__device__ __align__(16) float g_Wpair[4*DEC*DEC];        // 256 KB pair-transposed Whh_d

__device__ __forceinline__ float lrelu(float x){ return x >= 0.f ? x : 0.1f*x; }
__device__ __forceinline__ float sigf(float x){ return __fdividef(1.f, 1.f + __expf(-x)); }
__device__ __forceinline__ float tanh_fast(float x){ return 1.f - __fdividef(2.f, 1.f + __expf(2.f*x)); }

// packed 2xf32 FMA: d = a*b + d (elementwise on the two lanes)
__device__ __forceinline__ void fma2(u64& d, u64 a, u64 b){
    asm("fma.rn.f32x2 %0, %1, %2, %0;" : "+l"(d) : "l"(a), "l"(b));
}
__device__ __forceinline__ u64 packf2(float x, float y){
    u64 r; asm("mov.b64 %0, {%1,%2};" : "=l"(r) : "f"(x), "f"(y)); return r;
}
__device__ __forceinline__ float red2(u64 a){
    float x, y; asm("mov.b64 {%0,%1}, %2;" : "=f"(x), "=f"(y) : "l"(a)); return x + y;
}
// init packed acc as {bias, 0}
__device__ __forceinline__ u64 lo2(float x){ return (u64)__float_as_uint(x); }

// ============================================================
// Kernel 0: pair-transpose Whh_d [512][128] -> g_Wpair[k2][512][2]
// ============================================================
__global__ void prep_kernel(const float* __restrict__ Whh)
{
    int idx = blockIdx.x*256 + threadIdx.x;   // 0..32767 = 64 k2 * 512 rows
    int k2 = idx >> 9, r = idx & 511;
    float2 v = *(const float2*)(Whh + r*DEC + k2*2);
    *(float2*)(g_Wpair + ((size_t)k2*512 + r)*2) = v;
}

// ============================================================
// Kernel 1: neighbor MLP + segment max.  warp = 1 hero, lane = 1 neighbor.
// ============================================================
__global__ void nbr_kernel(const float* __restrict__ hist, const float* __restrict__ nbrs,
                           const float* __restrict__ Wnbr, const float* __restrict__ bnbr,
                           const int* __restrict__ seg)
{
    __shared__ __align__(16) float sW[ENC*32];
    __shared__ float sb[ENC];
    int tid = threadIdx.x;
    for (int i = tid; i < ENC*32; i += 256) sW[i] = Wnbr[i];
    if (tid < ENC) sb[tid] = bnbr[tid];
    __syncthreads();

    int warp = tid >> 5, lane = tid & 31;
    int b = blockIdx.x * 8 + warp;
    int n = b * KN + lane;
    int sgid = seg[n];

    u64 xp[16];
#pragma unroll
    for (int t = 0; t < T_IN; ++t) {
        float2 hv = *(const float2*)(hist + ((size_t)t*NB + sgid)*2);
        float2 nv = *(const float2*)(nbrs + ((size_t)t*NNBR + n)*2);
        xp[t] = packf2(hv.x - nv.x, hv.y - nv.y);
    }
#pragma unroll 4
    for (int g = 0; g < ENC; ++g) {
        u64 a2 = lo2(sb[g]);
        const u64* w = (const u64*)(sW + g*32);
#pragma unroll
        for (int k = 0; k < 16; ++k) fma2(a2, w[k], xp[k]);
        float acc = lrelu(red2(a2));
#pragma unroll
        for (int off = 16; off; off >>= 1)
            acc = fmaxf(acc, __shfl_xor_sync(0xffffffffu, acc, off));
        if (lane == 0) g_scene_max[b*ENC + g] = acc;
    }
}

// ============================================================
// Kernel 2: ego embedding + encoder LSTM (H=64) + hist_e projection.
// 256 threads = 4 heroes x 64 hidden units.  f32x2 packed dot products.
// ============================================================
#define EPI 36   // 36 floats = 144 B (16B aligned), stride%8==4 -> conflict-free
#define EPH 68   // 272 B, 16B aligned
__global__ void enc_kernel(const float* __restrict__ hist,
                           const float* __restrict__ Wip, const float* __restrict__ bip,
                           const float* __restrict__ Wih, const float* __restrict__ Whh,
                           const float* __restrict__ bih, const float* __restrict__ bhh,
                           const float* __restrict__ Wdyn, const float* __restrict__ bdyn)
{
    extern __shared__ __align__(16) float sm[];
    float* sWih = sm;                       // [256][EPI]
    float* sWhh = sm + 256*EPI;             // [256][EPH]
    float* sb   = sWhh + 256*EPH;           // [256]
    float* sEmb = sb + 256;                 // [4][32]
    float* sH   = sEmb + 4*EMB;             // [4][64]

    int tid = threadIdx.x;
    for (int i = tid; i < 256*EMB; i += 256) sWih[(i>>5)*EPI + (i&31)] = Wih[i];
    for (int i = tid; i < 256*ENC; i += 256) sWhh[(i>>6)*EPH + (i&63)] = Whh[i];
    sb[tid] = bih[tid] + bhh[tid];
    sH[tid] = 0.f;                          // 4*64 == 256

    int hl = tid >> 6, j = tid & 63;
    int b = blockIdx.x*4 + hl;
    float wip0 = 0.f, wip1 = 0.f, bipj = 0.f;
    if (j < EMB) { wip0 = Wip[j*2]; wip1 = Wip[j*2+1]; bipj = bip[j]; }
    float c = 0.f;
    __syncthreads();

    for (int t = 0; t < T_IN; ++t) {
        if (j < EMB) {
            const float* hp = hist + ((size_t)t*NB + b)*2;
            sEmb[hl*EMB + j] = lrelu(fmaf(wip0, hp[0], fmaf(wip1, hp[1], bipj)));
        }
        __syncthreads();
        float acc[4];
#pragma unroll
        for (int g = 0; g < 4; ++g) {
            int row = g*ENC + j;
            u64 a2 = lo2(sb[row]);
            const ulonglong2* wr = (const ulonglong2*)(sWih + row*EPI);
            const ulonglong2* er = (const ulonglong2*)(sEmb + hl*EMB);
#pragma unroll
            for (int kk = 0; kk < EMB/4; ++kk) {
                ulonglong2 w = wr[kk], e = er[kk];
                fma2(a2, w.x, e.x); fma2(a2, w.y, e.y);
            }
            const ulonglong2* wr2 = (const ulonglong2*)(sWhh + row*EPH);
            const ulonglong2* hr  = (const ulonglong2*)(sH + hl*ENC);
#pragma unroll
            for (int kk = 0; kk < ENC/4; ++kk) {
                ulonglong2 w = wr2[kk], h2 = hr[kk];
                fma2(a2, w.x, h2.x); fma2(a2, w.y, h2.y);
            }
            acc[g] = red2(a2);
        }
        float ig = sigf(acc[0]), fg = sigf(acc[1]);
        float gg = tanh_fast(acc[2]), og = sigf(acc[3]);
        c = fmaf(fg, c, ig*gg);
        float hnew = og * tanh_fast(c);
        __syncthreads();
        sH[hl*ENC + j] = hnew;
    }
    __syncthreads();
    if (j < DYN) {
        u64 a2 = lo2(__ldg(bdyn + j));
        const ulonglong2* wd = (const ulonglong2*)(Wdyn + j*ENC);
        const ulonglong2* hr = (const ulonglong2*)(sH + hl*ENC);
#pragma unroll
        for (int kk = 0; kk < ENC/4; ++kk) {
            ulonglong2 w = wd[kk], h2 = hr[kk];
            fma2(a2, w.x, h2.x); fma2(a2, w.y, h2.y);
        }
        g_histe[b*DYN + j] = lrelu(red2(a2));
    }
}

// ============================================================
// Kernel 3: scene projection + decoder-input precompute (unchanged)
// ============================================================
__global__ void mid_kernel(const float* __restrict__ Wdyn, const float* __restrict__ bdyn,
                           const float* __restrict__ Wih_d, const float* __restrict__ bih_d,
                           const float* __restrict__ bhh_d)
{
    __shared__ __align__(16) float sEnc[16][64];
    __shared__ __align__(16) float sMax[16][64];
    int tid = threadIdx.x;
    int b0 = blockIdx.x * 16;
    for (int i = tid; i < 16*64; i += 512) sMax[i>>6][i&63] = g_scene_max[b0*ENC + i];
    for (int i = tid; i < 16*32; i += 512) sEnc[i>>5][i&31] = g_histe[b0*DYN + i];
    __syncthreads();
    {
        int hl = tid >> 5, j = tid & 31;
        float a = __ldg(bdyn + j);
        const float4* wd = (const float4*)(Wdyn + j*ENC);
#pragma unroll
        for (int kk = 0; kk < ENC/4; ++kk) {
            float4 w = __ldg(wd+kk);
            float4 m = *(const float4*)&sMax[hl][kk*4];
            a = fmaf(w.x,m.x,a); a = fmaf(w.y,m.y,a);
            a = fmaf(w.z,m.z,a); a = fmaf(w.w,m.w,a);
        }
        sEnc[hl][32 + j] = lrelu(a);
    }
    __syncthreads();
    int row = tid;
    float acc[16];
    float bsum = __ldg(bih_d + row) + __ldg(bhh_d + row);
#pragma unroll
    for (int hl = 0; hl < 16; ++hl) acc[hl] = bsum;
    const float4* w = (const float4*)(Wih_d + row*64);
#pragma unroll
    for (int kk = 0; kk < 16; ++kk) {
        float4 wv = __ldg(w + kk);
#pragma unroll
        for (int hl = 0; hl < 16; ++hl) {
            float4 e = *(const float4*)&sEnc[hl][kk*4];
            acc[hl] = fmaf(wv.x,e.x,acc[hl]); acc[hl] = fmaf(wv.y,e.y,acc[hl]);
            acc[hl] = fmaf(wv.z,e.z,acc[hl]); acc[hl] = fmaf(wv.w,e.w,acc[hl]);
        }
    }
#pragma unroll
    for (int hl = 0; hl < 16; ++hl)
        g_pre[(size_t)(b0+hl)*512 + row] = acc[hl];
}

// ============================================================
// Kernel 4: decoder LSTM (H=128, 25 steps) + output projection.
// 128 threads = hidden units (4 gate rows each); HL=8 heroes per block.
// Weights read coalesced from pair-transposed g_Wpair; k-packed f32x2 FMA.
// ============================================================
__global__ void __launch_bounds__(128, 4) dec_kernel(const float* __restrict__ Wop,
                                                     const float* __restrict__ bop,
                                                     float* __restrict__ out)
{
    __shared__ __align__(16) float sPre[HL*512];   // 16 KB
    __shared__ __align__(16) float sH[HL*DEC];     // 4 KB
    __shared__ float sWop[2*DEC];

    int tid = threadIdx.x;           // 0..127
    int b0 = blockIdx.x * HL;
    for (int i = tid; i < HL*512; i += 128) sPre[i] = g_pre[(size_t)b0*512 + i];
    for (int i = tid; i < 2*DEC; i += 128) sWop[i] = Wop[i];
    for (int i = tid; i < HL*DEC; i += 128) sH[i] = 0.f;
    float c[HL];
#pragma unroll
    for (int hl = 0; hl < HL; ++hl) c[hl] = 0.f;
    __syncthreads();

    for (int t = 0; t < T_OUT; ++t) {
        u64 acc[4][HL];
#pragma unroll
        for (int g = 0; g < 4; ++g)
#pragma unroll
            for (int hl = 0; hl < HL; ++hl)
                acc[g][hl] = lo2(sPre[hl*512 + g*DEC + tid]);

#pragma unroll 2
        for (int kk = 0; kk < DEC/4; ++kk) {       // 4 k per iter = 2 k-pairs
            int k2 = kk*2;
            u64 w[4][2];
#pragma unroll
            for (int g = 0; g < 4; ++g) {
                w[g][0] = *(const u64*)(g_Wpair + ((size_t)(k2  )*512 + g*DEC + tid)*2);
                w[g][1] = *(const u64*)(g_Wpair + ((size_t)(k2+1)*512 + g*DEC + tid)*2);
            }
#pragma unroll
            for (int hl = 0; hl < HL; ++hl) {
                ulonglong2 hv = *(const ulonglong2*)(sH + hl*DEC + kk*4);
#pragma unroll
                for (int g = 0; g < 4; ++g) {
                    fma2(acc[g][hl], w[g][0], hv.x);
                    fma2(acc[g][hl], w[g][1], hv.y);
                }
            }
        }
        __syncthreads();   // all reads of old sH done
#pragma unroll
        for (int hl = 0; hl < HL; ++hl) {
            float ig = sigf(red2(acc[0][hl])), fg = sigf(red2(acc[1][hl]));
            float gg = tanh_fast(red2(acc[2][hl])), og = sigf(red2(acc[3][hl]));
            c[hl] = fmaf(fg, c[hl], ig*gg);
            sH[hl*DEC + tid] = og * tanh_fast(c[hl]);
        }
        __syncthreads();   // new sH visible
        if (tid < 2*HL) {
            int hl = tid >> 1, d = tid & 1;
            float a = __ldg(bop + d);
            const ulonglong2* wo = (const ulonglong2*)(sWop + d*DEC);
            const ulonglong2* hr = (const ulonglong2*)(sH + hl*DEC);
            u64 a2 = lo2(a);
#pragma unroll
            for (int kk = 0; kk < DEC/4; ++kk) {
                ulonglong2 w = wo[kk], h2 = hr[kk];
                fma2(a2, w.x, h2.x); fma2(a2, w.y, h2.y);
            }
            out[(size_t)t*NB*2 + (size_t)(b0+hl)*2 + d] = red2(a2);
        }
    }
}

// ============================================================
extern "C" void kernel_launch(void* const* d_in, const int* in_sizes, int n_in,
                              void* d_out, int out_size)
{
    const float* hist  = (const float*)d_in[0];
    const float* nbrs  = (const float*)d_in[1];
    const float* Wip   = (const float*)d_in[2];
    const float* bip   = (const float*)d_in[3];
    const float* Wih_e = (const float*)d_in[4];
    const float* Whh_e = (const float*)d_in[5];
    const float* bih_e = (const float*)d_in[6];
    const float* bhh_e = (const float*)d_in[7];
    const float* Wdyn  = (const float*)d_in[8];
    const float* bdyn  = (const float*)d_in[9];
    const float* Wnbr  = (const float*)d_in[10];
    const float* bnbr  = (const float*)d_in[11];
    const float* Wih_d = (const float*)d_in[12];
    const float* Whh_d = (const float*)d_in[13];
    const float* bih_d = (const float*)d_in[14];
    const float* bhh_d = (const float*)d_in[15];
    const float* Wop   = (const float*)d_in[16];
    const float* bop   = (const float*)d_in[17];
    const int*   seg   = (const int*)d_in[18];
    float* out = (float*)d_out;

    constexpr int ENC_SMEM = (256*EPI + 256*EPH + 256 + 4*EMB + 4*ENC) * (int)sizeof(float);
    cudaFuncSetAttribute(enc_kernel, cudaFuncAttributeMaxDynamicSharedMemorySize, ENC_SMEM);

    prep_kernel<<<128, 256>>>(Whh_d);
    nbr_kernel<<<NB/8, 256>>>(hist, nbrs, Wnbr, bnbr, seg);
    enc_kernel<<<NB/4, 256, ENC_SMEM>>>(hist, Wip, bip, Wih_e, Whh_e, bih_e, bhh_e, Wdyn, bdyn);
    mid_kernel<<<NB/16, 512>>>(Wdyn, bdyn, Wih_d, bih_d, bhh_d);
    dec_kernel<<<NB/HL, 128>>>(Wop, bop, out);
}

// round 3
// speedup vs baseline: 1.2024x; 1.0042x over previous
#include <cuda_runtime.h>

#define T_IN 16
#define T_OUT 25
#define NB 4096
#define KN 32
#define NNBR (NB*KN)
#define ENC 64
#define DEC 128
#define DYN 32
#define EMB 32
#define HL 8           // heroes per decoder block

typedef unsigned long long u64;

// -------- scratch (no allocations allowed) --------
__device__ float g_scene_max[NB*ENC];                     // 1 MB
__device__ float g_henc[NB*ENC];                          // raw encoder h_T, 1 MB
__device__ __align__(16) float g_preE[(size_t)T_IN*NB*256];   // 67 MB encoder input-GEMM
__device__ __align__(16) float g_pre[(size_t)NB*4*DEC];       // 8 MB decoder input-GEMM
__device__ __align__(16) float g_Wpair[4*DEC*DEC];            // 256 KB pair-transposed Whh_d
__device__ __align__(16) float g_Wd2[4*DEC*(2*DYN)];          // 128 KB pair-transposed Wih_d

__device__ __forceinline__ float lrelu(float x){ return x >= 0.f ? x : 0.1f*x; }
__device__ __forceinline__ float sigf(float x){ return __fdividef(1.f, 1.f + __expf(-x)); }
__device__ __forceinline__ float tanh_fast(float x){ return 1.f - __fdividef(2.f, 1.f + __expf(2.f*x)); }

__device__ __forceinline__ void fma2(u64& d, u64 a, u64 b){
    asm("fma.rn.f32x2 %0, %1, %2, %0;" : "+l"(d) : "l"(a), "l"(b));
}
__device__ __forceinline__ u64 packf2(float x, float y){
    u64 r; asm("mov.b64 %0, {%1,%2};" : "=l"(r) : "f"(x), "f"(y)); return r;
}
__device__ __forceinline__ float red2(u64 a){
    float x, y; asm("mov.b64 {%0,%1}, %2;" : "=f"(x), "=f"(y) : "l"(a)); return x + y;
}
__device__ __forceinline__ u64 lo2(float x){ return (u64)__float_as_uint(x); }

// ============================================================
// Kernel 0: pair-transpose Whh_d [512][128] and Wih_d [512][64]
// ============================================================
__global__ void prep_kernel(const float* __restrict__ Whh, const float* __restrict__ Wih)
{
    int idx = blockIdx.x*256 + threadIdx.x;
    if (idx < 4*DEC*DEC/2) {                       // 32768: Whh pairs
        int k2 = idx >> 9, r = idx & 511;
        float2 v = *(const float2*)(Whh + r*DEC + k2*2);
        *(float2*)(g_Wpair + ((size_t)k2*512 + r)*2) = v;
    } else {
        int j = idx - 4*DEC*DEC/2;                 // 16384: Wih_d pairs
        if (j < 4*DEC*DYN) {
            int k2 = j >> 9, r = j & 511;
            float2 v = *(const float2*)(Wih + r*(2*DYN) + k2*2);
            *(float2*)(g_Wd2 + ((size_t)k2*512 + r)*2) = v;
        }
    }
}

// ============================================================
// Kernel 1: neighbor MLP + segment max.  warp = 1 hero, lane = 1 neighbor.
// ============================================================
__global__ void nbr_kernel(const float* __restrict__ hist, const float* __restrict__ nbrs,
                           const float* __restrict__ Wnbr, const float* __restrict__ bnbr,
                           const int* __restrict__ seg)
{
    __shared__ __align__(16) float sW[ENC*32];
    __shared__ float sb[ENC];
    int tid = threadIdx.x;
    for (int i = tid; i < ENC*32; i += 256) sW[i] = Wnbr[i];
    if (tid < ENC) sb[tid] = bnbr[tid];
    __syncthreads();

    int warp = tid >> 5, lane = tid & 31;
    int b = blockIdx.x * 8 + warp;
    int n = b * KN + lane;
    int sgid = seg[n];

    u64 xp[16];
#pragma unroll
    for (int t = 0; t < T_IN; ++t) {
        float2 hv = *(const float2*)(hist + ((size_t)t*NB + sgid)*2);
        float2 nv = *(const float2*)(nbrs + ((size_t)t*NNBR + n)*2);
        xp[t] = packf2(hv.x - nv.x, hv.y - nv.y);
    }
#pragma unroll 4
    for (int g = 0; g < ENC; ++g) {
        u64 a2 = lo2(sb[g]);
        const u64* w = (const u64*)(sW + g*32);
#pragma unroll
        for (int k = 0; k < 16; ++k) fma2(a2, w[k], xp[k]);
        float acc = lrelu(red2(a2));
#pragma unroll
        for (int off = 16; off; off >>= 1)
            acc = fmaxf(acc, __shfl_xor_sync(0xffffffffu, acc, off));
        if (lane == 0) g_scene_max[b*ENC + g] = acc;
    }
}

// ============================================================
// Kernel 2a: encoder input GEMM, parallel over t.
//   preE[t][b][r] = bih_e[r]+bhh_e[r] + Wih_e[r] . lrelu(Wip@hist_t + bip)
// 256 threads = 256 gate rows; 8 heroes/block; grid (512, 16).
// ============================================================
__global__ void enc_pre_kernel(const float* __restrict__ hist,
                               const float* __restrict__ Wip, const float* __restrict__ bip,
                               const float* __restrict__ Wih,
                               const float* __restrict__ bih, const float* __restrict__ bhh)
{
    __shared__ __align__(16) float sEmb[8][EMB];
    int tid = threadIdx.x;
    int t = blockIdx.y;
    int b0 = blockIdx.x * 8;
    {
        int hl = tid >> 5, j = tid & 31;
        const float* hp = hist + ((size_t)t*NB + b0 + hl)*2;
        sEmb[hl][j] = lrelu(fmaf(Wip[j*2], hp[0], fmaf(Wip[j*2+1], hp[1], bip[j])));
    }
    int r = tid;
    u64 w[16];
    const u64* wrow = (const u64*)(Wih + r*EMB);
#pragma unroll
    for (int i = 0; i < 16; ++i) w[i] = wrow[i];
    float bsum = __ldg(bih + r) + __ldg(bhh + r);
    u64 acc[8];
#pragma unroll
    for (int hl = 0; hl < 8; ++hl) acc[hl] = lo2(bsum);
    __syncthreads();
#pragma unroll
    for (int k2 = 0; k2 < 16; ++k2) {
#pragma unroll
        for (int hl = 0; hl < 8; ++hl) {
            u64 hv = *(const u64*)&sEmb[hl][k2*2];
            fma2(acc[hl], w[k2], hv);
        }
    }
    float* dst = g_preE + ((size_t)t*NB + b0)*256 + r;
#pragma unroll
    for (int hl = 0; hl < 8; ++hl) dst[hl*256] = red2(acc[hl]);
}

// ============================================================
// Kernel 2b: encoder recurrence. 256 threads = 256 gate rows (g=r>>6,u=r&63);
// Whh_e row in registers; 8 heroes/block; grid 512.
// Thread (g,u) owns c-state for heroes hl=g and hl=g+4.
// ============================================================
__global__ void __launch_bounds__(256) enc_rec_kernel(const float* __restrict__ Whh)
{
    __shared__ __align__(16) float sH[2][8][ENC];   // 4 KB double-buffered h
    __shared__ __align__(16) float sG[4][8][ENC];   // 8 KB gate exchange
    int tid = threadIdx.x;
    int b0 = blockIdx.x * 8;
    int g = tid >> 6, u = tid & 63;

    u64 w[32];
    const u64* wrow = (const u64*)(Whh + tid*ENC);
#pragma unroll
    for (int i = 0; i < 32; ++i) w[i] = wrow[i];

    sH[0][tid>>6][tid&63] = 0.f;   // only 256 of 512 slots...
    sH[0][(tid+256)>>6][tid&63] = 0.f;
    float c0 = 0.f, c1 = 0.f;
    __syncthreads();

    for (int t = 0; t < T_IN; ++t) {
        int cur = t & 1, nxt = cur ^ 1;
        u64 acc[8];
        const float* pe = g_preE + ((size_t)t*NB + b0)*256 + tid;
#pragma unroll
        for (int hl = 0; hl < 8; ++hl) acc[hl] = lo2(__ldg(pe + hl*256));
#pragma unroll 8
        for (int k2 = 0; k2 < 32; ++k2) {
#pragma unroll
            for (int hl = 0; hl < 8; ++hl) {
                u64 hv = *(const u64*)&sH[cur][hl][k2*2];
                fma2(acc[hl], w[k2], hv);
            }
        }
#pragma unroll
        for (int hl = 0; hl < 8; ++hl) sG[g][hl][u] = red2(acc[hl]);
        __syncthreads();
        // activation for items (hl=g) and (hl=g+4)
        {
            float ii = sG[0][g][u], ff = sG[1][g][u], gg = sG[2][g][u], oo = sG[3][g][u];
            c0 = fmaf(sigf(ff), c0, sigf(ii)*tanh_fast(gg));
            sH[nxt][g][u] = sigf(oo)*tanh_fast(c0);
            int h2 = g + 4;
            float i2 = sG[0][h2][u], f2 = sG[1][h2][u], g2 = sG[2][h2][u], o2 = sG[3][h2][u];
            c1 = fmaf(sigf(f2), c1, sigf(i2)*tanh_fast(g2));
            sH[nxt][h2][u] = sigf(o2)*tanh_fast(c1);
        }
        __syncthreads();
    }
    // final h is in sH[T_IN & 1] = sH[0]
    g_henc[b0*ENC + tid] = sH[0][tid>>6][tid&63];
    g_henc[b0*ENC + 256 + tid] = sH[0][(tid+256)>>6][tid&63];
}

// ============================================================
// Kernel 3: Wdyn projections (hist_e, scene) + decoder-input GEMM.
// 512 threads, 16 heroes/block, grid 256.
// ============================================================
__global__ void mid_kernel(const float* __restrict__ Wdyn, const float* __restrict__ bdyn,
                           const float* __restrict__ bih_d, const float* __restrict__ bhh_d)
{
    __shared__ __align__(16) float sEnc[16][64];   // [0:32)=hist_e, [32:64)=scene
    __shared__ __align__(16) float sHe[16][ENC];
    __shared__ __align__(16) float sMax[16][ENC];
    __shared__ __align__(16) float sWdyn[DYN*ENC];
    int tid = threadIdx.x;
    int b0 = blockIdx.x * 16;
    for (int i = tid; i < 16*ENC; i += 512) {
        sHe[i>>6][i&63]  = g_henc[b0*ENC + i];
        sMax[i>>6][i&63] = g_scene_max[b0*ENC + i];
    }
    for (int i = tid; i < DYN*ENC; i += 512) sWdyn[i] = Wdyn[i];
    __syncthreads();
#pragma unroll
    for (int pass = 0; pass < 2; ++pass) {
        int it = tid + pass*512;          // 1024 items: 16 heroes x 64 outputs
        int hero = it >> 6, o = it & 63;
        int row = o & 31;
        const u64* wr = (const u64*)(sWdyn + row*ENC);
        const u64* src = (const u64*)((o < 32) ? sHe[hero] : sMax[hero]);
        u64 a2 = lo2(__ldg(bdyn + row));
#pragma unroll
        for (int k2 = 0; k2 < ENC/2; ++k2) fma2(a2, wr[k2], src[k2]);
        sEnc[hero][o] = lrelu(red2(a2));
    }
    __syncthreads();
    int r = tid;
    u64 acc[16];
    float bsum = __ldg(bih_d + r) + __ldg(bhh_d + r);
#pragma unroll
    for (int hl = 0; hl < 16; ++hl) acc[hl] = lo2(bsum);
#pragma unroll 8
    for (int k2 = 0; k2 < 32; ++k2) {
        u64 w = *(const u64*)(g_Wd2 + ((size_t)k2*512 + r)*2);
#pragma unroll
        for (int hl = 0; hl < 16; ++hl) {
            u64 e = *(const u64*)&sEnc[hl][k2*2];
            fma2(acc[hl], w, e);
        }
    }
#pragma unroll
    for (int hl = 0; hl < 16; ++hl)
        g_pre[(size_t)(b0+hl)*512 + r] = red2(acc[hl]);
}

// ============================================================
// Kernel 4: decoder LSTM (H=128, 25 steps) + output projection.
// 128 threads = hidden units (4 gate rows each); HL=8 heroes/block.
// h broadcasts via LDS.64; double-buffered sH -> 1 barrier/step.
// ============================================================
__global__ void __launch_bounds__(128, 3) dec_kernel(const float* __restrict__ Wop,
                                                     const float* __restrict__ bop,
                                                     float* __restrict__ out)
{
    __shared__ __align__(16) float sPre[HL*512];     // 16 KB
    __shared__ __align__(16) float sH[2][HL*DEC];    // 8 KB double-buffered
    __shared__ float sWop[2*DEC];

    int tid = threadIdx.x;           // 0..127
    int b0 = blockIdx.x * HL;
    for (int i = tid; i < HL*512; i += 128) sPre[i] = g_pre[(size_t)b0*512 + i];
    for (int i = tid; i < 2*DEC; i += 128) sWop[i] = Wop[i];
    for (int i = tid; i < HL*DEC; i += 128) sH[0][i] = 0.f;
    float c[HL];
#pragma unroll
    for (int hl = 0; hl < HL; ++hl) c[hl] = 0.f;
    __syncthreads();

    for (int t = 0; t < T_OUT; ++t) {
        int cur = t & 1, nxt = cur ^ 1;
        const float* sHc = sH[cur];
        u64 acc[4][HL];
#pragma unroll
        for (int g = 0; g < 4; ++g)
#pragma unroll
            for (int hl = 0; hl < HL; ++hl)
                acc[g][hl] = lo2(sPre[hl*512 + g*DEC + tid]);

#pragma unroll 2
        for (int kk = 0; kk < DEC/4; ++kk) {       // 4 k per iter = 2 k-pairs
            int k2 = kk*2;
            u64 w[4][2];
#pragma unroll
            for (int g = 0; g < 4; ++g) {
                w[g][0] = *(const u64*)(g_Wpair + ((size_t)(k2  )*512 + g*DEC + tid)*2);
                w[g][1] = *(const u64*)(g_Wpair + ((size_t)(k2+1)*512 + g*DEC + tid)*2);
            }
#pragma unroll
            for (int hl = 0; hl < HL; ++hl) {
                u64 ha = *(const u64*)(sHc + hl*DEC + kk*4);
                u64 hb = *(const u64*)(sHc + hl*DEC + kk*4 + 2);
#pragma unroll
                for (int g = 0; g < 4; ++g) {
                    fma2(acc[g][hl], w[g][0], ha);
                    fma2(acc[g][hl], w[g][1], hb);
                }
            }
        }
        // write new h into other buffer: no barrier needed before writes
#pragma unroll
        for (int hl = 0; hl < HL; ++hl) {
            float ig = sigf(red2(acc[0][hl])), fg = sigf(red2(acc[1][hl]));
            float gg = tanh_fast(red2(acc[2][hl])), og = sigf(red2(acc[3][hl]));
            c[hl] = fmaf(fg, c[hl], ig*gg);
            sH[nxt][hl*DEC + tid] = og * tanh_fast(c[hl]);
        }
        __syncthreads();   // new h visible to everyone
        if (tid < 2*HL) {
            int hl = tid >> 1, d = tid & 1;
            const u64* wo = (const u64*)(sWop + d*DEC);
            const u64* hr = (const u64*)(sH[nxt] + hl*DEC);
            u64 a2 = lo2(__ldg(bop + d));
#pragma unroll
            for (int k2 = 0; k2 < DEC/2; ++k2) fma2(a2, wo[k2], hr[k2]);
            out[(size_t)t*NB*2 + (size_t)(b0+hl)*2 + d] = red2(a2);
        }
    }
}

// ============================================================
extern "C" void kernel_launch(void* const* d_in, const int* in_sizes, int n_in,
                              void* d_out, int out_size)
{
    const float* hist  = (const float*)d_in[0];
    const float* nbrs  = (const float*)d_in[1];
    const float* Wip   = (const float*)d_in[2];
    const float* bip   = (const float*)d_in[3];
    const float* Wih_e = (const float*)d_in[4];
    const float* Whh_e = (const float*)d_in[5];
    const float* bih_e = (const float*)d_in[6];
    const float* bhh_e = (const float*)d_in[7];
    const float* Wdyn  = (const float*)d_in[8];
    const float* bdyn  = (const float*)d_in[9];
    const float* Wnbr  = (const float*)d_in[10];
    const float* bnbr  = (const float*)d_in[11];
    const float* Wih_d = (const float*)d_in[12];
    const float* Whh_d = (const float*)d_in[13];
    const float* bih_d = (const float*)d_in[14];
    const float* bhh_d = (const float*)d_in[15];
    const float* Wop   = (const float*)d_in[16];
    const float* bop   = (const float*)d_in[17];
    const int*   seg   = (const int*)d_in[18];
    float* out = (float*)d_out;

    prep_kernel<<<192, 256>>>(Whh_d, Wih_d);
    nbr_kernel<<<NB/8, 256>>>(hist, nbrs, Wnbr, bnbr, seg);
    enc_pre_kernel<<<dim3(NB/8, T_IN), 256>>>(hist, Wip, bip, Wih_e, bih_e, bhh_e);
    enc_rec_kernel<<<NB/8, 256>>>(Whh_e);
    mid_kernel<<<NB/16, 512>>>(Wdyn, bdyn, bih_d, bhh_d);
    dec_kernel<<<NB/HL, 128>>>(Wop, bop, out);
}

// round 4
// speedup vs baseline: 1.4715x; 1.2238x over previous
#include <cuda_runtime.h>

#define T_IN 16
#define T_OUT 25
#define NB 4096
#define KN 32
#define NNBR (NB*KN)
#define ENC 64
#define DEC 128
#define DYN 32
#define EMB 32
#define HLD 16         // heroes per decoder block

typedef unsigned long long u64;

// -------- scratch --------
__device__ float g_scene_max[NB*ENC];                 // 1 MB
__device__ float g_henc[NB*ENC];                      // 1 MB
__device__ __align__(16) float g_pre[(size_t)NB*4*DEC];   // 8 MB
__device__ __align__(16) float g_W4[4*DEC*DEC];           // 256 KB quad-transposed Whh_d
__device__ __align__(16) float g_Wd2[4*DEC*(2*DYN)];      // 128 KB pair-transposed Wih_d

__device__ __forceinline__ float lrelu(float x){ return x >= 0.f ? x : 0.1f*x; }
__device__ __forceinline__ float sigf(float x){ return __fdividef(1.f, 1.f + __expf(-x)); }
__device__ __forceinline__ float tanh_fast(float x){ return 1.f - __fdividef(2.f, 1.f + __expf(2.f*x)); }

__device__ __forceinline__ void fma2(u64& d, u64 a, u64 b){
    asm("fma.rn.f32x2 %0, %1, %2, %0;" : "+l"(d) : "l"(a), "l"(b));
}
__device__ __forceinline__ u64 packf2(float x, float y){
    u64 r; asm("mov.b64 %0, {%1,%2};" : "=l"(r) : "f"(x), "f"(y)); return r;
}
__device__ __forceinline__ float red2(u64 a){
    float x, y; asm("mov.b64 {%0,%1}, %2;" : "=f"(x), "=f"(y) : "l"(a)); return x + y;
}
__device__ __forceinline__ u64 lo2(float x){ return (u64)__float_as_uint(x); }

// ============================================================
// Kernel 0: quad-transpose Whh_d [512][128] -> g_W4[k4][512][4];
//           pair-transpose Wih_d [512][64]  -> g_Wd2[k2][512][2]
// ============================================================
__global__ void prep_kernel(const float* __restrict__ Whh, const float* __restrict__ Wih)
{
    int idx = blockIdx.x*256 + threadIdx.x;
    if (idx < 32*512) {                              // 16384 quads of Whh_d
        int k4 = idx >> 9, r = idx & 511;
        float4 v = *(const float4*)(Whh + r*DEC + k4*4);
        *(float4*)(g_W4 + ((size_t)k4*512 + r)*4) = v;
    } else {
        int j = idx - 32*512;                        // 16384 pairs of Wih_d
        if (j < 32*512) {
            int k2 = j >> 9, r = j & 511;
            float2 v = *(const float2*)(Wih + r*(2*DYN) + k2*2);
            *(float2*)(g_Wd2 + ((size_t)k2*512 + r)*2) = v;
        }
    }
}

// ============================================================
// Kernel 1: neighbor MLP + segment max. warp = hero, lane = neighbor.
// ============================================================
__global__ void nbr_kernel(const float* __restrict__ hist, const float* __restrict__ nbrs,
                           const float* __restrict__ Wnbr, const float* __restrict__ bnbr,
                           const int* __restrict__ seg)
{
    __shared__ __align__(16) float sW[ENC*32];
    __shared__ float sb[ENC];
    int tid = threadIdx.x;
    for (int i = tid; i < ENC*32; i += 256) sW[i] = Wnbr[i];
    if (tid < ENC) sb[tid] = bnbr[tid];
    __syncthreads();

    int warp = tid >> 5, lane = tid & 31;
    int b = blockIdx.x * 8 + warp;
    int n = b * KN + lane;
    int sgid = seg[n];

    u64 xp[16];
#pragma unroll
    for (int t = 0; t < T_IN; ++t) {
        float2 hv = *(const float2*)(hist + ((size_t)t*NB + sgid)*2);
        float2 nv = *(const float2*)(nbrs + ((size_t)t*NNBR + n)*2);
        xp[t] = packf2(hv.x - nv.x, hv.y - nv.y);
    }
#pragma unroll 4
    for (int g = 0; g < ENC; ++g) {
        u64 a2 = lo2(sb[g]);
        const ulonglong2* w = (const ulonglong2*)(sW + g*32);
#pragma unroll
        for (int k = 0; k < 8; ++k) {
            ulonglong2 wv = w[k];
            fma2(a2, wv.x, xp[2*k]);
            fma2(a2, wv.y, xp[2*k+1]);
        }
        float acc = lrelu(red2(a2));
#pragma unroll
        for (int off = 16; off; off >>= 1)
            acc = fmaxf(acc, __shfl_xor_sync(0xffffffffu, acc, off));
        if (lane == 0) g_scene_max[b*ENC + g] = acc;
    }
}

// ============================================================
// Kernel 2: FUSED encoder. 256 threads = 256 gate rows; 8 heroes/block.
// emb for all t in smem; Wih transposed in smem; Whh row in REGISTERS
// (every reg-array loop fully unrolled). grid 512.
// smem: sWihT 32KB + sEmb 16KB + sH 4KB + sG 8KB = 60KB (dynamic).
// ============================================================
__global__ void __launch_bounds__(256, 2) enc_kernel(
        const float* __restrict__ hist,
        const float* __restrict__ Wip, const float* __restrict__ bip,
        const float* __restrict__ Wih, const float* __restrict__ Whh,
        const float* __restrict__ bih, const float* __restrict__ bhh)
{
    extern __shared__ __align__(16) float sm[];
    float* sWihT = sm;                   // [8 kk][256 r][4]
    float* sEmb  = sm + 8*256*4;         // [16 t][8 hl][32]
    float* sH    = sEmb + 16*8*32;       // [2][8][64]
    float* sG    = sH + 2*8*64;          // [4][8][64]

    int tid = threadIdx.x;
    int b0 = blockIdx.x * 8;

    // transpose Wih into smem: sWihT[k>>2][r][k&3] = Wih[r][k]
    for (int i = tid; i < 256*EMB; i += 256) {
        int r = i >> 5, k = i & 31;
        sWihT[(k>>2)*1024 + r*4 + (k&3)] = Wih[i];
    }
    // emb for all t: thread -> (hl, j)
    {
        int hl = tid >> 5, j = tid & 31;
        float w0 = Wip[j*2], w1 = Wip[j*2+1], bj = bip[j];
#pragma unroll
        for (int t = 0; t < T_IN; ++t) {
            const float* hp = hist + ((size_t)t*NB + b0 + hl)*2;
            sEmb[(t*8 + hl)*32 + j] = lrelu(fmaf(w0, hp[0], fmaf(w1, hp[1], bj)));
        }
    }
    // Whh row in registers (FULLY unrolled everywhere it is indexed)
    u64 whh[32];
    {
        const u64* wrow = (const u64*)(Whh + tid*ENC);
#pragma unroll
        for (int i = 0; i < 32; ++i) whh[i] = wrow[i];
    }
    float bsum = __ldg(bih + tid) + __ldg(bhh + tid);
    int g = tid >> 6, u = tid & 63;
    float c0 = 0.f, c1 = 0.f;
    sH[tid] = 0.f; sH[256 + tid] = 0.f;   // zero both... only buffer 0 needed but cheap
    __syncthreads();

    for (int t = 0; t < T_IN; ++t) {
        int cur = t & 1, nxt = cur ^ 1;
        u64 acc[8];
#pragma unroll
        for (int hl = 0; hl < 8; ++hl) acc[hl] = lo2(bsum);
        // input part: Wih (from smem, conflict-free) . emb[t]
#pragma unroll
        for (int kk = 0; kk < 8; ++kk) {
            ulonglong2 w = *(const ulonglong2*)(sWihT + kk*1024 + tid*4);
#pragma unroll
            for (int hl = 0; hl < 8; ++hl) {
                ulonglong2 e = *(const ulonglong2*)(sEmb + (t*8 + hl)*32 + kk*4);
                fma2(acc[hl], w.x, e.x);
                fma2(acc[hl], w.y, e.y);
            }
        }
        // recurrent part: Whh (regs) . h
        const float* sHc = sH + cur*512;
#pragma unroll
        for (int kk = 0; kk < 16; ++kk) {
#pragma unroll
            for (int hl = 0; hl < 8; ++hl) {
                ulonglong2 h2 = *(const ulonglong2*)(sHc + hl*64 + kk*4);
                fma2(acc[hl], whh[2*kk],   h2.x);
                fma2(acc[hl], whh[2*kk+1], h2.y);
            }
        }
#pragma unroll
        for (int hl = 0; hl < 8; ++hl) sG[(g*8 + hl)*64 + u] = red2(acc[hl]);
        __syncthreads();
        // activation: thread (g,u) owns heroes g and g+4
        {
            float ii = sG[(0*8+g)*64+u], ff = sG[(1*8+g)*64+u];
            float gg = sG[(2*8+g)*64+u], oo = sG[(3*8+g)*64+u];
            c0 = fmaf(sigf(ff), c0, sigf(ii)*tanh_fast(gg));
            sH[nxt*512 + g*64 + u] = sigf(oo)*tanh_fast(c0);
            int h2i = g + 4;
            float i2 = sG[(0*8+h2i)*64+u], f2 = sG[(1*8+h2i)*64+u];
            float g2 = sG[(2*8+h2i)*64+u], o2 = sG[(3*8+h2i)*64+u];
            c1 = fmaf(sigf(f2), c1, sigf(i2)*tanh_fast(g2));
            sH[nxt*512 + h2i*64 + u] = sigf(o2)*tanh_fast(c1);
        }
        __syncthreads();
    }
    // final h in buffer (T_IN & 1) = 0
    g_henc[b0*ENC + tid] = sH[tid];
    g_henc[b0*ENC + 256 + tid] = sH[256 + tid];
}

// ============================================================
// Kernel 3: Wdyn projections + decoder-input GEMM. 512 thr, 16 heroes/blk.
// ============================================================
__global__ void mid_kernel(const float* __restrict__ Wdyn, const float* __restrict__ bdyn,
                           const float* __restrict__ bih_d, const float* __restrict__ bhh_d)
{
    __shared__ __align__(16) float sEnc[16][64];
    __shared__ __align__(16) float sHe[16][ENC];
    __shared__ __align__(16) float sMax[16][ENC];
    __shared__ __align__(16) float sWdyn[DYN*ENC];
    int tid = threadIdx.x;
    int b0 = blockIdx.x * 16;
    for (int i = tid; i < 16*ENC; i += 512) {
        sHe[i>>6][i&63]  = g_henc[b0*ENC + i];
        sMax[i>>6][i&63] = g_scene_max[b0*ENC + i];
    }
    for (int i = tid; i < DYN*ENC; i += 512) sWdyn[i] = Wdyn[i];
    __syncthreads();
#pragma unroll
    for (int pass = 0; pass < 2; ++pass) {
        int it = tid + pass*512;
        int hero = it >> 6, o = it & 63;
        int row = o & 31;
        const u64* wr = (const u64*)(sWdyn + row*ENC);
        const u64* src = (const u64*)((o < 32) ? sHe[hero] : sMax[hero]);
        u64 a2 = lo2(__ldg(bdyn + row));
#pragma unroll
        for (int k2 = 0; k2 < ENC/2; ++k2) fma2(a2, wr[k2], src[k2]);
        sEnc[hero][o] = lrelu(red2(a2));
    }
    __syncthreads();
    int r = tid;
    u64 acc[16];
    float bsum = __ldg(bih_d + r) + __ldg(bhh_d + r);
#pragma unroll
    for (int hl = 0; hl < 16; ++hl) acc[hl] = lo2(bsum);
#pragma unroll 8
    for (int k2 = 0; k2 < 32; ++k2) {
        u64 w = *(const u64*)(g_Wd2 + ((size_t)k2*512 + r)*2);
#pragma unroll
        for (int hl = 0; hl < 16; ++hl) {
            u64 e = *(const u64*)&sEnc[hl][k2*2];
            fma2(acc[hl], w, e);
        }
    }
#pragma unroll
    for (int hl = 0; hl < 16; ++hl)
        g_pre[(size_t)(b0+hl)*512 + r] = red2(acc[hl]);
}

// ============================================================
// Kernel 4: decoder LSTM (25 steps) + output projection.
// 256 threads: uh = tid&127 hidden unit (all 4 gates), half = tid>>7
// -> heroes half*8..half*8+7 of HLD=16. grid 256 -> SINGLE WAVE (2 blk/SM).
// Weights: quad layout g_W4, LDG.128 lane-coalesced. h: LDS.128 broadcast.
// smem: sPre 32KB + sH 16KB + sWop = ~49KB (dynamic).
// ============================================================
__global__ void __launch_bounds__(256, 2) dec_kernel(const float* __restrict__ Wop,
                                                     const float* __restrict__ bop,
                                                     float* __restrict__ out)
{
    extern __shared__ __align__(16) float dsm[];
    float* sPre = dsm;                  // [16][512]
    float* sH   = dsm + HLD*512;        // [2][16][128]
    float* sWop = sH + 2*HLD*DEC;       // [2][128]

    int tid = threadIdx.x;
    int uh = tid & 127, half = tid >> 7;
    int b0 = blockIdx.x * HLD;
    for (int i = tid; i < HLD*512; i += 256) sPre[i] = g_pre[(size_t)b0*512 + i];
    for (int i = tid; i < 2*DEC; i += 256) sWop[i] = Wop[i];
    for (int i = tid; i < HLD*DEC; i += 256) sH[i] = 0.f;
    float c[8];
#pragma unroll
    for (int hl = 0; hl < 8; ++hl) c[hl] = 0.f;
    __syncthreads();

    const float* myPre = sPre + (half*8)*512;
    for (int t = 0; t < T_OUT; ++t) {
        int cur = t & 1, nxt = cur ^ 1;
        const float* sHc = sH + cur*HLD*DEC + half*8*DEC;
        u64 acc[4][8];
#pragma unroll
        for (int g = 0; g < 4; ++g)
#pragma unroll
            for (int hl = 0; hl < 8; ++hl)
                acc[g][hl] = lo2(myPre[hl*512 + g*DEC + uh]);

#pragma unroll 4
        for (int kk = 0; kk < 32; ++kk) {            // k-quads
            ulonglong2 w[4];
#pragma unroll
            for (int g = 0; g < 4; ++g)
                w[g] = *(const ulonglong2*)(g_W4 + ((size_t)kk*512 + g*DEC + uh)*4);
#pragma unroll
            for (int hl = 0; hl < 8; ++hl) {
                ulonglong2 h2 = *(const ulonglong2*)(sHc + hl*DEC + kk*4);
#pragma unroll
                for (int g = 0; g < 4; ++g) {
                    fma2(acc[g][hl], w[g].x, h2.x);
                    fma2(acc[g][hl], w[g].y, h2.y);
                }
            }
        }
#pragma unroll
        for (int hl = 0; hl < 8; ++hl) {
            float ig = sigf(red2(acc[0][hl])), fg = sigf(red2(acc[1][hl]));
            float gg = tanh_fast(red2(acc[2][hl])), og = sigf(red2(acc[3][hl]));
            c[hl] = fmaf(fg, c[hl], ig*gg);
            sH[nxt*HLD*DEC + (half*8 + hl)*DEC + uh] = og * tanh_fast(c[hl]);
        }
        __syncthreads();   // new h visible
        if (tid < 2*HLD) {
            int hl = tid >> 1, d = tid & 1;
            const u64* wo = (const u64*)(sWop + d*DEC);
            const u64* hr = (const u64*)(sH + nxt*HLD*DEC + hl*DEC);
            u64 a2 = lo2(__ldg(bop + d));
#pragma unroll
            for (int k2 = 0; k2 < DEC/2; ++k2) fma2(a2, wo[k2], hr[k2]);
            out[(size_t)t*NB*2 + (size_t)(b0+hl)*2 + d] = red2(a2);
        }
    }
}

// ============================================================
extern "C" void kernel_launch(void* const* d_in, const int* in_sizes, int n_in,
                              void* d_out, int out_size)
{
    const float* hist  = (const float*)d_in[0];
    const float* nbrs  = (const float*)d_in[1];
    const float* Wip   = (const float*)d_in[2];
    const float* bip   = (const float*)d_in[3];
    const float* Wih_e = (const float*)d_in[4];
    const float* Whh_e = (const float*)d_in[5];
    const float* bih_e = (const float*)d_in[6];
    const float* bhh_e = (const float*)d_in[7];
    const float* Wdyn  = (const float*)d_in[8];
    const float* bdyn  = (const float*)d_in[9];
    const float* Wnbr  = (const float*)d_in[10];
    const float* bnbr  = (const float*)d_in[11];
    const float* Wih_d = (const float*)d_in[12];
    const float* Whh_d = (const float*)d_in[13];
    const float* bih_d = (const float*)d_in[14];
    const float* bhh_d = (const float*)d_in[15];
    const float* Wop   = (const float*)d_in[16];
    const float* bop   = (const float*)d_in[17];
    const int*   seg   = (const int*)d_in[18];
    float* out = (float*)d_out;

    constexpr int ENC_SMEM = (8*256*4 + 16*8*32 + 2*8*64 + 4*8*64) * (int)sizeof(float);
    constexpr int DEC_SMEM = (HLD*512 + 2*HLD*DEC + 2*DEC) * (int)sizeof(float);
    static int configured = 0;
    cudaFuncSetAttribute(enc_kernel, cudaFuncAttributeMaxDynamicSharedMemorySize, ENC_SMEM);
    cudaFuncSetAttribute(dec_kernel, cudaFuncAttributeMaxDynamicSharedMemorySize, DEC_SMEM);
    (void)configured;

    prep_kernel<<<128, 256>>>(Whh_d, Wih_d);
    nbr_kernel<<<NB/8, 256>>>(hist, nbrs, Wnbr, bnbr, seg);
    enc_kernel<<<NB/8, 256, ENC_SMEM>>>(hist, Wip, bip, Wih_e, Whh_e, bih_e, bhh_e);
    mid_kernel<<<NB/16, 512>>>(Wdyn, bdyn, bih_d, bhh_d);
    dec_kernel<<<NB/HLD, 256, DEC_SMEM>>>(Wop, bop, out);
}

// round 5
// speedup vs baseline: 1.5168x; 1.0308x over previous
#include <cuda_runtime.h>

#define T_IN 16
#define T_OUT 25
#define NB 4096
#define KN 32
#define NNBR (NB*KN)
#define ENC 64
#define DEC 128
#define DYN 32
#define EMB 32
#define HLD 32         // heroes per decoder block
#define HLE 16         // heroes per encoder block

typedef unsigned long long u64;

// -------- scratch --------
__device__ float g_scene_max[NB*ENC];                 // 1 MB
__device__ float g_henc[NB*ENC];                      // 1 MB
__device__ __align__(16) float g_pre[(size_t)NB*4*DEC];   // 8 MB
__device__ __align__(16) float g_W4[4*DEC*DEC];           // 256 KB quad-transposed Whh_d
__device__ __align__(16) float g_Wd4[4*DEC*(2*DYN)];      // 128 KB quad-transposed Wih_d

__device__ __forceinline__ float lrelu(float x){ return x >= 0.f ? x : 0.1f*x; }
__device__ __forceinline__ float sigf(float x){ return __fdividef(1.f, 1.f + __expf(-x)); }
__device__ __forceinline__ float tanh_fast(float x){ return 1.f - __fdividef(2.f, 1.f + __expf(2.f*x)); }

__device__ __forceinline__ void fma2(u64& d, u64 a, u64 b){
    asm("fma.rn.f32x2 %0, %1, %2, %0;" : "+l"(d) : "l"(a), "l"(b));
}
__device__ __forceinline__ u64 packf2(float x, float y){
    u64 r; asm("mov.b64 %0, {%1,%2};" : "=l"(r) : "f"(x), "f"(y)); return r;
}
__device__ __forceinline__ float red2(u64 a){
    float x, y; asm("mov.b64 {%0,%1}, %2;" : "=f"(x), "=f"(y) : "l"(a)); return x + y;
}
__device__ __forceinline__ u64 lo2(float x){ return (u64)__float_as_uint(x); }

// ============================================================
// Kernel 0: quad-transpose Whh_d [512][128] -> g_W4[k4][512][4]
//           quad-transpose Wih_d [512][64]  -> g_Wd4[k4][512][4]
// ============================================================
__global__ void prep_kernel(const float* __restrict__ Whh, const float* __restrict__ Wih)
{
    int idx = blockIdx.x*256 + threadIdx.x;
    if (idx < 32*512) {                              // Whh_d quads
        int k4 = idx >> 9, r = idx & 511;
        float4 v = *(const float4*)(Whh + r*DEC + k4*4);
        *(float4*)(g_W4 + ((size_t)k4*512 + r)*4) = v;
    } else {
        int j = idx - 32*512;                        // Wih_d quads
        if (j < 16*512) {
            int k4 = j >> 9, r = j & 511;
            float4 v = *(const float4*)(Wih + r*(2*DYN) + k4*4);
            *(float4*)(g_Wd4 + ((size_t)k4*512 + r)*4) = v;
        }
    }
}

// ============================================================
// Kernel 1: neighbor MLP + segment max. warp = hero, lane = neighbor.
// ============================================================
__global__ void nbr_kernel(const float* __restrict__ hist, const float* __restrict__ nbrs,
                           const float* __restrict__ Wnbr, const float* __restrict__ bnbr,
                           const int* __restrict__ seg)
{
    __shared__ __align__(16) float sW[ENC*32];
    __shared__ float sb[ENC];
    int tid = threadIdx.x;
    for (int i = tid; i < ENC*32; i += 256) sW[i] = Wnbr[i];
    if (tid < ENC) sb[tid] = bnbr[tid];
    __syncthreads();

    int warp = tid >> 5, lane = tid & 31;
    int b = blockIdx.x * 8 + warp;
    int n = b * KN + lane;
    int sgid = seg[n];

    u64 xp[16];
#pragma unroll
    for (int t = 0; t < T_IN; ++t) {
        float2 hv = *(const float2*)(hist + ((size_t)t*NB + sgid)*2);
        float2 nv = *(const float2*)(nbrs + ((size_t)t*NNBR + n)*2);
        xp[t] = packf2(hv.x - nv.x, hv.y - nv.y);
    }
#pragma unroll 4
    for (int g = 0; g < ENC; ++g) {
        u64 a2 = lo2(sb[g]);
        const ulonglong2* w = (const ulonglong2*)(sW + g*32);
#pragma unroll
        for (int k = 0; k < 8; ++k) {
            ulonglong2 wv = w[k];
            fma2(a2, wv.x, xp[2*k]);
            fma2(a2, wv.y, xp[2*k+1]);
        }
        float acc = lrelu(red2(a2));
#pragma unroll
        for (int off = 16; off; off >>= 1)
            acc = fmaxf(acc, __shfl_xor_sync(0xffffffffu, acc, off));
        if (lane == 0) g_scene_max[b*ENC + g] = acc;
    }
}

// ============================================================
// Kernel 2: FUSED encoder, HLE=16 heroes/block -> grid 256 = SINGLE WAVE.
// 256 threads = 256 gate rows (g=r>>6, u=r&63). Whh row in registers.
// smem: sWihT 32KB + sEmb 32KB + sH 8KB + sG 16KB = 88KB dynamic.
// ============================================================
__global__ void __launch_bounds__(256, 2) enc_kernel(
        const float* __restrict__ hist,
        const float* __restrict__ Wip, const float* __restrict__ bip,
        const float* __restrict__ Wih, const float* __restrict__ Whh,
        const float* __restrict__ bih, const float* __restrict__ bhh)
{
    extern __shared__ __align__(16) float sm[];
    float* sWihT = sm;                   // [8 kk][256 r][4]
    float* sEmb  = sm + 8*256*4;         // [16 t][16 hl][32]
    float* sH    = sEmb + 16*16*32;      // [2][16][64]
    float* sG    = sH + 2*16*64;         // [4][16][64]

    int tid = threadIdx.x;
    int b0 = blockIdx.x * HLE;

    // transpose Wih into smem: sWihT[k>>2][r][k&3]
    for (int i = tid; i < 256*EMB; i += 256) {
        int r = i >> 5, k = i & 31;
        sWihT[(k>>2)*1024 + r*4 + (k&3)] = Wih[i];
    }
    // emb for all (t, hl): thread -> (hlb, j), covers hl = hlb and hlb+8
    {
        int hlb = tid >> 5, j = tid & 31;
        float w0 = Wip[j*2], w1 = Wip[j*2+1], bj = bip[j];
#pragma unroll
        for (int t = 0; t < T_IN; ++t) {
#pragma unroll
            for (int ho = 0; ho < 2; ++ho) {
                int hl = hlb + ho*8;
                const float* hp = hist + ((size_t)t*NB + b0 + hl)*2;
                sEmb[(t*16 + hl)*32 + j] = lrelu(fmaf(w0, hp[0], fmaf(w1, hp[1], bj)));
            }
        }
    }
    // Whh row in registers (all indexing fully unrolled)
    u64 whh[32];
    {
        const u64* wrow = (const u64*)(Whh + tid*ENC);
#pragma unroll
        for (int i = 0; i < 32; ++i) whh[i] = wrow[i];
    }
    float bsum = __ldg(bih + tid) + __ldg(bhh + tid);
    int g = tid >> 6, u = tid & 63;
    float c[4];
#pragma unroll
    for (int i = 0; i < 4; ++i) c[i] = 0.f;
    sH[tid] = 0.f; sH[256 + tid] = 0.f;  // buffer 0: 1024 floats (16x64)
    sH[512 + tid] = 0.f; sH[768 + tid] = 0.f;
    __syncthreads();

    for (int t = 0; t < T_IN; ++t) {
        int cur = t & 1, nxt = cur ^ 1;
        u64 acc[16];
#pragma unroll
        for (int hl = 0; hl < 16; ++hl) acc[hl] = lo2(bsum);
        // input part
        const float* et = sEmb + t*16*32;
#pragma unroll
        for (int kk = 0; kk < 8; ++kk) {
            ulonglong2 w = *(const ulonglong2*)(sWihT + kk*1024 + tid*4);
#pragma unroll
            for (int hl = 0; hl < 16; ++hl) {
                ulonglong2 e = *(const ulonglong2*)(et + hl*32 + kk*4);
                fma2(acc[hl], w.x, e.x);
                fma2(acc[hl], w.y, e.y);
            }
        }
        // recurrent part (weights in registers)
        const float* sHc = sH + cur*1024;
#pragma unroll
        for (int kk = 0; kk < 16; ++kk) {
#pragma unroll
            for (int hl = 0; hl < 16; ++hl) {
                ulonglong2 h2 = *(const ulonglong2*)(sHc + hl*64 + kk*4);
                fma2(acc[hl], whh[2*kk],   h2.x);
                fma2(acc[hl], whh[2*kk+1], h2.y);
            }
        }
#pragma unroll
        for (int hl = 0; hl < 16; ++hl) sG[(g*16 + hl)*64 + u] = red2(acc[hl]);
        __syncthreads();
        // activation: thread (g,u) owns heroes g, g+4, g+8, g+12
#pragma unroll
        for (int i = 0; i < 4; ++i) {
            int hl = g + i*4;
            float ii = sG[(0*16+hl)*64+u], ff = sG[(1*16+hl)*64+u];
            float gg = sG[(2*16+hl)*64+u], oo = sG[(3*16+hl)*64+u];
            c[i] = fmaf(sigf(ff), c[i], sigf(ii)*tanh_fast(gg));
            sH[nxt*1024 + hl*64 + u] = sigf(oo)*tanh_fast(c[i]);
        }
        __syncthreads();
    }
    // final h in buffer 0 (T_IN even)
    for (int i = tid; i < HLE*ENC; i += 256)
        g_henc[b0*ENC + i] = sH[i];
}

// ============================================================
// Kernel 3: Wdyn projections + decoder-input GEMM. 512 thr, 16 heroes/blk.
// Wih_d quads (LDG.128) + LDS.128 activations.
// ============================================================
__global__ void mid_kernel(const float* __restrict__ Wdyn, const float* __restrict__ bdyn,
                           const float* __restrict__ bih_d, const float* __restrict__ bhh_d)
{
    __shared__ __align__(16) float sEnc[16][64];
    __shared__ __align__(16) float sHe[16][ENC];
    __shared__ __align__(16) float sMax[16][ENC];
    __shared__ __align__(16) float sWdyn[DYN*ENC];
    int tid = threadIdx.x;
    int b0 = blockIdx.x * 16;
    for (int i = tid; i < 16*ENC; i += 512) {
        sHe[i>>6][i&63]  = g_henc[b0*ENC + i];
        sMax[i>>6][i&63] = g_scene_max[b0*ENC + i];
    }
    for (int i = tid; i < DYN*ENC; i += 512) sWdyn[i] = Wdyn[i];
    __syncthreads();
#pragma unroll
    for (int pass = 0; pass < 2; ++pass) {
        int it = tid + pass*512;
        int hero = it >> 6, o = it & 63;
        int row = o & 31;
        const ulonglong2* wr = (const ulonglong2*)(sWdyn + row*ENC);
        const ulonglong2* src = (const ulonglong2*)((o < 32) ? sHe[hero] : sMax[hero]);
        u64 a2 = lo2(__ldg(bdyn + row));
#pragma unroll
        for (int k4 = 0; k4 < ENC/4; ++k4) {
            ulonglong2 w = wr[k4], s = src[k4];
            fma2(a2, w.x, s.x); fma2(a2, w.y, s.y);
        }
        sEnc[hero][o] = lrelu(red2(a2));
    }
    __syncthreads();
    int r = tid;
    u64 acc[16];
    float bsum = __ldg(bih_d + r) + __ldg(bhh_d + r);
#pragma unroll
    for (int hl = 0; hl < 16; ++hl) acc[hl] = lo2(bsum);
#pragma unroll 4
    for (int k4 = 0; k4 < 16; ++k4) {
        ulonglong2 w = *(const ulonglong2*)(g_Wd4 + ((size_t)k4*512 + r)*4);
#pragma unroll
        for (int hl = 0; hl < 16; ++hl) {
            ulonglong2 e = *(const ulonglong2*)&sEnc[hl][k4*4];
            fma2(acc[hl], w.x, e.x);
            fma2(acc[hl], w.y, e.y);
        }
    }
#pragma unroll
    for (int hl = 0; hl < 16; ++hl)
        g_pre[(size_t)(b0+hl)*512 + r] = red2(acc[hl]);
}

// ============================================================
// Kernel 4: decoder LSTM (25 steps) + output projection.
// 512 threads: uh = tid&127 hidden unit, quarter = tid>>7 -> 8 heroes each
// of HLD=32. grid 128 -> single wave, 1 block/SM, weight stream shared by
// 4 quarters through L1. smem 97KB dynamic.
// ============================================================
__global__ void __launch_bounds__(512, 1) dec_kernel(const float* __restrict__ Wop,
                                                     const float* __restrict__ bop,
                                                     float* __restrict__ out)
{
    extern __shared__ __align__(16) float dsm[];
    float* sPre = dsm;                  // [32][512] 64KB
    float* sH   = dsm + HLD*512;        // [2][32][128] 32KB
    float* sWop = sH + 2*HLD*DEC;       // [2][128]

    int tid = threadIdx.x;
    int uh = tid & 127, q = tid >> 7;
    int b0 = blockIdx.x * HLD;
    for (int i = tid; i < HLD*512; i += 512) sPre[i] = g_pre[(size_t)b0*512 + i];
    for (int i = tid; i < 2*DEC; i += 512) sWop[i] = Wop[i];
    for (int i = tid; i < HLD*DEC; i += 512) sH[i] = 0.f;
    float c[8];
#pragma unroll
    for (int hl = 0; hl < 8; ++hl) c[hl] = 0.f;
    __syncthreads();

    const float* myPre = sPre + (q*8)*512;
    for (int t = 0; t < T_OUT; ++t) {
        int cur = t & 1, nxt = cur ^ 1;
        const float* sHc = sH + cur*HLD*DEC + q*8*DEC;
        u64 acc[4][8];
#pragma unroll
        for (int g = 0; g < 4; ++g)
#pragma unroll
            for (int hl = 0; hl < 8; ++hl)
                acc[g][hl] = lo2(myPre[hl*512 + g*DEC + uh]);

#pragma unroll 4
        for (int kk = 0; kk < 32; ++kk) {            // k-quads
            ulonglong2 w[4];
#pragma unroll
            for (int g = 0; g < 4; ++g)
                w[g] = *(const ulonglong2*)(g_W4 + ((size_t)kk*512 + g*DEC + uh)*4);
#pragma unroll
            for (int hl = 0; hl < 8; ++hl) {
                ulonglong2 h2 = *(const ulonglong2*)(sHc + hl*DEC + kk*4);
#pragma unroll
                for (int g = 0; g < 4; ++g) {
                    fma2(acc[g][hl], w[g].x, h2.x);
                    fma2(acc[g][hl], w[g].y, h2.y);
                }
            }
        }
#pragma unroll
        for (int hl = 0; hl < 8; ++hl) {
            float ig = sigf(red2(acc[0][hl])), fg = sigf(red2(acc[1][hl]));
            float gg = tanh_fast(red2(acc[2][hl])), og = sigf(red2(acc[3][hl]));
            c[hl] = fmaf(fg, c[hl], ig*gg);
            sH[nxt*HLD*DEC + (q*8 + hl)*DEC + uh] = og * tanh_fast(c[hl]);
        }
        __syncthreads();   // new h visible
        if (tid < 2*HLD) {
            int hl = tid >> 1, d = tid & 1;
            const ulonglong2* wo = (const ulonglong2*)(sWop + d*DEC);
            const ulonglong2* hr = (const ulonglong2*)(sH + nxt*HLD*DEC + hl*DEC);
            u64 a2 = lo2(__ldg(bop + d));
#pragma unroll
            for (int k4 = 0; k4 < DEC/4; ++k4) {
                ulonglong2 w = wo[k4], h2 = hr[k4];
                fma2(a2, w.x, h2.x); fma2(a2, w.y, h2.y);
            }
            out[(size_t)t*NB*2 + (size_t)(b0+hl)*2 + d] = red2(a2);
        }
    }
}

// ============================================================
extern "C" void kernel_launch(void* const* d_in, const int* in_sizes, int n_in,
                              void* d_out, int out_size)
{
    const float* hist  = (const float*)d_in[0];
    const float* nbrs  = (const float*)d_in[1];
    const float* Wip   = (const float*)d_in[2];
    const float* bip   = (const float*)d_in[3];
    const float* Wih_e = (const float*)d_in[4];
    const float* Whh_e = (const float*)d_in[5];
    const float* bih_e = (const float*)d_in[6];
    const float* bhh_e = (const float*)d_in[7];
    const float* Wdyn  = (const float*)d_in[8];
    const float* bdyn  = (const float*)d_in[9];
    const float* Wnbr  = (const float*)d_in[10];
    const float* bnbr  = (const float*)d_in[11];
    const float* Wih_d = (const float*)d_in[12];
    const float* Whh_d = (const float*)d_in[13];
    const float* bih_d = (const float*)d_in[14];
    const float* bhh_d = (const float*)d_in[15];
    const float* Wop   = (const float*)d_in[16];
    const float* bop   = (const float*)d_in[17];
    const int*   seg   = (const int*)d_in[18];
    float* out = (float*)d_out;

    constexpr int ENC_SMEM = (8*256*4 + 16*16*32 + 2*16*64 + 4*16*64) * (int)sizeof(float);
    constexpr int DEC_SMEM = (HLD*512 + 2*HLD*DEC + 2*DEC) * (int)sizeof(float);
    cudaFuncSetAttribute(enc_kernel, cudaFuncAttributeMaxDynamicSharedMemorySize, ENC_SMEM);
    cudaFuncSetAttribute(dec_kernel, cudaFuncAttributeMaxDynamicSharedMemorySize, DEC_SMEM);

    prep_kernel<<<96, 256>>>(Whh_d, Wih_d);
    nbr_kernel<<<NB/8, 256>>>(hist, nbrs, Wnbr, bnbr, seg);
    enc_kernel<<<NB/HLE, 256, ENC_SMEM>>>(hist, Wip, bip, Wih_e, Whh_e, bih_e, bhh_e);
    mid_kernel<<<NB/16, 512>>>(Wdyn, bdyn, bih_d, bhh_d);
    dec_kernel<<<NB/HLD, 512, DEC_SMEM>>>(Wop, bop, out);
}

// round 6
// speedup vs baseline: 1.6981x; 1.1195x over previous
#include <cuda_runtime.h>

#define T_IN 16
#define T_OUT 25
#define NB 4096
#define KN 32
#define NNBR (NB*KN)
#define ENC 64
#define DEC 128
#define DYN 32
#define EMB 32
#define DHL 28         // heroes per decoder block (147 blocks x 28 = 4116)
#define DGRID 147
#define HLE 16         // heroes per front block

typedef unsigned long long u64;

// -------- scratch --------
__device__ __align__(16) float g_pre[(size_t)(NB+48)*4*DEC];  // padded for ragged dec grid
__device__ __align__(16) float g_W4[4*DEC*DEC];               // quad-transposed Whh_d
__device__ __align__(16) float g_Wd4[4*DEC*(2*DYN)];          // quad-transposed Wih_d

__device__ __forceinline__ float lrelu(float x){ return x >= 0.f ? x : 0.1f*x; }
__device__ __forceinline__ float sigf(float x){ return __fdividef(1.f, 1.f + __expf(-x)); }
__device__ __forceinline__ float tanh_fast(float x){ return 1.f - __fdividef(2.f, 1.f + __expf(2.f*x)); }

__device__ __forceinline__ void fma2(u64& d, u64 a, u64 b){
    asm("fma.rn.f32x2 %0, %1, %2, %0;" : "+l"(d) : "l"(a), "l"(b));
}
__device__ __forceinline__ u64 packf2(float x, float y){
    u64 r; asm("mov.b64 %0, {%1,%2};" : "=l"(r) : "f"(x), "f"(y)); return r;
}
__device__ __forceinline__ float red2(u64 a){
    float x, y; asm("mov.b64 {%0,%1}, %2;" : "=f"(x), "=f"(y) : "l"(a)); return x + y;
}
__device__ __forceinline__ u64 lo2(float x){ return (u64)__float_as_uint(x); }

// ============================================================
// Kernel 0: quad-transpose Whh_d & Wih_d; zero g_pre pad tail.
// grid 96 x 256 = 24576 threads.
// ============================================================
__global__ void prep_kernel(const float* __restrict__ Whh, const float* __restrict__ Wih)
{
    int idx = blockIdx.x*256 + threadIdx.x;
    if (idx < 32*512) {                              // Whh_d quads (16384)
        int k4 = idx >> 9, r = idx & 511;
        float4 v = *(const float4*)(Whh + r*DEC + k4*4);
        *(float4*)(g_W4 + ((size_t)k4*512 + r)*4) = v;
    } else {
        int j = idx - 32*512;                        // Wih_d quads (8192)
        if (j < 16*512) {
            int k4 = j >> 9, r = j & 511;
            float4 v = *(const float4*)(Wih + r*(2*DYN) + k4*4);
            *(float4*)(g_Wd4 + ((size_t)k4*512 + r)*4) = v;
        }
    }
    // zero padded tail of g_pre (48 heroes x 512 = 24576 elements)
    g_pre[(size_t)NB*512 + idx] = 0.f;
}

// ============================================================
// Kernel 1 (FRONT): neighbor MLP+max  ->  encoder LSTM  ->  Wdyn projections
//                   ->  decoder-input GEMM. 16 heroes/block, 256 threads,
//                   grid 256, occupancy 2 -> single wave.
// smem 68KB dynamic; region R (32KB) overlaid per phase.
// ============================================================
__global__ void __launch_bounds__(256, 2) front_kernel(
        const float* __restrict__ hist, const float* __restrict__ nbrs,
        const float* __restrict__ Wip,  const float* __restrict__ bip,
        const float* __restrict__ Wih,  const float* __restrict__ Whh,
        const float* __restrict__ bih,  const float* __restrict__ bhh,
        const float* __restrict__ Wdyn, const float* __restrict__ bdyn,
        const float* __restrict__ Wnbr, const float* __restrict__ bnbr,
        const float* __restrict__ bih_d,const float* __restrict__ bhh_d,
        const int* __restrict__ seg)
{
    extern __shared__ __align__(16) float sm[];
    float* R     = sm;                  // 8192 floats (32KB): phase A = Wnbr+bnbr,
                                        // phase B = WihT[8][256][4], phase C = Wdyn
    float* sMax  = sm + 8192;           // [16][64]
    float* sH    = sMax + 1024;         // [2][16][64]
    float* sG    = sH + 2048;           // [4][16][64]
    float* sEmbT = sG + 4096;           // [2][16][32]
    float* sEnc  = sEmbT + 1024;        // [16][64]

    int tid = threadIdx.x;
    int b0 = blockIdx.x * HLE;
    int warp = tid >> 5, lane = tid & 31;

    // ---------------- Phase A: neighbor MLP + segment max ----------------
    for (int i = tid; i < ENC*32; i += 256) R[i] = Wnbr[i];
    if (tid < ENC) R[ENC*32 + tid] = bnbr[tid];
    __syncthreads();

#pragma unroll
    for (int p = 0; p < 2; ++p) {
        int hero = warp + p*8;                 // 0..15 local
        int n = (b0 + hero)*KN + lane;
        int sgid = seg[n];
        u64 xp[16];
#pragma unroll
        for (int t = 0; t < T_IN; ++t) {
            float2 hv = *(const float2*)(hist + ((size_t)t*NB + sgid)*2);
            float2 nv = *(const float2*)(nbrs + ((size_t)t*NNBR + n)*2);
            xp[t] = packf2(hv.x - nv.x, hv.y - nv.y);
        }
#pragma unroll 4
        for (int g = 0; g < ENC; ++g) {
            u64 a2 = lo2(R[ENC*32 + g]);
            const ulonglong2* w = (const ulonglong2*)(R + g*32);
#pragma unroll
            for (int k = 0; k < 8; ++k) {
                ulonglong2 wv = w[k];
                fma2(a2, wv.x, xp[2*k]);
                fma2(a2, wv.y, xp[2*k+1]);
            }
            float acc = lrelu(red2(a2));
#pragma unroll
            for (int off = 16; off; off >>= 1)
                acc = fmaxf(acc, __shfl_xor_sync(0xffffffffu, acc, off));
            if (lane == 0) sMax[hero*ENC + g] = acc;
        }
    }
    __syncthreads();   // done with R as Wnbr; sMax complete

    // ---------------- Phase B: encoder LSTM ----------------
    // R := WihT[k>>2][r][k&3]
    for (int i = tid; i < 256*EMB; i += 256) {
        int r = i >> 5, k = i & 31;
        R[(k>>2)*1024 + r*4 + (k&3)] = Wih[i];
    }
    // Wip row for this thread's j (used for on-the-fly emb)
    int jE = tid & 31, hlE = tid >> 5;           // thread covers (hlE, jE) and (hlE+8, jE)
    float w0 = Wip[jE*2], w1 = Wip[jE*2+1], bj = bip[jE];
    // emb for t=0
    {
        const float* hp0 = hist + ((size_t)0*NB + b0 + hlE)*2;
        const float* hp1 = hist + ((size_t)0*NB + b0 + hlE + 8)*2;
        sEmbT[hlE*32 + jE]       = lrelu(fmaf(w0, hp0[0], fmaf(w1, hp0[1], bj)));
        sEmbT[(hlE+8)*32 + jE]   = lrelu(fmaf(w0, hp1[0], fmaf(w1, hp1[1], bj)));
    }
    // Whh row in registers
    u64 whh[32];
    {
        const u64* wrow = (const u64*)(Whh + tid*ENC);
#pragma unroll
        for (int i = 0; i < 32; ++i) whh[i] = wrow[i];
    }
    float bsum = __ldg(bih + tid) + __ldg(bhh + tid);
    int g = tid >> 6, u = tid & 63;
    float c[4];
#pragma unroll
    for (int i = 0; i < 4; ++i) c[i] = 0.f;
    sH[tid] = 0.f; sH[256 + tid] = 0.f; sH[512 + tid] = 0.f; sH[768 + tid] = 0.f;
    __syncthreads();

    for (int t = 0; t < T_IN; ++t) {
        int cur = t & 1, nxt = cur ^ 1;
        u64 acc[16];
#pragma unroll
        for (int hl = 0; hl < 16; ++hl) acc[hl] = lo2(bsum);
        const float* et = sEmbT + cur*512;
#pragma unroll
        for (int kk = 0; kk < 8; ++kk) {
            ulonglong2 w = *(const ulonglong2*)(R + kk*1024 + tid*4);
#pragma unroll
            for (int hl = 0; hl < 16; ++hl) {
                ulonglong2 e = *(const ulonglong2*)(et + hl*32 + kk*4);
                fma2(acc[hl], w.x, e.x);
                fma2(acc[hl], w.y, e.y);
            }
        }
        const float* sHc = sH + cur*1024;
#pragma unroll
        for (int kk = 0; kk < 16; ++kk) {
#pragma unroll
            for (int hl = 0; hl < 16; ++hl) {
                ulonglong2 h2 = *(const ulonglong2*)(sHc + hl*64 + kk*4);
                fma2(acc[hl], whh[2*kk],   h2.x);
                fma2(acc[hl], whh[2*kk+1], h2.y);
            }
        }
#pragma unroll
        for (int hl = 0; hl < 16; ++hl) sG[(g*16 + hl)*64 + u] = red2(acc[hl]);
        __syncthreads();
        // activation (thread owns heroes g, g+4, g+8, g+12) + emb for t+1
#pragma unroll
        for (int i = 0; i < 4; ++i) {
            int hl = g + i*4;
            float ii = sG[(0*16+hl)*64+u], ff = sG[(1*16+hl)*64+u];
            float gg = sG[(2*16+hl)*64+u], oo = sG[(3*16+hl)*64+u];
            c[i] = fmaf(sigf(ff), c[i], sigf(ii)*tanh_fast(gg));
            sH[nxt*1024 + hl*64 + u] = sigf(oo)*tanh_fast(c[i]);
        }
        if (t + 1 < T_IN) {
            const float* hp0 = hist + ((size_t)(t+1)*NB + b0 + hlE)*2;
            const float* hp1 = hist + ((size_t)(t+1)*NB + b0 + hlE + 8)*2;
            sEmbT[nxt*512 + hlE*32 + jE]     = lrelu(fmaf(w0, hp0[0], fmaf(w1, hp0[1], bj)));
            sEmbT[nxt*512 + (hlE+8)*32 + jE] = lrelu(fmaf(w0, hp1[0], fmaf(w1, hp1[1], bj)));
        }
        __syncthreads();
    }
    // final h in sH buffer 0 (T_IN even)

    // ---------------- Phase C: Wdyn projections + decoder-input GEMM ----------------
    for (int i = tid; i < DYN*ENC; i += 256) R[i] = Wdyn[i];
    __syncthreads();
#pragma unroll
    for (int pass = 0; pass < 4; ++pass) {
        int it = tid + pass*256;           // 1024 items = 16 heroes x 64 outputs
        int hero = it >> 6, o = it & 63;
        int row = o & 31;
        const ulonglong2* wr = (const ulonglong2*)(R + row*ENC);
        const ulonglong2* src = (const ulonglong2*)((o < 32) ? (sH + hero*64) : (sMax + hero*64));
        u64 a2 = lo2(__ldg(bdyn + row));
#pragma unroll
        for (int k4 = 0; k4 < ENC/4; ++k4) {
            ulonglong2 w = wr[k4], s = src[k4];
            fma2(a2, w.x, s.x); fma2(a2, w.y, s.y);
        }
        sEnc[hero*64 + o] = lrelu(red2(a2));
    }
    __syncthreads();
#pragma unroll
    for (int pass = 0; pass < 2; ++pass) {
        int r = tid + pass*256;
        u64 acc[16];
        float bs = __ldg(bih_d + r) + __ldg(bhh_d + r);
#pragma unroll
        for (int hl = 0; hl < 16; ++hl) acc[hl] = lo2(bs);
#pragma unroll 4
        for (int k4 = 0; k4 < 16; ++k4) {
            ulonglong2 w = *(const ulonglong2*)(g_Wd4 + ((size_t)k4*512 + r)*4);
#pragma unroll
            for (int hl = 0; hl < 16; ++hl) {
                ulonglong2 e = *(const ulonglong2*)(sEnc + hl*64 + k4*4);
                fma2(acc[hl], w.x, e.x);
                fma2(acc[hl], w.y, e.y);
            }
        }
#pragma unroll
        for (int hl = 0; hl < 16; ++hl)
            g_pre[(size_t)(b0+hl)*512 + r] = red2(acc[hl]);
    }
}

// ============================================================
// Kernel 2: decoder LSTM (25 steps) + output projection.
// 512 threads: uh = tid&127, quarter q = tid>>7 handles 7 heroes of DHL=28.
// grid 147 -> all SMs, single wave. g_pre padded so tail loads are safe.
// ============================================================
__global__ void __launch_bounds__(512, 1) dec_kernel(const float* __restrict__ Wop,
                                                     const float* __restrict__ bop,
                                                     float* __restrict__ out)
{
    extern __shared__ __align__(16) float dsm[];
    float* sPre = dsm;                  // [28][512] 56KB
    float* sH   = dsm + DHL*512;        // [2][28][128] 28KB
    float* sWop = sH + 2*DHL*DEC;       // [2][128]

    int tid = threadIdx.x;
    int uh = tid & 127, q = tid >> 7;
    int b0 = blockIdx.x * DHL;
    for (int i = tid; i < DHL*512; i += 512) sPre[i] = g_pre[(size_t)b0*512 + i];
    for (int i = tid; i < 2*DEC; i += 512) sWop[i] = Wop[i];
    for (int i = tid; i < DHL*DEC; i += 512) sH[i] = 0.f;
    float c[7];
#pragma unroll
    for (int hl = 0; hl < 7; ++hl) c[hl] = 0.f;
    __syncthreads();

    const float* myPre = sPre + (q*7)*512;
    for (int t = 0; t < T_OUT; ++t) {
        int cur = t & 1, nxt = cur ^ 1;
        const float* sHc = sH + cur*DHL*DEC + q*7*DEC;
        u64 acc[4][7];
#pragma unroll
        for (int g = 0; g < 4; ++g)
#pragma unroll
            for (int hl = 0; hl < 7; ++hl)
                acc[g][hl] = lo2(myPre[hl*512 + g*DEC + uh]);

#pragma unroll 4
        for (int kk = 0; kk < 32; ++kk) {            // k-quads
            ulonglong2 w[4];
#pragma unroll
            for (int g = 0; g < 4; ++g)
                w[g] = *(const ulonglong2*)(g_W4 + ((size_t)kk*512 + g*DEC + uh)*4);
#pragma unroll
            for (int hl = 0; hl < 7; ++hl) {
                ulonglong2 h2 = *(const ulonglong2*)(sHc + hl*DEC + kk*4);
#pragma unroll
                for (int g = 0; g < 4; ++g) {
                    fma2(acc[g][hl], w[g].x, h2.x);
                    fma2(acc[g][hl], w[g].y, h2.y);
                }
            }
        }
#pragma unroll
        for (int hl = 0; hl < 7; ++hl) {
            float ig = sigf(red2(acc[0][hl])), fg = sigf(red2(acc[1][hl]));
            float gg = tanh_fast(red2(acc[2][hl])), og = sigf(red2(acc[3][hl]));
            c[hl] = fmaf(fg, c[hl], ig*gg);
            sH[nxt*DHL*DEC + (q*7 + hl)*DEC + uh] = og * tanh_fast(c[hl]);
        }
        __syncthreads();   // new h visible
        if (tid < 2*DHL) {
            int hl = tid >> 1, d = tid & 1;
            int hero = b0 + hl;
            if (hero < NB) {
                const ulonglong2* wo = (const ulonglong2*)(sWop + d*DEC);
                const ulonglong2* hr = (const ulonglong2*)(sH + nxt*DHL*DEC + hl*DEC);
                u64 a2 = lo2(__ldg(bop + d));
#pragma unroll
                for (int k4 = 0; k4 < DEC/4; ++k4) {
                    ulonglong2 w = wo[k4], h2 = hr[k4];
                    fma2(a2, w.x, h2.x); fma2(a2, w.y, h2.y);
                }
                out[(size_t)t*NB*2 + (size_t)hero*2 + d] = red2(a2);
            }
        }
    }
}

// ============================================================
extern "C" void kernel_launch(void* const* d_in, const int* in_sizes, int n_in,
                              void* d_out, int out_size)
{
    const float* hist  = (const float*)d_in[0];
    const float* nbrs  = (const float*)d_in[1];
    const float* Wip   = (const float*)d_in[2];
    const float* bip   = (const float*)d_in[3];
    const float* Wih_e = (const float*)d_in[4];
    const float* Whh_e = (const float*)d_in[5];
    const float* bih_e = (const float*)d_in[6];
    const float* bhh_e = (const float*)d_in[7];
    const float* Wdyn  = (const float*)d_in[8];
    const float* bdyn  = (const float*)d_in[9];
    const float* Wnbr  = (const float*)d_in[10];
    const float* bnbr  = (const float*)d_in[11];
    const float* Wih_d = (const float*)d_in[12];
    const float* Whh_d = (const float*)d_in[13];
    const float* bih_d = (const float*)d_in[14];
    const float* bhh_d = (const float*)d_in[15];
    const float* Wop   = (const float*)d_in[16];
    const float* bop   = (const float*)d_in[17];
    const int*   seg   = (const int*)d_in[18];
    float* out = (float*)d_out;

    constexpr int FRONT_SMEM = (8192 + 1024 + 2048 + 4096 + 1024 + 1024) * (int)sizeof(float);
    constexpr int DEC_SMEM = (DHL*512 + 2*DHL*DEC + 2*DEC) * (int)sizeof(float);
    cudaFuncSetAttribute(front_kernel, cudaFuncAttributeMaxDynamicSharedMemorySize, FRONT_SMEM);
    cudaFuncSetAttribute(dec_kernel, cudaFuncAttributeMaxDynamicSharedMemorySize, DEC_SMEM);

    prep_kernel<<<96, 256>>>(Whh_d, Wih_d);
    front_kernel<<<NB/HLE, 256, FRONT_SMEM>>>(hist, nbrs, Wip, bip, Wih_e, Whh_e,
                                              bih_e, bhh_e, Wdyn, bdyn, Wnbr, bnbr,
                                              bih_d, bhh_d, seg);
    dec_kernel<<<DGRID, 512, DEC_SMEM>>>(Wop, bop, out);
}

// round 7
// speedup vs baseline: 1.6983x; 1.0001x over previous
#include <cuda_runtime.h>

#define T_IN 16
#define T_OUT 25
#define NB 4096
#define KN 32
#define NNBR (NB*KN)
#define ENC 64
#define DEC 128
#define DYN 32
#define EMB 32
#define DHL 28         // heroes per decoder block (147 blocks x 28 = 4116)
#define DGRID 147
#define HLE 16         // heroes per front block

typedef unsigned long long u64;

// -------- scratch --------
__device__ __align__(16) float g_pre[(size_t)(NB+48)*4*DEC];  // padded for ragged dec grid
__device__ __align__(16) float g_W4[4*DEC*DEC];               // quad-transposed Whh_d
__device__ __align__(16) float g_Wd4[4*DEC*(2*DYN)];          // quad-transposed Wih_d

__device__ __forceinline__ float lrelu(float x){ return x >= 0.f ? x : 0.1f*x; }
__device__ __forceinline__ float sigf(float x){ return __fdividef(1.f, 1.f + __expf(-x)); }
__device__ __forceinline__ float tanh_fast(float x){ return 1.f - __fdividef(2.f, 1.f + __expf(2.f*x)); }

__device__ __forceinline__ void fma2(u64& d, u64 a, u64 b){
    asm("fma.rn.f32x2 %0, %1, %2, %0;" : "+l"(d) : "l"(a), "l"(b));
}
__device__ __forceinline__ u64 packf2(float x, float y){
    u64 r; asm("mov.b64 %0, {%1,%2};" : "=l"(r) : "f"(x), "f"(y)); return r;
}
__device__ __forceinline__ float red2(u64 a){
    float x, y; asm("mov.b64 {%0,%1}, %2;" : "=f"(x), "=f"(y) : "l"(a)); return x + y;
}
__device__ __forceinline__ u64 lo2(float x){ return (u64)__float_as_uint(x); }

// ============================================================
// Kernel 0: quad-transpose Whh_d & Wih_d; zero g_pre pad tail.
// grid 96 x 256 = 24576 threads.
// ============================================================
__global__ void prep_kernel(const float* __restrict__ Whh, const float* __restrict__ Wih)
{
    int idx = blockIdx.x*256 + threadIdx.x;
    if (idx < 32*512) {                              // Whh_d quads (16384)
        int k4 = idx >> 9, r = idx & 511;
        float4 v = *(const float4*)(Whh + r*DEC + k4*4);
        *(float4*)(g_W4 + ((size_t)k4*512 + r)*4) = v;
    } else {
        int j = idx - 32*512;                        // Wih_d quads (8192)
        if (j < 16*512) {
            int k4 = j >> 9, r = j & 511;
            float4 v = *(const float4*)(Wih + r*(2*DYN) + k4*4);
            *(float4*)(g_Wd4 + ((size_t)k4*512 + r)*4) = v;
        }
    }
    // zero padded tail of g_pre (48 heroes x 512 = 24576 elements)
    g_pre[(size_t)NB*512 + idx] = 0.f;
}

// ============================================================
// Kernel 1 (FRONT): neighbor MLP+max  ->  encoder LSTM  ->  Wdyn projections
//                   ->  decoder-input GEMM. 16 heroes/block, 256 threads,
//                   grid 256, occupancy 2 -> single wave.
// smem 68KB dynamic; region R (32KB) overlaid per phase.
// ============================================================
__global__ void __launch_bounds__(256, 2) front_kernel(
        const float* __restrict__ hist, const float* __restrict__ nbrs,
        const float* __restrict__ Wip,  const float* __restrict__ bip,
        const float* __restrict__ Wih,  const float* __restrict__ Whh,
        const float* __restrict__ bih,  const float* __restrict__ bhh,
        const float* __restrict__ Wdyn, const float* __restrict__ bdyn,
        const float* __restrict__ Wnbr, const float* __restrict__ bnbr,
        const float* __restrict__ bih_d,const float* __restrict__ bhh_d,
        const int* __restrict__ seg)
{
    extern __shared__ __align__(16) float sm[];
    float* R     = sm;                  // 8192 floats (32KB): phase A = Wnbr+bnbr,
                                        // phase B = WihT[8][256][4], phase C = Wdyn
    float* sMax  = sm + 8192;           // [16][64]
    float* sH    = sMax + 1024;         // [2][16][64]
    float* sG    = sH + 2048;           // [4][16][64]
    float* sEmbT = sG + 4096;           // [2][16][32]
    float* sEnc  = sEmbT + 1024;        // [16][64]

    int tid = threadIdx.x;
    int b0 = blockIdx.x * HLE;
    int warp = tid >> 5, lane = tid & 31;

    // ---------------- Phase A: neighbor MLP + segment max ----------------
    for (int i = tid; i < ENC*32; i += 256) R[i] = Wnbr[i];
    if (tid < ENC) R[ENC*32 + tid] = bnbr[tid];
    __syncthreads();

#pragma unroll
    for (int p = 0; p < 2; ++p) {
        int hero = warp + p*8;                 // 0..15 local
        int n = (b0 + hero)*KN + lane;
        int sgid = seg[n];
        u64 xp[16];
#pragma unroll
        for (int t = 0; t < T_IN; ++t) {
            float2 hv = *(const float2*)(hist + ((size_t)t*NB + sgid)*2);
            float2 nv = *(const float2*)(nbrs + ((size_t)t*NNBR + n)*2);
            xp[t] = packf2(hv.x - nv.x, hv.y - nv.y);
        }
#pragma unroll 4
        for (int g = 0; g < ENC; ++g) {
            u64 a2 = lo2(R[ENC*32 + g]);
            const ulonglong2* w = (const ulonglong2*)(R + g*32);
#pragma unroll
            for (int k = 0; k < 8; ++k) {
                ulonglong2 wv = w[k];
                fma2(a2, wv.x, xp[2*k]);
                fma2(a2, wv.y, xp[2*k+1]);
            }
            float acc = lrelu(red2(a2));
#pragma unroll
            for (int off = 16; off; off >>= 1)
                acc = fmaxf(acc, __shfl_xor_sync(0xffffffffu, acc, off));
            if (lane == 0) sMax[hero*ENC + g] = acc;
        }
    }
    __syncthreads();   // done with R as Wnbr; sMax complete

    // ---------------- Phase B: encoder LSTM ----------------
    // R := WihT[k>>2][r][k&3]
    for (int i = tid; i < 256*EMB; i += 256) {
        int r = i >> 5, k = i & 31;
        R[(k>>2)*1024 + r*4 + (k&3)] = Wih[i];
    }
    // Wip row for this thread's j (used for on-the-fly emb)
    int jE = tid & 31, hlE = tid >> 5;           // thread covers (hlE, jE) and (hlE+8, jE)
    float w0 = Wip[jE*2], w1 = Wip[jE*2+1], bj = bip[jE];
    // emb for t=0
    {
        const float* hp0 = hist + ((size_t)0*NB + b0 + hlE)*2;
        const float* hp1 = hist + ((size_t)0*NB + b0 + hlE + 8)*2;
        sEmbT[hlE*32 + jE]       = lrelu(fmaf(w0, hp0[0], fmaf(w1, hp0[1], bj)));
        sEmbT[(hlE+8)*32 + jE]   = lrelu(fmaf(w0, hp1[0], fmaf(w1, hp1[1], bj)));
    }
    // Whh row in registers
    u64 whh[32];
    {
        const u64* wrow = (const u64*)(Whh + tid*ENC);
#pragma unroll
        for (int i = 0; i < 32; ++i) whh[i] = wrow[i];
    }
    float bsum = __ldg(bih + tid) + __ldg(bhh + tid);
    int g = tid >> 6, u = tid & 63;
    float c[4];
#pragma unroll
    for (int i = 0; i < 4; ++i) c[i] = 0.f;
    sH[tid] = 0.f; sH[256 + tid] = 0.f; sH[512 + tid] = 0.f; sH[768 + tid] = 0.f;
    __syncthreads();

    for (int t = 0; t < T_IN; ++t) {
        int cur = t & 1, nxt = cur ^ 1;
        u64 acc[16];
#pragma unroll
        for (int hl = 0; hl < 16; ++hl) acc[hl] = lo2(bsum);
        const float* et = sEmbT + cur*512;
#pragma unroll
        for (int kk = 0; kk < 8; ++kk) {
            ulonglong2 w = *(const ulonglong2*)(R + kk*1024 + tid*4);
#pragma unroll
            for (int hl = 0; hl < 16; ++hl) {
                ulonglong2 e = *(const ulonglong2*)(et + hl*32 + kk*4);
                fma2(acc[hl], w.x, e.x);
                fma2(acc[hl], w.y, e.y);
            }
        }
        const float* sHc = sH + cur*1024;
#pragma unroll
        for (int kk = 0; kk < 16; ++kk) {
#pragma unroll
            for (int hl = 0; hl < 16; ++hl) {
                ulonglong2 h2 = *(const ulonglong2*)(sHc + hl*64 + kk*4);
                fma2(acc[hl], whh[2*kk],   h2.x);
                fma2(acc[hl], whh[2*kk+1], h2.y);
            }
        }
#pragma unroll
        for (int hl = 0; hl < 16; ++hl) sG[(g*16 + hl)*64 + u] = red2(acc[hl]);
        __syncthreads();
        // activation (thread owns heroes g, g+4, g+8, g+12) + emb for t+1
#pragma unroll
        for (int i = 0; i < 4; ++i) {
            int hl = g + i*4;
            float ii = sG[(0*16+hl)*64+u], ff = sG[(1*16+hl)*64+u];
            float gg = sG[(2*16+hl)*64+u], oo = sG[(3*16+hl)*64+u];
            c[i] = fmaf(sigf(ff), c[i], sigf(ii)*tanh_fast(gg));
            sH[nxt*1024 + hl*64 + u] = sigf(oo)*tanh_fast(c[i]);
        }
        if (t + 1 < T_IN) {
            const float* hp0 = hist + ((size_t)(t+1)*NB + b0 + hlE)*2;
            const float* hp1 = hist + ((size_t)(t+1)*NB + b0 + hlE + 8)*2;
            sEmbT[nxt*512 + hlE*32 + jE]     = lrelu(fmaf(w0, hp0[0], fmaf(w1, hp0[1], bj)));
            sEmbT[nxt*512 + (hlE+8)*32 + jE] = lrelu(fmaf(w0, hp1[0], fmaf(w1, hp1[1], bj)));
        }
        __syncthreads();
    }
    // final h in sH buffer 0 (T_IN even)

    // ---------------- Phase C: Wdyn projections + decoder-input GEMM ----------------
    for (int i = tid; i < DYN*ENC; i += 256) R[i] = Wdyn[i];
    __syncthreads();
#pragma unroll
    for (int pass = 0; pass < 4; ++pass) {
        int it = tid + pass*256;           // 1024 items = 16 heroes x 64 outputs
        int hero = it >> 6, o = it & 63;
        int row = o & 31;
        const ulonglong2* wr = (const ulonglong2*)(R + row*ENC);
        const ulonglong2* src = (const ulonglong2*)((o < 32) ? (sH + hero*64) : (sMax + hero*64));
        u64 a2 = lo2(__ldg(bdyn + row));
#pragma unroll
        for (int k4 = 0; k4 < ENC/4; ++k4) {
            ulonglong2 w = wr[k4], s = src[k4];
            fma2(a2, w.x, s.x); fma2(a2, w.y, s.y);
        }
        sEnc[hero*64 + o] = lrelu(red2(a2));
    }
    __syncthreads();
#pragma unroll
    for (int pass = 0; pass < 2; ++pass) {
        int r = tid + pass*256;
        u64 acc[16];
        float bs = __ldg(bih_d + r) + __ldg(bhh_d + r);
#pragma unroll
        for (int hl = 0; hl < 16; ++hl) acc[hl] = lo2(bs);
#pragma unroll 4
        for (int k4 = 0; k4 < 16; ++k4) {
            ulonglong2 w = *(const ulonglong2*)(g_Wd4 + ((size_t)k4*512 + r)*4);
#pragma unroll
            for (int hl = 0; hl < 16; ++hl) {
                ulonglong2 e = *(const ulonglong2*)(sEnc + hl*64 + k4*4);
                fma2(acc[hl], w.x, e.x);
                fma2(acc[hl], w.y, e.y);
            }
        }
#pragma unroll
        for (int hl = 0; hl < 16; ++hl)
            g_pre[(size_t)(b0+hl)*512 + r] = red2(acc[hl]);
    }
}

// ============================================================
// Kernel 2: decoder LSTM (25 steps) + output projection.
// 512 threads: uh = tid&127, quarter q = tid>>7 handles 7 heroes of DHL=28.
// grid 147 -> all SMs, single wave. g_pre padded so tail loads are safe.
// ============================================================
__global__ void __launch_bounds__(512, 1) dec_kernel(const float* __restrict__ Wop,
                                                     const float* __restrict__ bop,
                                                     float* __restrict__ out)
{
    extern __shared__ __align__(16) float dsm[];
    float* sPre = dsm;                  // [28][512] 56KB
    float* sH   = dsm + DHL*512;        // [2][28][128] 28KB
    float* sWop = sH + 2*DHL*DEC;       // [2][128]

    int tid = threadIdx.x;
    int uh = tid & 127, q = tid >> 7;
    int b0 = blockIdx.x * DHL;
    for (int i = tid; i < DHL*512; i += 512) sPre[i] = g_pre[(size_t)b0*512 + i];
    for (int i = tid; i < 2*DEC; i += 512) sWop[i] = Wop[i];
    for (int i = tid; i < DHL*DEC; i += 512) sH[i] = 0.f;
    float c[7];
#pragma unroll
    for (int hl = 0; hl < 7; ++hl) c[hl] = 0.f;
    __syncthreads();

    const float* myPre = sPre + (q*7)*512;
    for (int t = 0; t < T_OUT; ++t) {
        int cur = t & 1, nxt = cur ^ 1;
        const float* sHc = sH + cur*DHL*DEC + q*7*DEC;
        u64 acc[4][7];
#pragma unroll
        for (int g = 0; g < 4; ++g)
#pragma unroll
            for (int hl = 0; hl < 7; ++hl)
                acc[g][hl] = lo2(myPre[hl*512 + g*DEC + uh]);

#pragma unroll 4
        for (int kk = 0; kk < 32; ++kk) {            // k-quads
            ulonglong2 w[4];
#pragma unroll
            for (int g = 0; g < 4; ++g)
                w[g] = *(const ulonglong2*)(g_W4 + ((size_t)kk*512 + g*DEC + uh)*4);
#pragma unroll
            for (int hl = 0; hl < 7; ++hl) {
                ulonglong2 h2 = *(const ulonglong2*)(sHc + hl*DEC + kk*4);
#pragma unroll
                for (int g = 0; g < 4; ++g) {
                    fma2(acc[g][hl], w[g].x, h2.x);
                    fma2(acc[g][hl], w[g].y, h2.y);
                }
            }
        }
#pragma unroll
        for (int hl = 0; hl < 7; ++hl) {
            float ig = sigf(red2(acc[0][hl])), fg = sigf(red2(acc[1][hl]));
            float gg = tanh_fast(red2(acc[2][hl])), og = sigf(red2(acc[3][hl]));
            c[hl] = fmaf(fg, c[hl], ig*gg);
            sH[nxt*DHL*DEC + (q*7 + hl)*DEC + uh] = og * tanh_fast(c[hl]);
        }
        __syncthreads();   // new h visible
        if (tid < 2*DHL) {
            int hl = tid >> 1, d = tid & 1;
            int hero = b0 + hl;
            if (hero < NB) {
                const ulonglong2* wo = (const ulonglong2*)(sWop + d*DEC);
                const ulonglong2* hr = (const ulonglong2*)(sH + nxt*DHL*DEC + hl*DEC);
                u64 a2 = lo2(__ldg(bop + d));
#pragma unroll
                for (int k4 = 0; k4 < DEC/4; ++k4) {
                    ulonglong2 w = wo[k4], h2 = hr[k4];
                    fma2(a2, w.x, h2.x); fma2(a2, w.y, h2.y);
                }
                out[(size_t)t*NB*2 + (size_t)hero*2 + d] = red2(a2);
            }
        }
    }
}

// ============================================================
extern "C" void kernel_launch(void* const* d_in, const int* in_sizes, int n_in,
                              void* d_out, int out_size)
{
    const float* hist  = (const float*)d_in[0];
    const float* nbrs  = (const float*)d_in[1];
    const float* Wip   = (const float*)d_in[2];
    const float* bip   = (const float*)d_in[3];
    const float* Wih_e = (const float*)d_in[4];
    const float* Whh_e = (const float*)d_in[5];
    const float* bih_e = (const float*)d_in[6];
    const float* bhh_e = (const float*)d_in[7];
    const float* Wdyn  = (const float*)d_in[8];
    const float* bdyn  = (const float*)d_in[9];
    const float* Wnbr  = (const float*)d_in[10];
    const float* bnbr  = (const float*)d_in[11];
    const float* Wih_d = (const float*)d_in[12];
    const float* Whh_d = (const float*)d_in[13];
    const float* bih_d = (const float*)d_in[14];
    const float* bhh_d = (const float*)d_in[15];
    const float* Wop   = (const float*)d_in[16];
    const float* bop   = (const float*)d_in[17];
    const int*   seg   = (const int*)d_in[18];
    float* out = (float*)d_out;

    constexpr int FRONT_SMEM = (8192 + 1024 + 2048 + 4096 + 1024 + 1024) * (int)sizeof(float);
    constexpr int DEC_SMEM = (DHL*512 + 2*DHL*DEC + 2*DEC) * (int)sizeof(float);
    cudaFuncSetAttribute(front_kernel, cudaFuncAttributeMaxDynamicSharedMemorySize, FRONT_SMEM);
    cudaFuncSetAttribute(dec_kernel, cudaFuncAttributeMaxDynamicSharedMemorySize, DEC_SMEM);

    prep_kernel<<<96, 256>>>(Whh_d, Wih_d);
    front_kernel<<<NB/HLE, 256, FRONT_SMEM>>>(hist, nbrs, Wip, bip, Wih_e, Whh_e,
                                              bih_e, bhh_e, Wdyn, bdyn, Wnbr, bnbr,
                                              bih_d, bhh_d, seg);
    dec_kernel<<<DGRID, 512, DEC_SMEM>>>(Wop, bop, out);
}

// round 9
// speedup vs baseline: 2.5365x; 1.4935x over previous
#include <cuda_runtime.h>
#include <cuda_fp16.h>
#include <cstdint>

#define T_IN 16
#define T_OUT 25
#define NB 4096
#define KN 32
#define NNBR (NB*KN)
#define ENC 64
#define DEC 128
#define DYN 32
#define EMB 32
#define HLE 16

typedef unsigned long long u64;

// -------- scratch --------
__device__ __align__(16) float g_preT[(size_t)512*NB];      // 8 MB, gate-row-major
__device__ __align__(16) float g_Wd4[4*DEC*(2*DYN)];        // quad-transposed Wih_d
__device__ __align__(16) uint4 g_A[32*8*2*32];              // pre-fragmented Whh_d (hi/lo fp16)

__device__ __forceinline__ float lrelu(float x){ return x >= 0.f ? x : 0.1f*x; }
__device__ __forceinline__ float sigf(float x){ return __fdividef(1.f, 1.f + __expf(-x)); }
__device__ __forceinline__ float tanh_fast(float x){ return 1.f - __fdividef(2.f, 1.f + __expf(2.f*x)); }

__device__ __forceinline__ void fma2(u64& d, u64 a, u64 b){
    asm("fma.rn.f32x2 %0, %1, %2, %0;" : "+l"(d) : "l"(a), "l"(b));
}
__device__ __forceinline__ u64 packf2(float x, float y){
    u64 r; asm("mov.b64 %0, {%1,%2};" : "=l"(r) : "f"(x), "f"(y)); return r;
}
__device__ __forceinline__ float red2(u64 a){
    float x, y; asm("mov.b64 {%0,%1}, %2;" : "=f"(x), "=f"(y) : "l"(a)); return x + y;
}
__device__ __forceinline__ u64 lo2(float x){ return (u64)__float_as_uint(x); }

// mma.sync m16n8k16 fp16 -> f32, D accum in place
#define MMA(d, a, bx, by) \
    asm volatile("mma.sync.aligned.m16n8k16.row.col.f32.f16.f16.f32 " \
        "{%0,%1,%2,%3},{%4,%5,%6,%7},{%8,%9},{%0,%1,%2,%3};" \
        : "+f"((d)[0]), "+f"((d)[1]), "+f"((d)[2]), "+f"((d)[3]) \
        : "r"((a).x), "r"((a).y), "r"((a).z), "r"((a).w), "r"(bx), "r"(by))

// pack two floats' hi- or lo-fp16 halves into one b32
__device__ __forceinline__ unsigned ph2(float a, float b, int hl){
    __half ah = __float2half_rn(a), bh = __float2half_rn(b);
    __half x = hl ? __float2half_rn(a - __half2float(ah)) : ah;
    __half y = hl ? __float2half_rn(b - __half2float(bh)) : bh;
    return (unsigned)__half_as_ushort(x) | ((unsigned)__half_as_ushort(y) << 16);
}

// ============================================================
// Kernel 0: pre-fragment Whh_d (fp16 hi/lo, mma A-frag layout);
//           quad-transpose Wih_d.
// A frag (m16k16 row-major, lane l, gr=l>>2, ct=l&3):
//   a0={A[gr][2ct],A[gr][2ct+1]} a1={A[gr+8][..]} a2={A[gr][2ct+8..9]} a3={A[gr+8][+8..9]}
// Packed row pr = 4u+g  (u=unit 0..127, g=gate i/f/g/o). Orig row = g*128+u.
// ============================================================
__global__ void prep_kernel(const float* __restrict__ Whh, const float* __restrict__ Wih)
{
    int idx = blockIdx.x*256 + threadIdx.x;
    if (idx < 16384) {
        int mt = idx >> 9, ks = (idx >> 6) & 7, hl = (idx >> 5) & 1, l = idx & 31;
        int gr = l >> 2, ct = l & 3;
        int pr0 = 16*mt + gr, pr1 = pr0 + 8;
        int k0 = 16*ks + 2*ct;
        int r0 = (pr0 & 3)*128 + (pr0 >> 2);
        int r1 = (pr1 & 3)*128 + (pr1 >> 2);
        uint4 v;
        v.x = ph2(Whh[r0*128 + k0],     Whh[r0*128 + k0 + 1], hl);
        v.y = ph2(Whh[r1*128 + k0],     Whh[r1*128 + k0 + 1], hl);
        v.z = ph2(Whh[r0*128 + k0 + 8], Whh[r0*128 + k0 + 9], hl);
        v.w = ph2(Whh[r1*128 + k0 + 8], Whh[r1*128 + k0 + 9], hl);
        g_A[((mt*8 + ks)*2 + hl)*32 + l] = v;
    } else {
        int j = idx - 16384;
        if (j < 16*512) {
            int k4 = j >> 9, r = j & 511;
            float4 v = *(const float4*)(Wih + r*(2*DYN) + k4*4);
            *(float4*)(g_Wd4 + ((size_t)k4*512 + r)*4) = v;
        }
    }
}

// ============================================================
// Kernel 1 (FRONT): unchanged logic from R6 except the final store
// goes to gate-row-major g_preT.
// ============================================================
__global__ void __launch_bounds__(256, 2) front_kernel(
        const float* __restrict__ hist, const float* __restrict__ nbrs,
        const float* __restrict__ Wip,  const float* __restrict__ bip,
        const float* __restrict__ Wih,  const float* __restrict__ Whh,
        const float* __restrict__ bih,  const float* __restrict__ bhh,
        const float* __restrict__ Wdyn, const float* __restrict__ bdyn,
        const float* __restrict__ Wnbr, const float* __restrict__ bnbr,
        const float* __restrict__ bih_d,const float* __restrict__ bhh_d,
        const int* __restrict__ seg)
{
    extern __shared__ __align__(16) float sm[];
    float* R     = sm;
    float* sMax  = sm + 8192;
    float* sH    = sMax + 1024;
    float* sG    = sH + 2048;
    float* sEmbT = sG + 4096;
    float* sEnc  = sEmbT + 1024;

    int tid = threadIdx.x;
    int b0 = blockIdx.x * HLE;
    int warp = tid >> 5, lane = tid & 31;

    for (int i = tid; i < ENC*32; i += 256) R[i] = Wnbr[i];
    if (tid < ENC) R[ENC*32 + tid] = bnbr[tid];
    __syncthreads();
#pragma unroll
    for (int p = 0; p < 2; ++p) {
        int hero = warp + p*8;
        int n = (b0 + hero)*KN + lane;
        int sgid = seg[n];
        u64 xp[16];
#pragma unroll
        for (int t = 0; t < T_IN; ++t) {
            float2 hv = *(const float2*)(hist + ((size_t)t*NB + sgid)*2);
            float2 nv = *(const float2*)(nbrs + ((size_t)t*NNBR + n)*2);
            xp[t] = packf2(hv.x - nv.x, hv.y - nv.y);
        }
#pragma unroll 4
        for (int g = 0; g < ENC; ++g) {
            u64 a2 = lo2(R[ENC*32 + g]);
            const ulonglong2* w = (const ulonglong2*)(R + g*32);
#pragma unroll
            for (int k = 0; k < 8; ++k) {
                ulonglong2 wv = w[k];
                fma2(a2, wv.x, xp[2*k]);
                fma2(a2, wv.y, xp[2*k+1]);
            }
            float acc = lrelu(red2(a2));
#pragma unroll
            for (int off = 16; off; off >>= 1)
                acc = fmaxf(acc, __shfl_xor_sync(0xffffffffu, acc, off));
            if (lane == 0) sMax[hero*ENC + g] = acc;
        }
    }
    __syncthreads();

    for (int i = tid; i < 256*EMB; i += 256) {
        int r = i >> 5, k = i & 31;
        R[(k>>2)*1024 + r*4 + (k&3)] = Wih[i];
    }
    int jE = tid & 31, hlE = tid >> 5;
    float w0 = Wip[jE*2], w1 = Wip[jE*2+1], bj = bip[jE];
    {
        const float* hp0 = hist + ((size_t)0*NB + b0 + hlE)*2;
        const float* hp1 = hist + ((size_t)0*NB + b0 + hlE + 8)*2;
        sEmbT[hlE*32 + jE]     = lrelu(fmaf(w0, hp0[0], fmaf(w1, hp0[1], bj)));
        sEmbT[(hlE+8)*32 + jE] = lrelu(fmaf(w0, hp1[0], fmaf(w1, hp1[1], bj)));
    }
    u64 whh[32];
    {
        const u64* wrow = (const u64*)(Whh + tid*ENC);
#pragma unroll
        for (int i = 0; i < 32; ++i) whh[i] = wrow[i];
    }
    float bsum = __ldg(bih + tid) + __ldg(bhh + tid);
    int g = tid >> 6, u = tid & 63;
    float c[4];
#pragma unroll
    for (int i = 0; i < 4; ++i) c[i] = 0.f;
    sH[tid] = 0.f; sH[256 + tid] = 0.f; sH[512 + tid] = 0.f; sH[768 + tid] = 0.f;
    __syncthreads();

    for (int t = 0; t < T_IN; ++t) {
        int cur = t & 1, nxt = cur ^ 1;
        u64 acc[16];
#pragma unroll
        for (int hl = 0; hl < 16; ++hl) acc[hl] = lo2(bsum);
        const float* et = sEmbT + cur*512;
#pragma unroll
        for (int kk = 0; kk < 8; ++kk) {
            ulonglong2 w = *(const ulonglong2*)(R + kk*1024 + tid*4);
#pragma unroll
            for (int hl = 0; hl < 16; ++hl) {
                ulonglong2 e = *(const ulonglong2*)(et + hl*32 + kk*4);
                fma2(acc[hl], w.x, e.x);
                fma2(acc[hl], w.y, e.y);
            }
        }
        const float* sHc = sH + cur*1024;
#pragma unroll
        for (int kk = 0; kk < 16; ++kk) {
#pragma unroll
            for (int hl = 0; hl < 16; ++hl) {
                ulonglong2 h2 = *(const ulonglong2*)(sHc + hl*64 + kk*4);
                fma2(acc[hl], whh[2*kk],   h2.x);
                fma2(acc[hl], whh[2*kk+1], h2.y);
            }
        }
#pragma unroll
        for (int hl = 0; hl < 16; ++hl) sG[(g*16 + hl)*64 + u] = red2(acc[hl]);
        __syncthreads();
#pragma unroll
        for (int i = 0; i < 4; ++i) {
            int hl = g + i*4;
            float ii = sG[(0*16+hl)*64+u], ff = sG[(1*16+hl)*64+u];
            float gg = sG[(2*16+hl)*64+u], oo = sG[(3*16+hl)*64+u];
            c[i] = fmaf(sigf(ff), c[i], sigf(ii)*tanh_fast(gg));
            sH[nxt*1024 + hl*64 + u] = sigf(oo)*tanh_fast(c[i]);
        }
        if (t + 1 < T_IN) {
            const float* hp0 = hist + ((size_t)(t+1)*NB + b0 + hlE)*2;
            const float* hp1 = hist + ((size_t)(t+1)*NB + b0 + hlE + 8)*2;
            sEmbT[nxt*512 + hlE*32 + jE]     = lrelu(fmaf(w0, hp0[0], fmaf(w1, hp0[1], bj)));
            sEmbT[nxt*512 + (hlE+8)*32 + jE] = lrelu(fmaf(w0, hp1[0], fmaf(w1, hp1[1], bj)));
        }
        __syncthreads();
    }

    for (int i = tid; i < DYN*ENC; i += 256) R[i] = Wdyn[i];
    __syncthreads();
#pragma unroll
    for (int pass = 0; pass < 4; ++pass) {
        int it = tid + pass*256;
        int hero = it >> 6, o = it & 63;
        int row = o & 31;
        const ulonglong2* wr = (const ulonglong2*)(R + row*ENC);
        const ulonglong2* src = (const ulonglong2*)((o < 32) ? (sH + hero*64) : (sMax + hero*64));
        u64 a2 = lo2(__ldg(bdyn + row));
#pragma unroll
        for (int k4 = 0; k4 < ENC/4; ++k4) {
            ulonglong2 w = wr[k4], s = src[k4];
            fma2(a2, w.x, s.x); fma2(a2, w.y, s.y);
        }
        sEnc[hero*64 + o] = lrelu(red2(a2));
    }
    __syncthreads();
#pragma unroll
    for (int pass = 0; pass < 2; ++pass) {
        int r = tid + pass*256;
        u64 acc[16];
        float bs = __ldg(bih_d + r) + __ldg(bhh_d + r);
#pragma unroll
        for (int hl = 0; hl < 16; ++hl) acc[hl] = lo2(bs);
#pragma unroll 4
        for (int k4 = 0; k4 < 16; ++k4) {
            ulonglong2 w = *(const ulonglong2*)(g_Wd4 + ((size_t)k4*512 + r)*4);
#pragma unroll
            for (int hl = 0; hl < 16; ++hl) {
                ulonglong2 e = *(const ulonglong2*)(sEnc + hl*64 + k4*4);
                fma2(acc[hl], w.x, e.x);
                fma2(acc[hl], w.y, e.y);
            }
        }
        // gate-row-major store for the HMMA decoder
#pragma unroll
        for (int hl = 0; hl < 16; ++hl)
            g_preT[(size_t)r*NB + b0 + hl] = red2(acc[hl]);
    }
}

// ============================================================
// Kernel 2: HMMA decoder. 128 CTAs x 32 heroes, 512 threads (16 warps).
// Warp w owns M16-tiles w and w+16 (packed rows pr=4u+g), N=32 heroes.
// A: pre-fragmented global (LDG.128). B: pre-fragmented smem, stride-5
// 16B-unit padding, double-buffered; epilogue writes h hi/lo directly
// into fragment positions.
// ============================================================
__global__ void __launch_bounds__(512, 1) dec_kernel(const float* __restrict__ Wop,
                                                     const float* __restrict__ bop,
                                                     float* __restrict__ out)
{
    extern __shared__ __align__(16) float dsm[];
    float* sD   = dsm;                 // [512][34]  69632 B
    float* sHf  = dsm + 512*34;        // [32][130]  16640 B
    float* sWop = sHf + 32*130;        // 256 floats
    float* Bbuf0 = sWop + 256;         // 5120 floats (20 KB): [8ks][32l][5 pad-units][4 words]
    float* Bbuf1 = Bbuf0 + 5120;

    int tid = threadIdx.x;
    int w = tid >> 5, lane = tid & 31;
    int gr = lane >> 2, ct = lane & 3;
    int b0h = blockIdx.x * 32;
    int n = tid & 31;                 // LSTM hero
    int ubase = (tid >> 5) * 8;       // LSTM units [ubase, ubase+8)

    for (int i = tid; i < 10240; i += 512) Bbuf0[i] = 0.f;   // zeros both buffers
    if (tid < 256) sWop[tid] = Wop[tid];

    // pre (gate-row-major, coalesced across lanes)
    float pre[4][8];
#pragma unroll
    for (int g = 0; g < 4; ++g)
#pragma unroll
        for (int i = 0; i < 8; ++i)
            pre[g][i] = __ldg(&g_preT[(size_t)(g*128 + ubase + i)*NB + b0h + n]);

    float c[8];
#pragma unroll
    for (int i = 0; i < 8; ++i) c[i] = 0.f;
    __syncthreads();

    for (int t = 0; t < T_OUT; ++t) {
        const float* Bc = (t & 1) ? Bbuf1 : Bbuf0;
        float* Bn = (t & 1) ? Bbuf0 : Bbuf1;

        float acc[2][4][4];
#pragma unroll
        for (int m = 0; m < 2; ++m)
#pragma unroll
            for (int nb = 0; nb < 4; ++nb)
#pragma unroll
                for (int r = 0; r < 4; ++r) acc[m][nb][r] = 0.f;

#pragma unroll
        for (int ks = 0; ks < 8; ++ks) {
            const uint4* bp = (const uint4*)(Bc + (ks*32 + lane)*20);
            uint4 bv[4];
#pragma unroll
            for (int nb = 0; nb < 4; ++nb) bv[nb] = bp[nb];
#pragma unroll
            for (int m = 0; m < 2; ++m) {
                int mt = w + 16*m;
                uint4 ahi = __ldg(&g_A[((mt*8 + ks)*2 + 0)*32 + lane]);
                uint4 alo = __ldg(&g_A[((mt*8 + ks)*2 + 1)*32 + lane]);
#pragma unroll
                for (int nb = 0; nb < 4; ++nb) {
                    MMA(acc[m][nb], ahi, bv[nb].x, bv[nb].y);   // hi*hi
                    MMA(acc[m][nb], ahi, bv[nb].z, bv[nb].w);   // hi*lo
                    MMA(acc[m][nb], alo, bv[nb].x, bv[nb].y);   // lo*hi
                }
            }
        }
        // C frags -> sD   (c0,c1 = row gr cols 2ct,2ct+1; c2,c3 = row gr+8)
#pragma unroll
        for (int m = 0; m < 2; ++m) {
            int pr = 16*(w + 16*m) + gr;
#pragma unroll
            for (int nb = 0; nb < 4; ++nb) {
                int col = 8*nb + 2*ct;
                *(float2*)&sD[pr*34 + col]     = make_float2(acc[m][nb][0], acc[m][nb][1]);
                *(float2*)&sD[(pr+8)*34 + col] = make_float2(acc[m][nb][2], acc[m][nb][3]);
            }
        }
        __syncthreads();
        // LSTM: 8 (unit, hero=n) items per thread
#pragma unroll
        for (int i = 0; i < 8; ++i) {
            int u = ubase + i;
            float gi = sD[(4*u+0)*34 + n] + pre[0][i];
            float gf = sD[(4*u+1)*34 + n] + pre[1][i];
            float gg = sD[(4*u+2)*34 + n] + pre[2][i];
            float go = sD[(4*u+3)*34 + n] + pre[3][i];
            c[i] = fmaf(sigf(gf), c[i], sigf(gi)*tanh_fast(gg));
            float hv = sigf(go) * tanh_fast(c[i]);
            sHf[n*130 + u] = hv;
            __half hhi = __float2half_rn(hv);
            __half hlo = __float2half_rn(hv - __half2float(hhi));
            // B frag position: b0={B[2ct'][n'],B[2ct'+1][n']}, b1 = rows +8
            int ks2 = u >> 4, kk = u & 15;
            int rg = kk >> 3, ctq = (kk & 7) >> 1, dl = kk & 1;
            int lp = (n & 7)*4 + ctq, nbl = n >> 3;
            char* bptr = (char*)(Bn + (ks2*32 + lp)*20) + nbl*16 + rg*4 + dl*2;
            *(__half*)bptr = hhi;
            *(__half*)(bptr + 8) = hlo;
        }
        __syncthreads();
        // output projection
        if (tid < 64) {
            int hero = tid >> 1, d = tid & 1;
            u64 a2 = lo2(__ldg(bop + d));
            const u64* wo = (const u64*)(sWop + d*128);
            const u64* hr = (const u64*)(sHf + hero*130);
#pragma unroll
            for (int k2 = 0; k2 < 64; ++k2) fma2(a2, wo[k2], hr[k2]);
            out[(size_t)t*NB*2 + (size_t)(b0h + hero)*2 + d] = red2(a2);
        }
    }
}

// ============================================================
extern "C" void kernel_launch(void* const* d_in, const int* in_sizes, int n_in,
                              void* d_out, int out_size)
{
    const float* hist  = (const float*)d_in[0];
    const float* nbrs  = (const float*)d_in[1];
    const float* Wip   = (const float*)d_in[2];
    const float* bip   = (const float*)d_in[3];
    const float* Wih_e = (const float*)d_in[4];
    const float* Whh_e = (const float*)d_in[5];
    const float* bih_e = (const float*)d_in[6];
    const float* bhh_e = (const float*)d_in[7];
    const float* Wdyn  = (const float*)d_in[8];
    const float* bdyn  = (const float*)d_in[9];
    const float* Wnbr  = (const float*)d_in[10];
    const float* bnbr  = (const float*)d_in[11];
    const float* Wih_d = (const float*)d_in[12];
    const float* Whh_d = (const float*)d_in[13];
    const float* bih_d = (const float*)d_in[14];
    const float* bhh_d = (const float*)d_in[15];
    const float* Wop   = (const float*)d_in[16];
    const float* bop   = (const float*)d_in[17];
    const int*   seg   = (const int*)d_in[18];
    float* out = (float*)d_out;

    constexpr int FRONT_SMEM = (8192 + 1024 + 2048 + 4096 + 1024 + 1024) * (int)sizeof(float);
    constexpr int DEC_SMEM = (512*34 + 32*130 + 256 + 2*5120) * (int)sizeof(float);
    cudaFuncSetAttribute(front_kernel, cudaFuncAttributeMaxDynamicSharedMemorySize, FRONT_SMEM);
    cudaFuncSetAttribute(dec_kernel, cudaFuncAttributeMaxDynamicSharedMemorySize, DEC_SMEM);

    prep_kernel<<<96, 256>>>(Whh_d, Wih_d);
    front_kernel<<<NB/HLE, 256, FRONT_SMEM>>>(hist, nbrs, Wip, bip, Wih_e, Whh_e,
                                              bih_e, bhh_e, Wdyn, bdyn, Wnbr, bnbr,
                                              bih_d, bhh_d, seg);
    dec_kernel<<<NB/32, 512, DEC_SMEM>>>(Wop, bop, out);
}

// round 10
// speedup vs baseline: 3.5250x; 1.3897x over previous
#include <cuda_runtime.h>
#include <cuda_fp16.h>
#include <cstdint>

#define T_IN 16
#define T_OUT 25
#define NB 4096
#define KN 32
#define NNBR (NB*KN)
#define ENC 64
#define DEC 128
#define DYN 32
#define EMB 32
#define FHL 32

typedef unsigned long long u64;

// -------- scratch --------
__device__ __align__(16) float g_preT[(size_t)512*NB];      // 8 MB, gate-row-major
__device__ __align__(16) float g_Wd4[4*DEC*(2*DYN)];        // quad-transposed Wih_d
__device__ __align__(16) uint4 g_A[32*8*2*32];              // dec Whh_d frags (hi/lo)
__device__ __align__(16) uint4 g_Ae[16*6*2*32];             // enc [Whh_e|Wih_e] frags (hi/lo)

__device__ __forceinline__ float lrelu(float x){ return x >= 0.f ? x : 0.1f*x; }
__device__ __forceinline__ float sigf(float x){ return __fdividef(1.f, 1.f + __expf(-x)); }
__device__ __forceinline__ float tanh_fast(float x){ return 1.f - __fdividef(2.f, 1.f + __expf(2.f*x)); }

__device__ __forceinline__ void fma2(u64& d, u64 a, u64 b){
    asm("fma.rn.f32x2 %0, %1, %2, %0;" : "+l"(d) : "l"(a), "l"(b));
}
__device__ __forceinline__ u64 packf2(float x, float y){
    u64 r; asm("mov.b64 %0, {%1,%2};" : "=l"(r) : "f"(x), "f"(y)); return r;
}
__device__ __forceinline__ float red2(u64 a){
    float x, y; asm("mov.b64 {%0,%1}, %2;" : "=f"(x), "=f"(y) : "l"(a)); return x + y;
}
__device__ __forceinline__ u64 lo2(float x){ return (u64)__float_as_uint(x); }

#define MMA(d, a, bx, by) \
    asm volatile("mma.sync.aligned.m16n8k16.row.col.f32.f16.f16.f32 " \
        "{%0,%1,%2,%3},{%4,%5,%6,%7},{%8,%9},{%0,%1,%2,%3};" \
        : "+f"((d)[0]), "+f"((d)[1]), "+f"((d)[2]), "+f"((d)[3]) \
        : "r"((a).x), "r"((a).y), "r"((a).z), "r"((a).w), "r"(bx), "r"(by))

__device__ __forceinline__ unsigned ph2(float a, float b, int hl){
    __half ah = __float2half_rn(a), bh = __float2half_rn(b);
    __half x = hl ? __float2half_rn(a - __half2float(ah)) : ah;
    __half y = hl ? __float2half_rn(b - __half2float(bh)) : bh;
    return (unsigned)__half_as_ushort(x) | ((unsigned)__half_as_ushort(y) << 16);
}

// store one fp32 value as hi/lo halves into a B-fragment buffer (verified mapping)
__device__ __forceinline__ void bfrag_store(float* Bn, int k, int n, float v){
    __half hhi = __float2half_rn(v);
    __half hlo = __float2half_rn(v - __half2float(hhi));
    int ks2 = k >> 4, kk = k & 15;
    int rg = kk >> 3, ctq = (kk & 7) >> 1, dl = kk & 1;
    int lp = (n & 7)*4 + ctq, nbl = n >> 3;
    char* bptr = (char*)(Bn + (ks2*32 + lp)*20) + nbl*16 + rg*4 + dl*2;
    *(__half*)bptr = hhi;
    *(__half*)(bptr + 8) = hlo;
}

// ============================================================
// Kernel 0: fragment Whh_d (dec) and [Whh_e|Wih_e] (enc); transpose Wih_d.
// grid 120 x 256 = 30720.
// ============================================================
__global__ void prep_kernel(const float* __restrict__ WhhD, const float* __restrict__ WihD,
                            const float* __restrict__ WhhE, const float* __restrict__ WihE)
{
    int idx = blockIdx.x*256 + threadIdx.x;
    if (idx < 16384) {
        int mt = idx >> 9, ks = (idx >> 6) & 7, hl = (idx >> 5) & 1, l = idx & 31;
        int gr = l >> 2, ct = l & 3;
        int pr0 = 16*mt + gr, pr1 = pr0 + 8;
        int k0 = 16*ks + 2*ct;
        int r0 = (pr0 & 3)*128 + (pr0 >> 2);
        int r1 = (pr1 & 3)*128 + (pr1 >> 2);
        uint4 v;
        v.x = ph2(WhhD[r0*128 + k0],     WhhD[r0*128 + k0 + 1], hl);
        v.y = ph2(WhhD[r1*128 + k0],     WhhD[r1*128 + k0 + 1], hl);
        v.z = ph2(WhhD[r0*128 + k0 + 8], WhhD[r0*128 + k0 + 9], hl);
        v.w = ph2(WhhD[r1*128 + k0 + 8], WhhD[r1*128 + k0 + 9], hl);
        g_A[((mt*8 + ks)*2 + hl)*32 + l] = v;
    } else if (idx < 24576) {
        int j = idx - 16384;
        int k4 = j >> 9, r = j & 511;
        float4 v = *(const float4*)(WihD + r*(2*DYN) + k4*4);
        *(float4*)(g_Wd4 + ((size_t)k4*512 + r)*4) = v;
    } else {
        int j2 = idx - 24576;        // < 6144
        int mt = j2 / 384;
        int rem = j2 - mt*384;
        int ks = rem >> 6, hl = (rem >> 5) & 1, l = rem & 31;
        int gr = l >> 2, ct = l & 3;
        int pr0 = 16*mt + gr, pr1 = pr0 + 8;
        int k0 = 16*ks + 2*ct;
        auto W = [&](int pr, int k) -> float {
            int u = pr >> 2, g = pr & 3, row = g*64 + u;
            return (k < 64) ? WhhE[row*64 + k] : WihE[row*32 + (k - 64)];
        };
        uint4 v;
        v.x = ph2(W(pr0,k0),   W(pr0,k0+1), hl);
        v.y = ph2(W(pr1,k0),   W(pr1,k0+1), hl);
        v.z = ph2(W(pr0,k0+8), W(pr0,k0+9), hl);
        v.w = ph2(W(pr1,k0+8), W(pr1,k0+9), hl);
        g_Ae[((mt*6 + ks)*2 + hl)*32 + l] = v;
    }
}

// ============================================================
// Kernel 1 (FRONT): nbr MLP+max -> HMMA encoder -> Wdyn proj -> dec-input GEMM.
// 32 heroes/block, 256 threads (8 warps), grid 128.
// ============================================================
__global__ void __launch_bounds__(256, 1) front_kernel(
        const float* __restrict__ hist, const float* __restrict__ nbrs,
        const float* __restrict__ Wip,  const float* __restrict__ bip,
        const float* __restrict__ bih,  const float* __restrict__ bhh,
        const float* __restrict__ Wdyn, const float* __restrict__ bdyn,
        const float* __restrict__ Wnbr, const float* __restrict__ bnbr,
        const float* __restrict__ bih_d,const float* __restrict__ bhh_d,
        const int* __restrict__ seg)
{
    extern __shared__ __align__(16) float sm[];
    float* sD   = sm;               // 8704 floats: A=Wnbr+b, B=gates[256][34], C=WdynT
    float* Bb0  = sm + 8704;        // 3840: [6ks][32][20]
    float* Bb1  = Bb0 + 3840;       // 3840
    float* sMax = Bb1 + 3840;       // 2048 [hero][64]
    float* sHT  = sMax + 2048;      // 2112 [u*33+n] final h
    float* sEnc = sHT + 2112;       // 2048 [hero][64]

    int tid = threadIdx.x;
    int b0 = blockIdx.x * FHL;
    int warp = tid >> 5, lane = tid & 31;

    // ---------------- Phase A: neighbor MLP + segment max ----------------
    for (int i = tid; i < ENC*32; i += 256) sD[i] = Wnbr[i];
    if (tid < ENC) sD[ENC*32 + tid] = bnbr[tid];
    __syncthreads();
#pragma unroll
    for (int p = 0; p < 4; ++p) {
        int hero = warp + p*8;
        int n = (b0 + hero)*KN + lane;
        int sgid = seg[n];
        u64 xp[16];
#pragma unroll
        for (int t = 0; t < T_IN; ++t) {
            float2 hv = *(const float2*)(hist + ((size_t)t*NB + sgid)*2);
            float2 nv = *(const float2*)(nbrs + ((size_t)t*NNBR + n)*2);
            xp[t] = packf2(hv.x - nv.x, hv.y - nv.y);
        }
#pragma unroll 4
        for (int g = 0; g < ENC; ++g) {
            u64 a2 = lo2(sD[ENC*32 + g]);
            const ulonglong2* w = (const ulonglong2*)(sD + g*32);
#pragma unroll
            for (int k = 0; k < 8; ++k) {
                ulonglong2 wv = w[k];
                fma2(a2, wv.x, xp[2*k]);
                fma2(a2, wv.y, xp[2*k+1]);
            }
            float acc = lrelu(red2(a2));
#pragma unroll
            for (int off = 16; off; off >>= 1)
                acc = fmaxf(acc, __shfl_xor_sync(0xffffffffu, acc, off));
            if (lane == 0) sMax[hero*ENC + g] = acc;
        }
    }
    __syncthreads();

    // ---------------- Phase B: HMMA encoder ----------------
    for (int i = tid; i < 7680; i += 256) Bb0[i] = 0.f;   // both buffers
    int nn = tid & 31, ub = (tid >> 5) * 8;
    float bsum[4][8];
#pragma unroll
    for (int g = 0; g < 4; ++g)
#pragma unroll
        for (int i = 0; i < 8; ++i)
            bsum[g][i] = __ldg(bih + g*64 + ub + i) + __ldg(bhh + g*64 + ub + i);
    int jb = (tid >> 5) * 4;
    float wj0[4], wj1[4], bj[4];
#pragma unroll
    for (int jj = 0; jj < 4; ++jj) {
        wj0[jj] = Wip[(jb+jj)*2]; wj1[jj] = Wip[(jb+jj)*2+1]; bj[jj] = bip[jb+jj];
    }
    float c[8];
#pragma unroll
    for (int i = 0; i < 8; ++i) c[i] = 0.f;
    __syncthreads();
    // emb(0) -> Bb0 (k = 64+j)
    {
        float2 hv = *(const float2*)(hist + ((size_t)(b0 + nn))*2);
#pragma unroll
        for (int jj = 0; jj < 4; ++jj) {
            float e = lrelu(fmaf(wj0[jj], hv.x, fmaf(wj1[jj], hv.y, bj[jj])));
            bfrag_store(Bb0, 64 + jb + jj, nn, e);
        }
    }
    __syncthreads();

    int gr = lane >> 2, ct = lane & 3;
#pragma unroll 1
    for (int t = 0; t < T_IN; ++t) {
        float* Bc = (t & 1) ? Bb1 : Bb0;
        float* Bn = (t & 1) ? Bb0 : Bb1;
        float acc[2][4][4];
#pragma unroll
        for (int m = 0; m < 2; ++m)
#pragma unroll
            for (int nb = 0; nb < 4; ++nb)
#pragma unroll
                for (int r = 0; r < 4; ++r) acc[m][nb][r] = 0.f;
#pragma unroll
        for (int ks = 0; ks < 6; ++ks) {
            const uint4* bp = (const uint4*)(Bc + (ks*32 + lane)*20);
            uint4 bv[4];
#pragma unroll
            for (int nb = 0; nb < 4; ++nb) bv[nb] = bp[nb];
#pragma unroll
            for (int m = 0; m < 2; ++m) {
                int mt = warp + 8*m;
                uint4 ahi = __ldg(&g_Ae[((mt*6 + ks)*2 + 0)*32 + lane]);
                uint4 alo = __ldg(&g_Ae[((mt*6 + ks)*2 + 1)*32 + lane]);
#pragma unroll
                for (int nb = 0; nb < 4; ++nb) {
                    MMA(acc[m][nb], ahi, bv[nb].x, bv[nb].y);
                    MMA(acc[m][nb], ahi, bv[nb].z, bv[nb].w);
                    MMA(acc[m][nb], alo, bv[nb].x, bv[nb].y);
                }
            }
        }
#pragma unroll
        for (int m = 0; m < 2; ++m) {
            int pr = 16*(warp + 8*m) + gr;
#pragma unroll
            for (int nb = 0; nb < 4; ++nb) {
                int col = 8*nb + 2*ct;
                *(float2*)&sD[pr*34 + col]     = make_float2(acc[m][nb][0], acc[m][nb][1]);
                *(float2*)&sD[(pr+8)*34 + col] = make_float2(acc[m][nb][2], acc[m][nb][3]);
            }
        }
        __syncthreads();
#pragma unroll
        for (int i = 0; i < 8; ++i) {
            int u = ub + i;
            float gi = sD[(4*u+0)*34 + nn] + bsum[0][i];
            float gf = sD[(4*u+1)*34 + nn] + bsum[1][i];
            float gg = sD[(4*u+2)*34 + nn] + bsum[2][i];
            float go = sD[(4*u+3)*34 + nn] + bsum[3][i];
            c[i] = fmaf(sigf(gf), c[i], sigf(gi)*tanh_fast(gg));
            float hv = sigf(go) * tanh_fast(c[i]);
            sHT[u*33 + nn] = hv;
            bfrag_store(Bn, u, nn, hv);
        }
        if (t < T_IN - 1) {
            float2 hv2 = *(const float2*)(hist + ((size_t)(t+1)*NB + b0 + nn)*2);
#pragma unroll
            for (int jj = 0; jj < 4; ++jj) {
                float e = lrelu(fmaf(wj0[jj], hv2.x, fmaf(wj1[jj], hv2.y, bj[jj])));
                bfrag_store(Bn, 64 + jb + jj, nn, e);
            }
        }
        __syncthreads();
    }

    // ---------------- Phase C ----------------
    // WdynT into sD: sD[k*32 + row]
    for (int i = tid; i < DYN*ENC; i += 256) {
        int r = i >> 6, cc = i & 63;
        sD[cc*32 + r] = Wdyn[i];
    }
    __syncthreads();
#pragma unroll
    for (int pass = 0; pass < 8; ++pass) {
        int it = tid + pass*256;
        int hero = it >> 6, o = it & 63;
        int row = o & 31;
        float a = __ldg(bdyn + row);
        if (o < 32) {
#pragma unroll 8
            for (int k = 0; k < 64; ++k) a = fmaf(sD[k*32 + row], sHT[k*33 + hero], a);
        } else {
#pragma unroll 8
            for (int k = 0; k < 64; ++k) a = fmaf(sD[k*32 + row], sMax[hero*64 + k], a);
        }
        sEnc[hero*64 + o] = lrelu(a);
    }
    __syncthreads();
#pragma unroll
    for (int rp = 0; rp < 2; ++rp) {
        int r = tid + rp*256;
        float bs = __ldg(bih_d + r) + __ldg(bhh_d + r);
#pragma unroll
        for (int hp = 0; hp < 2; ++hp) {
            u64 acc2[16];
#pragma unroll
            for (int hl = 0; hl < 16; ++hl) acc2[hl] = lo2(bs);
#pragma unroll 4
            for (int k4 = 0; k4 < 16; ++k4) {
                ulonglong2 w = *(const ulonglong2*)(g_Wd4 + ((size_t)k4*512 + r)*4);
#pragma unroll
                for (int hl = 0; hl < 16; ++hl) {
                    ulonglong2 e = *(const ulonglong2*)(sEnc + (hp*16 + hl)*64 + k4*4);
                    fma2(acc2[hl], w.x, e.x);
                    fma2(acc2[hl], w.y, e.y);
                }
            }
#pragma unroll
            for (int hl = 0; hl < 16; ++hl)
                g_preT[(size_t)r*NB + b0 + hp*16 + hl] = red2(acc2[hl]);
        }
    }
}

// ============================================================
// Kernel 2: HMMA decoder (2-term split). 128 CTAs x 32 heroes, 512 threads.
// ============================================================
__global__ void __launch_bounds__(512, 1) dec_kernel(const float* __restrict__ Wop,
                                                     const float* __restrict__ bop,
                                                     float* __restrict__ out)
{
    extern __shared__ __align__(16) float dsm[];
    float* sD   = dsm;                 // [512][34]
    float* sHf  = dsm + 512*34;        // [32][130]
    float* sWop = sHf + 32*130;        // 256
    float* Bbuf0 = sWop + 256;         // 5120
    float* Bbuf1 = Bbuf0 + 5120;

    int tid = threadIdx.x;
    int w = tid >> 5, lane = tid & 31;
    int gr = lane >> 2, ct = lane & 3;
    int b0h = blockIdx.x * 32;
    int n = tid & 31;
    int ubase = (tid >> 5) * 8;

    for (int i = tid; i < 10240; i += 512) Bbuf0[i] = 0.f;
    if (tid < 256) sWop[tid] = Wop[tid];

    float pre[4][8];
#pragma unroll
    for (int g = 0; g < 4; ++g)
#pragma unroll
        for (int i = 0; i < 8; ++i)
            pre[g][i] = __ldg(&g_preT[(size_t)(g*128 + ubase + i)*NB + b0h + n]);

    float c[8];
#pragma unroll
    for (int i = 0; i < 8; ++i) c[i] = 0.f;
    __syncthreads();

    for (int t = 0; t < T_OUT; ++t) {
        const float* Bc = (t & 1) ? Bbuf1 : Bbuf0;
        float* Bn = (t & 1) ? Bbuf0 : Bbuf1;

        float acc[2][4][4];
#pragma unroll
        for (int m = 0; m < 2; ++m)
#pragma unroll
            for (int nb = 0; nb < 4; ++nb)
#pragma unroll
                for (int r = 0; r < 4; ++r) acc[m][nb][r] = 0.f;

#pragma unroll
        for (int ks = 0; ks < 8; ++ks) {
            const uint4* bp = (const uint4*)(Bc + (ks*32 + lane)*20);
            uint4 bv[4];
#pragma unroll
            for (int nb = 0; nb < 4; ++nb) bv[nb] = bp[nb];
#pragma unroll
            for (int m = 0; m < 2; ++m) {
                int mt = w + 16*m;
                uint4 ahi = __ldg(&g_A[((mt*8 + ks)*2 + 0)*32 + lane]);
#pragma unroll
                for (int nb = 0; nb < 4; ++nb) {
                    MMA(acc[m][nb], ahi, bv[nb].x, bv[nb].y);   // hi*hi
                    MMA(acc[m][nb], ahi, bv[nb].z, bv[nb].w);   // hi*lo
                }
            }
        }
#pragma unroll
        for (int m = 0; m < 2; ++m) {
            int pr = 16*(w + 16*m) + gr;
#pragma unroll
            for (int nb = 0; nb < 4; ++nb) {
                int col = 8*nb + 2*ct;
                *(float2*)&sD[pr*34 + col]     = make_float2(acc[m][nb][0], acc[m][nb][1]);
                *(float2*)&sD[(pr+8)*34 + col] = make_float2(acc[m][nb][2], acc[m][nb][3]);
            }
        }
        __syncthreads();
#pragma unroll
        for (int i = 0; i < 8; ++i) {
            int u = ubase + i;
            float gi = sD[(4*u+0)*34 + n] + pre[0][i];
            float gf = sD[(4*u+1)*34 + n] + pre[1][i];
            float gg = sD[(4*u+2)*34 + n] + pre[2][i];
            float go = sD[(4*u+3)*34 + n] + pre[3][i];
            c[i] = fmaf(sigf(gf), c[i], sigf(gi)*tanh_fast(gg));
            float hv = sigf(go) * tanh_fast(c[i]);
            sHf[n*130 + u] = hv;
            bfrag_store(Bn, u, n, hv);
        }
        __syncthreads();
        if (tid < 64) {
            int hero = tid >> 1, d = tid & 1;
            u64 a2 = lo2(__ldg(bop + d));
            const u64* wo = (const u64*)(sWop + d*128);
            const u64* hr = (const u64*)(sHf + hero*130);
#pragma unroll
            for (int k2 = 0; k2 < 64; ++k2) fma2(a2, wo[k2], hr[k2]);
            out[(size_t)t*NB*2 + (size_t)(b0h + hero)*2 + d] = red2(a2);
        }
    }
}

// ============================================================
extern "C" void kernel_launch(void* const* d_in, const int* in_sizes, int n_in,
                              void* d_out, int out_size)
{
    const float* hist  = (const float*)d_in[0];
    const float* nbrs  = (const float*)d_in[1];
    const float* Wip   = (const float*)d_in[2];
    const float* bip   = (const float*)d_in[3];
    const float* Wih_e = (const float*)d_in[4];
    const float* Whh_e = (const float*)d_in[5];
    const float* bih_e = (const float*)d_in[6];
    const float* bhh_e = (const float*)d_in[7];
    const float* Wdyn  = (const float*)d_in[8];
    const float* bdyn  = (const float*)d_in[9];
    const float* Wnbr  = (const float*)d_in[10];
    const float* bnbr  = (const float*)d_in[11];
    const float* Wih_d = (const float*)d_in[12];
    const float* Whh_d = (const float*)d_in[13];
    const float* bih_d = (const float*)d_in[14];
    const float* bhh_d = (const float*)d_in[15];
    const float* Wop   = (const float*)d_in[16];
    const float* bop   = (const float*)d_in[17];
    const int*   seg   = (const int*)d_in[18];
    float* out = (float*)d_out;

    constexpr int FRONT_SMEM = (8704 + 2*3840 + 2048 + 2112 + 2048) * (int)sizeof(float);
    constexpr int DEC_SMEM = (512*34 + 32*130 + 256 + 2*5120) * (int)sizeof(float);
    cudaFuncSetAttribute(front_kernel, cudaFuncAttributeMaxDynamicSharedMemorySize, FRONT_SMEM);
    cudaFuncSetAttribute(dec_kernel, cudaFuncAttributeMaxDynamicSharedMemorySize, DEC_SMEM);

    prep_kernel<<<120, 256>>>(Whh_d, Wih_d, Whh_e, Wih_e);
    front_kernel<<<NB/FHL, 256, FRONT_SMEM>>>(hist, nbrs, Wip, bip,
                                              bih_e, bhh_e, Wdyn, bdyn, Wnbr, bnbr,
                                              bih_d, bhh_d, seg);
    dec_kernel<<<NB/32, 512, DEC_SMEM>>>(Wop, bop, out);
}

// round 11
// speedup vs baseline: 3.7711x; 1.0698x over previous
#include <cuda_runtime.h>
#include <cuda_fp16.h>
#include <cstdint>

#define T_IN 16
#define T_OUT 25
#define NB 4096
#define KN 32
#define NNBR (NB*KN)
#define ENC 64
#define DEC 128
#define DYN 32
#define EMB 32
#define FHL 32

typedef unsigned long long u64;

// -------- scratch --------
__device__ __align__(16) float g_preT[(size_t)512*NB];      // 8 MB, gate-row-major
__device__ __align__(16) float g_Wd4[4*DEC*(2*DYN)];        // quad-transposed Wih_d
__device__ __align__(16) uint4 g_A[32*8*2*32];              // dec Whh_d frags (hi/lo)
__device__ __align__(16) uint4 g_Ae[16*6*2*32];             // enc [Whh_e|Wih_e] frags (hi/lo)

__device__ __forceinline__ float lrelu(float x){ return x >= 0.f ? x : 0.1f*x; }
__device__ __forceinline__ float sigf(float x){ return __fdividef(1.f, 1.f + __expf(-x)); }
__device__ __forceinline__ float tanh_fast(float x){ return 1.f - __fdividef(2.f, 1.f + __expf(2.f*x)); }

__device__ __forceinline__ void fma2(u64& d, u64 a, u64 b){
    asm("fma.rn.f32x2 %0, %1, %2, %0;" : "+l"(d) : "l"(a), "l"(b));
}
__device__ __forceinline__ u64 packf2(float x, float y){
    u64 r; asm("mov.b64 %0, {%1,%2};" : "=l"(r) : "f"(x), "f"(y)); return r;
}
__device__ __forceinline__ float red2(u64 a){
    float x, y; asm("mov.b64 {%0,%1}, %2;" : "=f"(x), "=f"(y) : "l"(a)); return x + y;
}
__device__ __forceinline__ u64 lo2(float x){ return (u64)__float_as_uint(x); }

#define MMA(d, a, bx, by) \
    asm volatile("mma.sync.aligned.m16n8k16.row.col.f32.f16.f16.f32 " \
        "{%0,%1,%2,%3},{%4,%5,%6,%7},{%8,%9},{%0,%1,%2,%3};" \
        : "+f"((d)[0]), "+f"((d)[1]), "+f"((d)[2]), "+f"((d)[3]) \
        : "r"((a).x), "r"((a).y), "r"((a).z), "r"((a).w), "r"(bx), "r"(by))

__device__ __forceinline__ unsigned ph2(float a, float b, int hl){
    __half ah = __float2half_rn(a), bh = __float2half_rn(b);
    __half x = hl ? __float2half_rn(a - __half2float(ah)) : ah;
    __half y = hl ? __float2half_rn(b - __half2float(bh)) : bh;
    return (unsigned)__half_as_ushort(x) | ((unsigned)__half_as_ushort(y) << 16);
}

// store one fp32 value as hi/lo halves into a B-fragment buffer (verified mapping)
__device__ __forceinline__ void bfrag_store(float* Bn, int k, int n, float v){
    __half hhi = __float2half_rn(v);
    __half hlo = __float2half_rn(v - __half2float(hhi));
    int ks2 = k >> 4, kk = k & 15;
    int rg = kk >> 3, ctq = (kk & 7) >> 1, dl = kk & 1;
    int lp = (n & 7)*4 + ctq, nbl = n >> 3;
    char* bptr = (char*)(Bn + (ks2*32 + lp)*20) + nbl*16 + rg*4 + dl*2;
    *(__half*)bptr = hhi;
    *(__half*)(bptr + 8) = hlo;
}
// hi-only variant (decoder, 1-term split)
__device__ __forceinline__ void bfrag_store_hi(float* Bn, int k, int n, float v){
    __half hhi = __float2half_rn(v);
    int ks2 = k >> 4, kk = k & 15;
    int rg = kk >> 3, ctq = (kk & 7) >> 1, dl = kk & 1;
    int lp = (n & 7)*4 + ctq, nbl = n >> 3;
    char* bptr = (char*)(Bn + (ks2*32 + lp)*20) + nbl*16 + rg*4 + dl*2;
    *(__half*)bptr = hhi;
}

// ============================================================
// Kernel 0: fragment Whh_d (dec) and [Whh_e|Wih_e] (enc); transpose Wih_d.
// ============================================================
__global__ void prep_kernel(const float* __restrict__ WhhD, const float* __restrict__ WihD,
                            const float* __restrict__ WhhE, const float* __restrict__ WihE)
{
    int idx = blockIdx.x*256 + threadIdx.x;
    if (idx < 16384) {
        int mt = idx >> 9, ks = (idx >> 6) & 7, hl = (idx >> 5) & 1, l = idx & 31;
        int gr = l >> 2, ct = l & 3;
        int pr0 = 16*mt + gr, pr1 = pr0 + 8;
        int k0 = 16*ks + 2*ct;
        int r0 = (pr0 & 3)*128 + (pr0 >> 2);
        int r1 = (pr1 & 3)*128 + (pr1 >> 2);
        uint4 v;
        v.x = ph2(WhhD[r0*128 + k0],     WhhD[r0*128 + k0 + 1], hl);
        v.y = ph2(WhhD[r1*128 + k0],     WhhD[r1*128 + k0 + 1], hl);
        v.z = ph2(WhhD[r0*128 + k0 + 8], WhhD[r0*128 + k0 + 9], hl);
        v.w = ph2(WhhD[r1*128 + k0 + 8], WhhD[r1*128 + k0 + 9], hl);
        g_A[((mt*8 + ks)*2 + hl)*32 + l] = v;
    } else if (idx < 24576) {
        int j = idx - 16384;
        int k4 = j >> 9, r = j & 511;
        float4 v = *(const float4*)(WihD + r*(2*DYN) + k4*4);
        *(float4*)(g_Wd4 + ((size_t)k4*512 + r)*4) = v;
    } else {
        int j2 = idx - 24576;        // < 6144
        int mt = j2 / 384;
        int rem = j2 - mt*384;
        int ks = rem >> 6, hl = (rem >> 5) & 1, l = rem & 31;
        int gr = l >> 2, ct = l & 3;
        int pr0 = 16*mt + gr, pr1 = pr0 + 8;
        int k0 = 16*ks + 2*ct;
        auto W = [&](int pr, int k) -> float {
            int u = pr >> 2, g = pr & 3, row = g*64 + u;
            return (k < 64) ? WhhE[row*64 + k] : WihE[row*32 + (k - 64)];
        };
        uint4 v;
        v.x = ph2(W(pr0,k0),   W(pr0,k0+1), hl);
        v.y = ph2(W(pr1,k0),   W(pr1,k0+1), hl);
        v.z = ph2(W(pr0,k0+8), W(pr0,k0+9), hl);
        v.w = ph2(W(pr1,k0+8), W(pr1,k0+9), hl);
        g_Ae[((mt*6 + ks)*2 + hl)*32 + l] = v;
    }
}

// ============================================================
// Kernel 1 (FRONT): nbr MLP+max -> HMMA encoder (2-term) -> Wdyn proj
//                   -> dec-input GEMM. 32 heroes/block, 256 thr, grid 128.
// ============================================================
__global__ void __launch_bounds__(256, 1) front_kernel(
        const float* __restrict__ hist, const float* __restrict__ nbrs,
        const float* __restrict__ Wip,  const float* __restrict__ bip,
        const float* __restrict__ bih,  const float* __restrict__ bhh,
        const float* __restrict__ Wdyn, const float* __restrict__ bdyn,
        const float* __restrict__ Wnbr, const float* __restrict__ bnbr,
        const float* __restrict__ bih_d,const float* __restrict__ bhh_d,
        const int* __restrict__ seg)
{
    extern __shared__ __align__(16) float sm[];
    float* sD   = sm;               // 8704 floats overlay
    float* Bb0  = sm + 8704;        // 3840: [6ks][32][20]
    float* Bb1  = Bb0 + 3840;
    float* sMax = Bb1 + 3840;       // 2048 [hero][64]
    float* sHT  = sMax + 2048;      // 2112 [u*33+n]
    float* sEnc = sHT + 2112;       // 2048 [hero][64]

    int tid = threadIdx.x;
    int b0 = blockIdx.x * FHL;
    int warp = tid >> 5, lane = tid & 31;

    // ---------------- Phase A: neighbor MLP + segment max ----------------
    for (int i = tid; i < ENC*32; i += 256) sD[i] = Wnbr[i];
    if (tid < ENC) sD[ENC*32 + tid] = bnbr[tid];
    __syncthreads();
#pragma unroll
    for (int p = 0; p < 4; ++p) {
        int hero = warp + p*8;
        int n = (b0 + hero)*KN + lane;
        int sgid = seg[n];
        u64 xp[16];
#pragma unroll
        for (int t = 0; t < T_IN; ++t) {
            float2 hv = *(const float2*)(hist + ((size_t)t*NB + sgid)*2);
            float2 nv = *(const float2*)(nbrs + ((size_t)t*NNBR + n)*2);
            xp[t] = packf2(hv.x - nv.x, hv.y - nv.y);
        }
#pragma unroll 4
        for (int g = 0; g < ENC; ++g) {
            u64 a2 = lo2(sD[ENC*32 + g]);
            const ulonglong2* w = (const ulonglong2*)(sD + g*32);
#pragma unroll
            for (int k = 0; k < 8; ++k) {
                ulonglong2 wv = w[k];
                fma2(a2, wv.x, xp[2*k]);
                fma2(a2, wv.y, xp[2*k+1]);
            }
            float acc = lrelu(red2(a2));
#pragma unroll
            for (int off = 16; off; off >>= 1)
                acc = fmaxf(acc, __shfl_xor_sync(0xffffffffu, acc, off));
            if (lane == 0) sMax[hero*ENC + g] = acc;
        }
    }
    __syncthreads();

    // ---------------- Phase B: HMMA encoder (2-term: ahi*bhi + ahi*blo) ----------------
    for (int i = tid; i < 7680; i += 256) Bb0[i] = 0.f;
    int nn = tid & 31, ub = (tid >> 5) * 8;
    float bsum[4][8];
#pragma unroll
    for (int g = 0; g < 4; ++g)
#pragma unroll
        for (int i = 0; i < 8; ++i)
            bsum[g][i] = __ldg(bih + g*64 + ub + i) + __ldg(bhh + g*64 + ub + i);
    int jb = (tid >> 5) * 4;
    float wj0[4], wj1[4], bj[4];
#pragma unroll
    for (int jj = 0; jj < 4; ++jj) {
        wj0[jj] = Wip[(jb+jj)*2]; wj1[jj] = Wip[(jb+jj)*2+1]; bj[jj] = bip[jb+jj];
    }
    float c[8];
#pragma unroll
    for (int i = 0; i < 8; ++i) c[i] = 0.f;
    __syncthreads();
    {
        float2 hv = *(const float2*)(hist + ((size_t)(b0 + nn))*2);
#pragma unroll
        for (int jj = 0; jj < 4; ++jj) {
            float e = lrelu(fmaf(wj0[jj], hv.x, fmaf(wj1[jj], hv.y, bj[jj])));
            bfrag_store(Bb0, 64 + jb + jj, nn, e);
        }
    }
    __syncthreads();

    int gr = lane >> 2, ct = lane & 3;
#pragma unroll 1
    for (int t = 0; t < T_IN; ++t) {
        float* Bc = (t & 1) ? Bb1 : Bb0;
        float* Bn = (t & 1) ? Bb0 : Bb1;
        float acc[2][4][4];
#pragma unroll
        for (int m = 0; m < 2; ++m)
#pragma unroll
            for (int nb = 0; nb < 4; ++nb)
#pragma unroll
                for (int r = 0; r < 4; ++r) acc[m][nb][r] = 0.f;
#pragma unroll
        for (int ks = 0; ks < 6; ++ks) {
            const uint4* bp = (const uint4*)(Bc + (ks*32 + lane)*20);
            uint4 bv[4];
#pragma unroll
            for (int nb = 0; nb < 4; ++nb) bv[nb] = bp[nb];
#pragma unroll
            for (int m = 0; m < 2; ++m) {
                int mt = warp + 8*m;
                uint4 ahi = __ldg(&g_Ae[((mt*6 + ks)*2 + 0)*32 + lane]);
#pragma unroll
                for (int nb = 0; nb < 4; ++nb) {
                    MMA(acc[m][nb], ahi, bv[nb].x, bv[nb].y);
                    MMA(acc[m][nb], ahi, bv[nb].z, bv[nb].w);
                }
            }
        }
#pragma unroll
        for (int m = 0; m < 2; ++m) {
            int pr = 16*(warp + 8*m) + gr;
#pragma unroll
            for (int nb = 0; nb < 4; ++nb) {
                int col = 8*nb + 2*ct;
                *(float2*)&sD[pr*34 + col]     = make_float2(acc[m][nb][0], acc[m][nb][1]);
                *(float2*)&sD[(pr+8)*34 + col] = make_float2(acc[m][nb][2], acc[m][nb][3]);
            }
        }
        __syncthreads();
#pragma unroll
        for (int i = 0; i < 8; ++i) {
            int u = ub + i;
            float gi = sD[(4*u+0)*34 + nn] + bsum[0][i];
            float gf = sD[(4*u+1)*34 + nn] + bsum[1][i];
            float gg = sD[(4*u+2)*34 + nn] + bsum[2][i];
            float go = sD[(4*u+3)*34 + nn] + bsum[3][i];
            c[i] = fmaf(sigf(gf), c[i], sigf(gi)*tanh_fast(gg));
            float hv = sigf(go) * tanh_fast(c[i]);
            sHT[u*33 + nn] = hv;
            bfrag_store(Bn, u, nn, hv);
        }
        if (t < T_IN - 1) {
            float2 hv2 = *(const float2*)(hist + ((size_t)(t+1)*NB + b0 + nn)*2);
#pragma unroll
            for (int jj = 0; jj < 4; ++jj) {
                float e = lrelu(fmaf(wj0[jj], hv2.x, fmaf(wj1[jj], hv2.y, bj[jj])));
                bfrag_store(Bn, 64 + jb + jj, nn, e);
            }
        }
        __syncthreads();
    }

    // ---------------- Phase C ----------------
    for (int i = tid; i < DYN*ENC; i += 256) {
        int r = i >> 6, cc = i & 63;
        sD[cc*32 + r] = Wdyn[i];
    }
    __syncthreads();
#pragma unroll
    for (int pass = 0; pass < 8; ++pass) {
        int it = tid + pass*256;
        int hero = it >> 6, o = it & 63;
        int row = o & 31;
        float a = __ldg(bdyn + row);
        if (o < 32) {
#pragma unroll 8
            for (int k = 0; k < 64; ++k) a = fmaf(sD[k*32 + row], sHT[k*33 + hero], a);
        } else {
#pragma unroll 8
            for (int k = 0; k < 64; ++k) a = fmaf(sD[k*32 + row], sMax[hero*64 + k], a);
        }
        sEnc[hero*64 + o] = lrelu(a);
    }
    __syncthreads();
#pragma unroll
    for (int rp = 0; rp < 2; ++rp) {
        int r = tid + rp*256;
        float bs = __ldg(bih_d + r) + __ldg(bhh_d + r);
#pragma unroll
        for (int hp = 0; hp < 2; ++hp) {
            u64 acc2[16];
#pragma unroll
            for (int hl = 0; hl < 16; ++hl) acc2[hl] = lo2(bs);
#pragma unroll 4
            for (int k4 = 0; k4 < 16; ++k4) {
                ulonglong2 w = *(const ulonglong2*)(g_Wd4 + ((size_t)k4*512 + r)*4);
#pragma unroll
                for (int hl = 0; hl < 16; ++hl) {
                    ulonglong2 e = *(const ulonglong2*)(sEnc + (hp*16 + hl)*64 + k4*4);
                    fma2(acc2[hl], w.x, e.x);
                    fma2(acc2[hl], w.y, e.y);
                }
            }
#pragma unroll
            for (int hl = 0; hl < 16; ++hl)
                g_preT[(size_t)r*NB + b0 + hp*16 + hl] = red2(acc2[hl]);
        }
    }
}

// ============================================================
// Kernel 2: HMMA decoder (1-term split: whi*hhi). 128 CTAs, 512 threads.
// ============================================================
__global__ void __launch_bounds__(512, 1) dec_kernel(const float* __restrict__ Wop,
                                                     const float* __restrict__ bop,
                                                     float* __restrict__ out)
{
    extern __shared__ __align__(16) float dsm[];
    float* sD   = dsm;                 // [512][34]
    float* sHf  = dsm + 512*34;        // [32][130]
    float* sWop = sHf + 32*130;        // 256
    float* Bbuf0 = sWop + 256;         // 5120
    float* Bbuf1 = Bbuf0 + 5120;

    int tid = threadIdx.x;
    int w = tid >> 5, lane = tid & 31;
    int gr = lane >> 2, ct = lane & 3;
    int b0h = blockIdx.x * 32;
    int n = tid & 31;
    int ubase = (tid >> 5) * 8;

    for (int i = tid; i < 10240; i += 512) Bbuf0[i] = 0.f;
    if (tid < 256) sWop[tid] = Wop[tid];

    float pre[4][8];
#pragma unroll
    for (int g = 0; g < 4; ++g)
#pragma unroll
        for (int i = 0; i < 8; ++i)
            pre[g][i] = __ldg(&g_preT[(size_t)(g*128 + ubase + i)*NB + b0h + n]);

    float c[8];
#pragma unroll
    for (int i = 0; i < 8; ++i) c[i] = 0.f;
    __syncthreads();

    for (int t = 0; t < T_OUT; ++t) {
        const float* Bc = (t & 1) ? Bbuf1 : Bbuf0;
        float* Bn = (t & 1) ? Bbuf0 : Bbuf1;

        float acc[2][4][4];
#pragma unroll
        for (int m = 0; m < 2; ++m)
#pragma unroll
            for (int nb = 0; nb < 4; ++nb)
#pragma unroll
                for (int r = 0; r < 4; ++r) acc[m][nb][r] = 0.f;

#pragma unroll
        for (int ks = 0; ks < 8; ++ks) {
            const float* bbase = Bc + (ks*32 + lane)*20;
            uint2 bv[4];
#pragma unroll
            for (int nb = 0; nb < 4; ++nb) bv[nb] = *(const uint2*)(bbase + nb*4);
#pragma unroll
            for (int m = 0; m < 2; ++m) {
                int mt = w + 16*m;
                uint4 ahi = __ldg(&g_A[((mt*8 + ks)*2 + 0)*32 + lane]);
#pragma unroll
                for (int nb = 0; nb < 4; ++nb)
                    MMA(acc[m][nb], ahi, bv[nb].x, bv[nb].y);   // hi*hi only
            }
        }
#pragma unroll
        for (int m = 0; m < 2; ++m) {
            int pr = 16*(w + 16*m) + gr;
#pragma unroll
            for (int nb = 0; nb < 4; ++nb) {
                int col = 8*nb + 2*ct;
                *(float2*)&sD[pr*34 + col]     = make_float2(acc[m][nb][0], acc[m][nb][1]);
                *(float2*)&sD[(pr+8)*34 + col] = make_float2(acc[m][nb][2], acc[m][nb][3]);
            }
        }
        __syncthreads();
#pragma unroll
        for (int i = 0; i < 8; ++i) {
            int u = ubase + i;
            float gi = sD[(4*u+0)*34 + n] + pre[0][i];
            float gf = sD[(4*u+1)*34 + n] + pre[1][i];
            float gg = sD[(4*u+2)*34 + n] + pre[2][i];
            float go = sD[(4*u+3)*34 + n] + pre[3][i];
            c[i] = fmaf(sigf(gf), c[i], sigf(gi)*tanh_fast(gg));
            float hv = sigf(go) * tanh_fast(c[i]);
            sHf[n*130 + u] = hv;
            bfrag_store_hi(Bn, u, n, hv);
        }
        __syncthreads();
        if (tid < 64) {
            int hero = tid >> 1, d = tid & 1;
            u64 a2 = lo2(__ldg(bop + d));
            const u64* wo = (const u64*)(sWop + d*128);
            const u64* hr = (const u64*)(sHf + hero*130);
#pragma unroll
            for (int k2 = 0; k2 < 64; ++k2) fma2(a2, wo[k2], hr[k2]);
            out[(size_t)t*NB*2 + (size_t)(b0h + hero)*2 + d] = red2(a2);
        }
    }
}

// ============================================================
extern "C" void kernel_launch(void* const* d_in, const int* in_sizes, int n_in,
                              void* d_out, int out_size)
{
    const float* hist  = (const float*)d_in[0];
    const float* nbrs  = (const float*)d_in[1];
    const float* Wip   = (const float*)d_in[2];
    const float* bip   = (const float*)d_in[3];
    const float* Wih_e = (const float*)d_in[4];
    const float* Whh_e = (const float*)d_in[5];
    const float* bih_e = (const float*)d_in[6];
    const float* bhh_e = (const float*)d_in[7];
    const float* Wdyn  = (const float*)d_in[8];
    const float* bdyn  = (const float*)d_in[9];
    const float* Wnbr  = (const float*)d_in[10];
    const float* bnbr  = (const float*)d_in[11];
    const float* Wih_d = (const float*)d_in[12];
    const float* Whh_d = (const float*)d_in[13];
    const float* bih_d = (const float*)d_in[14];
    const float* bhh_d = (const float*)d_in[15];
    const float* Wop   = (const float*)d_in[16];
    const float* bop   = (const float*)d_in[17];
    const int*   seg   = (const int*)d_in[18];
    float* out = (float*)d_out;

    constexpr int FRONT_SMEM = (8704 + 2*3840 + 2048 + 2112 + 2048) * (int)sizeof(float);
    constexpr int DEC_SMEM = (512*34 + 32*130 + 256 + 2*5120) * (int)sizeof(float);
    cudaFuncSetAttribute(front_kernel, cudaFuncAttributeMaxDynamicSharedMemorySize, FRONT_SMEM);
    cudaFuncSetAttribute(dec_kernel, cudaFuncAttributeMaxDynamicSharedMemorySize, DEC_SMEM);

    prep_kernel<<<120, 256>>>(Whh_d, Wih_d, Whh_e, Wih_e);
    front_kernel<<<NB/FHL, 256, FRONT_SMEM>>>(hist, nbrs, Wip, bip,
                                              bih_e, bhh_e, Wdyn, bdyn, Wnbr, bnbr,
                                              bih_d, bhh_d, seg);
    dec_kernel<<<NB/32, 512, DEC_SMEM>>>(Wop, bop, out);
}

// round 12
// speedup vs baseline: 4.8345x; 1.2820x over previous
#include <cuda_runtime.h>
#include <cuda_fp16.h>
#include <cstdint>

#define T_IN 16
#define T_OUT 25
#define NB 4096
#define KN 32
#define NNBR (NB*KN)
#define ENC 64
#define DEC 128
#define DYN 32
#define EMB 32
#define FHL 32

typedef unsigned long long u64;

// -------- scratch --------
__device__ __align__(16) float g_preT[(size_t)512*NB];      // 8 MB, gate-row-major
__device__ __align__(16) float g_Wd4[4*DEC*(2*DYN)];        // quad-transposed Wih_d
__device__ __align__(16) uint4 g_A[32*8*2*32];              // dec Whh_d frags (hi/lo)
__device__ __align__(16) uint4 g_Ae[16*6*2*32];             // enc [Whh_e|Wih_e] frags (hi/lo)

__device__ __forceinline__ float lrelu(float x){ return x >= 0.f ? x : 0.1f*x; }
__device__ __forceinline__ float sigf(float x){ return __fdividef(1.f, 1.f + __expf(-x)); }
__device__ __forceinline__ float tanh_fast(float x){ return 1.f - __fdividef(2.f, 1.f + __expf(2.f*x)); }

__device__ __forceinline__ void fma2(u64& d, u64 a, u64 b){
    asm("fma.rn.f32x2 %0, %1, %2, %0;" : "+l"(d) : "l"(a), "l"(b));
}
__device__ __forceinline__ u64 packf2(float x, float y){
    u64 r; asm("mov.b64 %0, {%1,%2};" : "=l"(r) : "f"(x), "f"(y)); return r;
}
__device__ __forceinline__ float red2(u64 a){
    float x, y; asm("mov.b64 {%0,%1}, %2;" : "=f"(x), "=f"(y) : "l"(a)); return x + y;
}
__device__ __forceinline__ u64 lo2(float x){ return (u64)__float_as_uint(x); }

#define MMA(d, a, bx, by) \
    asm volatile("mma.sync.aligned.m16n8k16.row.col.f32.f16.f16.f32 " \
        "{%0,%1,%2,%3},{%4,%5,%6,%7},{%8,%9},{%0,%1,%2,%3};" \
        : "+f"((d)[0]), "+f"((d)[1]), "+f"((d)[2]), "+f"((d)[3]) \
        : "r"((a).x), "r"((a).y), "r"((a).z), "r"((a).w), "r"(bx), "r"(by))

__device__ __forceinline__ unsigned ph2(float a, float b, int hl){
    __half ah = __float2half_rn(a), bh = __float2half_rn(b);
    __half x = hl ? __float2half_rn(a - __half2float(ah)) : ah;
    __half y = hl ? __float2half_rn(b - __half2float(bh)) : bh;
    return (unsigned)__half_as_ushort(x) | ((unsigned)__half_as_ushort(y) << 16);
}

// store one fp32 value as hi/lo halves into a B-fragment buffer (verified mapping)
__device__ __forceinline__ void bfrag_store(float* Bn, int k, int n, float v){
    __half hhi = __float2half_rn(v);
    __half hlo = __float2half_rn(v - __half2float(hhi));
    int ks2 = k >> 4, kk = k & 15;
    int rg = kk >> 3, ctq = (kk & 7) >> 1, dl = kk & 1;
    int lp = (n & 7)*4 + ctq, nbl = n >> 3;
    char* bptr = (char*)(Bn + (ks2*32 + lp)*20) + nbl*16 + rg*4 + dl*2;
    *(__half*)bptr = hhi;
    *(__half*)(bptr + 8) = hlo;
}
__device__ __forceinline__ void bfrag_store_hi(float* Bn, int k, int n, float v){
    __half hhi = __float2half_rn(v);
    int ks2 = k >> 4, kk = k & 15;
    int rg = kk >> 3, ctq = (kk & 7) >> 1, dl = kk & 1;
    int lp = (n & 7)*4 + ctq, nbl = n >> 3;
    char* bptr = (char*)(Bn + (ks2*32 + lp)*20) + nbl*16 + rg*4 + dl*2;
    *(__half*)bptr = hhi;
}

// ============================================================
// Kernel 0: fragment weights with GATE-PAIR interleave:
// tile row r16: unit_local = (r16&7)>>1, j = r16&1, half = r16>>3,
// gate = j + 2*half. Lane (gr) rows {gr, gr+8} = gates j, j+2 of one unit.
// ============================================================
__global__ void prep_kernel(const float* __restrict__ WhhD, const float* __restrict__ WihD,
                            const float* __restrict__ WhhE, const float* __restrict__ WihE)
{
    int idx = blockIdx.x*256 + threadIdx.x;
    if (idx < 16384) {
        int mt = idx >> 9, ks = (idx >> 6) & 7, hl = (idx >> 5) & 1, l = idx & 31;
        int gr = l >> 2, ct = l & 3;
        int unit = 4*mt + (gr >> 1);
        int r0 = (gr & 1)*128 + unit;          // gate j
        int r1 = r0 + 256;                     // gate j+2
        int k0 = 16*ks + 2*ct;
        uint4 v;
        v.x = ph2(WhhD[r0*128 + k0],     WhhD[r0*128 + k0 + 1], hl);
        v.y = ph2(WhhD[r1*128 + k0],     WhhD[r1*128 + k0 + 1], hl);
        v.z = ph2(WhhD[r0*128 + k0 + 8], WhhD[r0*128 + k0 + 9], hl);
        v.w = ph2(WhhD[r1*128 + k0 + 8], WhhD[r1*128 + k0 + 9], hl);
        g_A[((mt*8 + ks)*2 + hl)*32 + l] = v;
    } else if (idx < 24576) {
        int j = idx - 16384;
        int k4 = j >> 9, r = j & 511;
        float4 v = *(const float4*)(WihD + r*(2*DYN) + k4*4);
        *(float4*)(g_Wd4 + ((size_t)k4*512 + r)*4) = v;
    } else {
        int j2 = idx - 24576;        // < 6144
        int mt = j2 / 384;
        int rem = j2 - mt*384;
        int ks = rem >> 6, hl = (rem >> 5) & 1, l = rem & 31;
        int gr = l >> 2, ct = l & 3;
        int unit = 4*mt + (gr >> 1);
        int g0 = gr & 1, g1 = g0 + 2;
        int k0 = 16*ks + 2*ct;
        auto W = [&](int gate, int k) -> float {
            int row = gate*64 + unit;
            return (k < 64) ? WhhE[row*64 + k] : WihE[row*32 + (k - 64)];
        };
        uint4 v;
        v.x = ph2(W(g0,k0),   W(g0,k0+1), hl);
        v.y = ph2(W(g1,k0),   W(g1,k0+1), hl);
        v.z = ph2(W(g0,k0+8), W(g0,k0+9), hl);
        v.w = ph2(W(g1,k0+8), W(g1,k0+9), hl);
        g_Ae[((mt*6 + ks)*2 + hl)*32 + l] = v;
    }
}

// ============================================================
// Kernel 1 (FRONT): nbr MLP+max -> HMMA encoder (2-term, shfl-exchange
// epilogue, 1 sync/step) -> Wdyn proj -> dec-input GEMM.
// 32 heroes/block, 256 threads (8 warps), grid 128.
// ============================================================
__global__ void __launch_bounds__(256, 1) front_kernel(
        const float* __restrict__ hist, const float* __restrict__ nbrs,
        const float* __restrict__ Wip,  const float* __restrict__ bip,
        const float* __restrict__ bih,  const float* __restrict__ bhh,
        const float* __restrict__ Wdyn, const float* __restrict__ bdyn,
        const float* __restrict__ Wnbr, const float* __restrict__ bnbr,
        const float* __restrict__ bih_d,const float* __restrict__ bhh_d,
        const int* __restrict__ seg)
{
    extern __shared__ __align__(16) float sm[];
    float* sD   = sm;               // 8704 floats overlay (phases A & C only)
    float* Bb0  = sm + 8704;        // 3840: [6ks][32][20]
    float* Bb1  = Bb0 + 3840;
    float* sMax = Bb1 + 3840;       // 2048 [hero][64]
    float* sHT  = sMax + 2048;      // 2112 [u*33+n] final h only
    float* sEnc = sHT + 2112;       // 2048 [hero][64]

    int tid = threadIdx.x;
    int b0 = blockIdx.x * FHL;
    int warp = tid >> 5, lane = tid & 31;
    int gr = lane >> 2, ct = lane & 3;
    int jx = gr & 1, ul = gr >> 1;

    // ---------------- Phase A: neighbor MLP + segment max ----------------
    for (int i = tid; i < ENC*32; i += 256) sD[i] = Wnbr[i];
    if (tid < ENC) sD[ENC*32 + tid] = bnbr[tid];
    __syncthreads();
#pragma unroll
    for (int p = 0; p < 4; ++p) {
        int hero = warp + p*8;
        int n = (b0 + hero)*KN + lane;
        int sgid = seg[n];
        u64 xp[16];
#pragma unroll
        for (int t = 0; t < T_IN; ++t) {
            float2 hv = *(const float2*)(hist + ((size_t)t*NB + sgid)*2);
            float2 nv = *(const float2*)(nbrs + ((size_t)t*NNBR + n)*2);
            xp[t] = packf2(hv.x - nv.x, hv.y - nv.y);
        }
#pragma unroll 4
        for (int g = 0; g < ENC; ++g) {
            u64 a2 = lo2(sD[ENC*32 + g]);
            const ulonglong2* w = (const ulonglong2*)(sD + g*32);
#pragma unroll
            for (int k = 0; k < 8; ++k) {
                ulonglong2 wv = w[k];
                fma2(a2, wv.x, xp[2*k]);
                fma2(a2, wv.y, xp[2*k+1]);
            }
            float acc = lrelu(red2(a2));
#pragma unroll
            for (int off = 16; off; off >>= 1)
                acc = fmaxf(acc, __shfl_xor_sync(0xffffffffu, acc, off));
            if (lane == 0) sMax[hero*ENC + g] = acc;
        }
    }
    __syncthreads();

    // ---------------- Phase B: HMMA encoder (2-term), shfl epilogue ----------------
    for (int i = tid; i < 7680; i += 256) Bb0[i] = 0.f;
    // per-item (m,nb) bias sums: unit = 4*(warp+8m)+ul
    float bsum[4][8];
#pragma unroll
    for (int m = 0; m < 2; ++m) {
        int unit = 4*(warp + 8*m) + ul;
#pragma unroll
        for (int nb = 0; nb < 4; ++nb)
#pragma unroll
            for (int g = 0; g < 4; ++g)
                bsum[g][m*4+nb] = __ldg(bih + g*64 + unit) + __ldg(bhh + g*64 + unit);
    }
    int nn = tid & 31;
    int jb = (tid >> 5) * 4;
    float wj0[4], wj1[4], bj[4];
#pragma unroll
    for (int jj = 0; jj < 4; ++jj) {
        wj0[jj] = Wip[(jb+jj)*2]; wj1[jj] = Wip[(jb+jj)*2+1]; bj[jj] = bip[jb+jj];
    }
    float c[8];
#pragma unroll
    for (int i = 0; i < 8; ++i) c[i] = 0.f;
    __syncthreads();
    {
        float2 hv = *(const float2*)(hist + ((size_t)(b0 + nn))*2);
#pragma unroll
        for (int jj = 0; jj < 4; ++jj) {
            float e = lrelu(fmaf(wj0[jj], hv.x, fmaf(wj1[jj], hv.y, bj[jj])));
            bfrag_store(Bb0, 64 + jb + jj, nn, e);
        }
    }
    __syncthreads();

#pragma unroll 1
    for (int t = 0; t < T_IN; ++t) {
        float* Bc = (t & 1) ? Bb1 : Bb0;
        float* Bn = (t & 1) ? Bb0 : Bb1;
        float acc[2][4][4];
#pragma unroll
        for (int m = 0; m < 2; ++m)
#pragma unroll
            for (int nb = 0; nb < 4; ++nb)
#pragma unroll
                for (int r = 0; r < 4; ++r) acc[m][nb][r] = 0.f;
#pragma unroll
        for (int ks = 0; ks < 6; ++ks) {
            const uint4* bp = (const uint4*)(Bc + (ks*32 + lane)*20);
            uint4 bv[4];
#pragma unroll
            for (int nb = 0; nb < 4; ++nb) bv[nb] = bp[nb];
#pragma unroll
            for (int m = 0; m < 2; ++m) {
                int mt = warp + 8*m;
                uint4 ahi = __ldg(&g_Ae[((mt*6 + ks)*2 + 0)*32 + lane]);
#pragma unroll
                for (int nb = 0; nb < 4; ++nb) {
                    MMA(acc[m][nb], ahi, bv[nb].x, bv[nb].y);
                    MMA(acc[m][nb], ahi, bv[nb].z, bv[nb].w);
                }
            }
        }
        // shfl gate exchange + LSTM + B-frag write
#pragma unroll
        for (int m = 0; m < 2; ++m) {
            int unit = 4*(warp + 8*m) + ul;
#pragma unroll
            for (int nb = 0; nb < 4; ++nb) {
                float c0 = acc[m][nb][0], c1 = acc[m][nb][1];
                float c2 = acc[m][nb][2], c3 = acc[m][nb][3];
                float sAv = jx ? c0 : c1;
                float sBv = jx ? c2 : c3;
                float rA = __shfl_xor_sync(0xffffffffu, sAv, 4);
                float rB = __shfl_xor_sync(0xffffffffu, sBv, 4);
                float g0 = jx ? rA : c0;
                float g1 = jx ? c1 : rA;
                float g2 = jx ? rB : c2;
                float g3 = jx ? c3 : rB;
                int it = m*4 + nb;
                float gi = g0 + bsum[0][it];
                float gf = g1 + bsum[1][it];
                float gg = g2 + bsum[2][it];
                float go = g3 + bsum[3][it];
                c[it] = fmaf(sigf(gf), c[it], sigf(gi)*tanh_fast(gg));
                float hv = sigf(go)*tanh_fast(c[it]);
                int hero = 8*nb + 2*ct + jx;
                bfrag_store(Bn, unit, hero, hv);
                if (t == T_IN - 1) sHT[unit*33 + hero] = hv;
            }
        }
        if (t < T_IN - 1) {
            float2 hv2 = *(const float2*)(hist + ((size_t)(t+1)*NB + b0 + nn)*2);
#pragma unroll
            for (int jj = 0; jj < 4; ++jj) {
                float e = lrelu(fmaf(wj0[jj], hv2.x, fmaf(wj1[jj], hv2.y, bj[jj])));
                bfrag_store(Bn, 64 + jb + jj, nn, e);
            }
        }
        __syncthreads();
    }

    // ---------------- Phase C ----------------
    for (int i = tid; i < DYN*ENC; i += 256) {
        int r = i >> 6, cc = i & 63;
        sD[cc*32 + r] = Wdyn[i];
    }
    __syncthreads();
#pragma unroll
    for (int pass = 0; pass < 8; ++pass) {
        int it = tid + pass*256;
        int hero = it >> 6, o = it & 63;
        int row = o & 31;
        float a = __ldg(bdyn + row);
        if (o < 32) {
#pragma unroll 8
            for (int k = 0; k < 64; ++k) a = fmaf(sD[k*32 + row], sHT[k*33 + hero], a);
        } else {
#pragma unroll 8
            for (int k = 0; k < 64; ++k) a = fmaf(sD[k*32 + row], sMax[hero*64 + k], a);
        }
        sEnc[hero*64 + o] = lrelu(a);
    }
    __syncthreads();
#pragma unroll
    for (int rp = 0; rp < 2; ++rp) {
        int r = tid + rp*256;
        float bs = __ldg(bih_d + r) + __ldg(bhh_d + r);
#pragma unroll
        for (int hp = 0; hp < 2; ++hp) {
            u64 acc2[16];
#pragma unroll
            for (int hl = 0; hl < 16; ++hl) acc2[hl] = lo2(bs);
#pragma unroll 4
            for (int k4 = 0; k4 < 16; ++k4) {
                ulonglong2 w = *(const ulonglong2*)(g_Wd4 + ((size_t)k4*512 + r)*4);
#pragma unroll
                for (int hl = 0; hl < 16; ++hl) {
                    ulonglong2 e = *(const ulonglong2*)(sEnc + (hp*16 + hl)*64 + k4*4);
                    fma2(acc2[hl], w.x, e.x);
                    fma2(acc2[hl], w.y, e.y);
                }
            }
#pragma unroll
            for (int hl = 0; hl < 16; ++hl)
                g_preT[(size_t)r*NB + b0 + hp*16 + hl] = red2(acc2[hl]);
        }
    }
}

// ============================================================
// Kernel 2: HMMA decoder (1-term), shfl-exchange epilogue, 1 sync/step,
// double-buffered sHf. 128 CTAs x 32 heroes, 512 threads.
// ============================================================
__global__ void __launch_bounds__(512, 1) dec_kernel(const float* __restrict__ Wop,
                                                     const float* __restrict__ bop,
                                                     float* __restrict__ out)
{
    extern __shared__ __align__(16) float dsm[];
    float* sHf  = dsm;                 // [2][32][130]
    float* sWop = dsm + 2*4160;        // 256
    float* Bbuf0 = sWop + 256;         // 5120
    float* Bbuf1 = Bbuf0 + 5120;

    int tid = threadIdx.x;
    int w = tid >> 5, lane = tid & 31;
    int gr = lane >> 2, ct = lane & 3;
    int jx = gr & 1, ul = gr >> 1;
    int b0h = blockIdx.x * 32;

    for (int i = tid; i < 10240; i += 512) Bbuf0[i] = 0.f;
    if (tid < 256) sWop[tid] = Wop[tid];

    // per-item pre: item (m,nb) -> unit 4*(w+16m)+ul, hero 8nb+2ct+jx
    float pre[4][8];
#pragma unroll
    for (int m = 0; m < 2; ++m) {
        int unit = 4*(w + 16*m) + ul;
#pragma unroll
        for (int nb = 0; nb < 4; ++nb) {
            int hero = 8*nb + 2*ct + jx;
#pragma unroll
            for (int g = 0; g < 4; ++g)
                pre[g][m*4+nb] = __ldg(&g_preT[(size_t)(g*128 + unit)*NB + b0h + hero]);
        }
    }

    float c[8];
#pragma unroll
    for (int i = 0; i < 8; ++i) c[i] = 0.f;
    __syncthreads();

    for (int t = 0; t < T_OUT; ++t) {
        const float* Bc = (t & 1) ? Bbuf1 : Bbuf0;
        float* Bn = (t & 1) ? Bbuf0 : Bbuf1;
        float* sHfW = sHf + (t & 1)*4160;

        float acc[2][4][4];
#pragma unroll
        for (int m = 0; m < 2; ++m)
#pragma unroll
            for (int nb = 0; nb < 4; ++nb)
#pragma unroll
                for (int r = 0; r < 4; ++r) acc[m][nb][r] = 0.f;

#pragma unroll
        for (int ks = 0; ks < 8; ++ks) {
            const float* bbase = Bc + (ks*32 + lane)*20;
            uint2 bv[4];
#pragma unroll
            for (int nb = 0; nb < 4; ++nb) bv[nb] = *(const uint2*)(bbase + nb*4);
#pragma unroll
            for (int m = 0; m < 2; ++m) {
                int mt = w + 16*m;
                uint4 ahi = __ldg(&g_A[((mt*8 + ks)*2 + 0)*32 + lane]);
#pragma unroll
                for (int nb = 0; nb < 4; ++nb)
                    MMA(acc[m][nb], ahi, bv[nb].x, bv[nb].y);
            }
        }
        // shfl gate exchange + LSTM + writes
#pragma unroll
        for (int m = 0; m < 2; ++m) {
            int unit = 4*(w + 16*m) + ul;
#pragma unroll
            for (int nb = 0; nb < 4; ++nb) {
                float c0 = acc[m][nb][0], c1 = acc[m][nb][1];
                float c2 = acc[m][nb][2], c3 = acc[m][nb][3];
                float sAv = jx ? c0 : c1;
                float sBv = jx ? c2 : c3;
                float rA = __shfl_xor_sync(0xffffffffu, sAv, 4);
                float rB = __shfl_xor_sync(0xffffffffu, sBv, 4);
                float g0 = jx ? rA : c0;
                float g1 = jx ? c1 : rA;
                float g2 = jx ? rB : c2;
                float g3 = jx ? c3 : rB;
                int it = m*4 + nb;
                float gi = g0 + pre[0][it];
                float gf = g1 + pre[1][it];
                float gg = g2 + pre[2][it];
                float go = g3 + pre[3][it];
                c[it] = fmaf(sigf(gf), c[it], sigf(gi)*tanh_fast(gg));
                float hv = sigf(go)*tanh_fast(c[it]);
                int hero = 8*nb + 2*ct + jx;
                sHfW[hero*130 + unit] = hv;
                bfrag_store_hi(Bn, unit, hero, hv);
            }
        }
        __syncthreads();
        // output projection (overlaps next step's MMA on other warps)
        if (tid < 64) {
            int hero = tid >> 1, d = tid & 1;
            u64 a2 = lo2(__ldg(bop + d));
            const u64* wo = (const u64*)(sWop + d*128);
            const u64* hr = (const u64*)(sHfW + hero*130);
#pragma unroll
            for (int k2 = 0; k2 < 64; ++k2) fma2(a2, wo[k2], hr[k2]);
            out[(size_t)t*NB*2 + (size_t)(b0h + hero)*2 + d] = red2(a2);
        }
    }
}

// ============================================================
extern "C" void kernel_launch(void* const* d_in, const int* in_sizes, int n_in,
                              void* d_out, int out_size)
{
    const float* hist  = (const float*)d_in[0];
    const float* nbrs  = (const float*)d_in[1];
    const float* Wip   = (const float*)d_in[2];
    const float* bip   = (const float*)d_in[3];
    const float* Wih_e = (const float*)d_in[4];
    const float* Whh_e = (const float*)d_in[5];
    const float* bih_e = (const float*)d_in[6];
    const float* bhh_e = (const float*)d_in[7];
    const float* Wdyn  = (const float*)d_in[8];
    const float* bdyn  = (const float*)d_in[9];
    const float* Wnbr  = (const float*)d_in[10];
    const float* bnbr  = (const float*)d_in[11];
    const float* Wih_d = (const float*)d_in[12];
    const float* Whh_d = (const float*)d_in[13];
    const float* bih_d = (const float*)d_in[14];
    const float* bhh_d = (const float*)d_in[15];
    const float* Wop   = (const float*)d_in[16];
    const float* bop   = (const float*)d_in[17];
    const int*   seg   = (const int*)d_in[18];
    float* out = (float*)d_out;

    constexpr int FRONT_SMEM = (8704 + 2*3840 + 2048 + 2112 + 2048) * (int)sizeof(float);
    constexpr int DEC_SMEM = (2*4160 + 256 + 2*5120) * (int)sizeof(float);
    cudaFuncSetAttribute(front_kernel, cudaFuncAttributeMaxDynamicSharedMemorySize, FRONT_SMEM);
    cudaFuncSetAttribute(dec_kernel, cudaFuncAttributeMaxDynamicSharedMemorySize, DEC_SMEM);

    prep_kernel<<<120, 256>>>(Whh_d, Wih_d, Whh_e, Wih_e);
    front_kernel<<<NB/FHL, 256, FRONT_SMEM>>>(hist, nbrs, Wip, bip,
                                              bih_e, bhh_e, Wdyn, bdyn, Wnbr, bnbr,
                                              bih_d, bhh_d, seg);
    dec_kernel<<<NB/32, 512, DEC_SMEM>>>(Wop, bop, out);
}

// round 13
// speedup vs baseline: 5.9409x; 1.2289x over previous
#include <cuda_runtime.h>
#include <cuda_fp16.h>
#include <cstdint>

#define T_IN 16
#define T_OUT 25
#define NB 4096
#define KN 32
#define NNBR (NB*KN)
#define ENC 64
#define DEC 128
#define DYN 32
#define EMB 32
#define FHL 32

typedef unsigned long long u64;

// -------- scratch --------
__device__ __align__(16) float g_Wd4[4*DEC*(2*DYN)];        // quad-transposed Wih_d
__device__ __align__(16) uint4 g_A[32*8*2*32];              // dec Whh_d frags (hi/lo)
__device__ __align__(16) uint4 g_Ae[16*6*2*32];             // enc [Whh_e|Wih_e] frags (hi/lo)

__device__ __forceinline__ float lrelu(float x){ return x >= 0.f ? x : 0.1f*x; }
__device__ __forceinline__ float tanha(float x){
    float r; asm("tanh.approx.f32 %0, %1;" : "=f"(r) : "f"(x)); return r;
}
__device__ __forceinline__ float sig_t(float x){ return fmaf(0.5f, tanha(0.5f*x), 0.5f); }

__device__ __forceinline__ void fma2(u64& d, u64 a, u64 b){
    asm("fma.rn.f32x2 %0, %1, %2, %0;" : "+l"(d) : "l"(a), "l"(b));
}
__device__ __forceinline__ u64 packf2(float x, float y){
    u64 r; asm("mov.b64 %0, {%1,%2};" : "=l"(r) : "f"(x), "f"(y)); return r;
}
__device__ __forceinline__ float red2(u64 a){
    float x, y; asm("mov.b64 {%0,%1}, %2;" : "=f"(x), "=f"(y) : "l"(a)); return x + y;
}
__device__ __forceinline__ u64 lo2(float x){ return (u64)__float_as_uint(x); }

#define MMA(d, a, bx, by) \
    asm volatile("mma.sync.aligned.m16n8k16.row.col.f32.f16.f16.f32 " \
        "{%0,%1,%2,%3},{%4,%5,%6,%7},{%8,%9},{%0,%1,%2,%3};" \
        : "+f"((d)[0]), "+f"((d)[1]), "+f"((d)[2]), "+f"((d)[3]) \
        : "r"((a).x), "r"((a).y), "r"((a).z), "r"((a).w), "r"(bx), "r"(by))

__device__ __forceinline__ unsigned ph2(float a, float b, int hl){
    __half ah = __float2half_rn(a), bh = __float2half_rn(b);
    __half x = hl ? __float2half_rn(a - __half2float(ah)) : ah;
    __half y = hl ? __float2half_rn(b - __half2float(bh)) : bh;
    return (unsigned)__half_as_ushort(x) | ((unsigned)__half_as_ushort(y) << 16);
}

__device__ __forceinline__ void bfrag_store(float* Bn, int k, int n, float v){
    __half hhi = __float2half_rn(v);
    __half hlo = __float2half_rn(v - __half2float(hhi));
    int ks2 = k >> 4, kk = k & 15;
    int rg = kk >> 3, ctq = (kk & 7) >> 1, dl = kk & 1;
    int lp = (n & 7)*4 + ctq, nbl = n >> 3;
    char* bptr = (char*)(Bn + (ks2*32 + lp)*20) + nbl*16 + rg*4 + dl*2;
    *(__half*)bptr = hhi;
    *(__half*)(bptr + 8) = hlo;
}
__device__ __forceinline__ void bfrag_store_hi(float* Bn, int k, int n, float v){
    __half hhi = __float2half_rn(v);
    int ks2 = k >> 4, kk = k & 15;
    int rg = kk >> 3, ctq = (kk & 7) >> 1, dl = kk & 1;
    int lp = (n & 7)*4 + ctq, nbl = n >> 3;
    char* bptr = (char*)(Bn + (ks2*32 + lp)*20) + nbl*16 + rg*4 + dl*2;
    *(__half*)bptr = hhi;
}

// ============================================================
// Kernel 0: fragment weights, gate-pair interleave (unchanged from R12).
// ============================================================
__global__ void prep_kernel(const float* __restrict__ WhhD, const float* __restrict__ WihD,
                            const float* __restrict__ WhhE, const float* __restrict__ WihE)
{
    int idx = blockIdx.x*256 + threadIdx.x;
    if (idx < 16384) {
        int mt = idx >> 9, ks = (idx >> 6) & 7, hl = (idx >> 5) & 1, l = idx & 31;
        int gr = l >> 2, ct = l & 3;
        int unit = 4*mt + (gr >> 1);
        int r0 = (gr & 1)*128 + unit;
        int r1 = r0 + 256;
        int k0 = 16*ks + 2*ct;
        uint4 v;
        v.x = ph2(WhhD[r0*128 + k0],     WhhD[r0*128 + k0 + 1], hl);
        v.y = ph2(WhhD[r1*128 + k0],     WhhD[r1*128 + k0 + 1], hl);
        v.z = ph2(WhhD[r0*128 + k0 + 8], WhhD[r0*128 + k0 + 9], hl);
        v.w = ph2(WhhD[r1*128 + k0 + 8], WhhD[r1*128 + k0 + 9], hl);
        g_A[((mt*8 + ks)*2 + hl)*32 + l] = v;
    } else if (idx < 24576) {
        int j = idx - 16384;
        int k4 = j >> 9, r = j & 511;
        float4 v = *(const float4*)(WihD + r*(2*DYN) + k4*4);
        *(float4*)(g_Wd4 + ((size_t)k4*512 + r)*4) = v;
    } else {
        int j2 = idx - 24576;
        int mt = j2 / 384;
        int rem = j2 - mt*384;
        int ks = rem >> 6, hl = (rem >> 5) & 1, l = rem & 31;
        int gr = l >> 2, ct = l & 3;
        int unit = 4*mt + (gr >> 1);
        int g0 = gr & 1, g1 = g0 + 2;
        int k0 = 16*ks + 2*ct;
        auto W = [&](int gate, int k) -> float {
            int row = gate*64 + unit;
            return (k < 64) ? WhhE[row*64 + k] : WihE[row*32 + (k - 64)];
        };
        uint4 v;
        v.x = ph2(W(g0,k0),   W(g0,k0+1), hl);
        v.y = ph2(W(g1,k0),   W(g1,k0+1), hl);
        v.z = ph2(W(g0,k0+8), W(g0,k0+9), hl);
        v.w = ph2(W(g1,k0+8), W(g1,k0+9), hl);
        g_Ae[((mt*6 + ks)*2 + hl)*32 + l] = v;
    }
}

// ============================================================
// FUSED kernel: nbr MLP+max -> HMMA encoder -> Wdyn proj -> dec-input GEMM
// -> HMMA decoder LSTM + output. 32 heroes/block, 512 threads, grid 128.
// smem 172 KB (occupancy 1).
// ============================================================
__global__ void __launch_bounds__(512, 1) fused_kernel(
        const float* __restrict__ hist, const float* __restrict__ nbrs,
        const float* __restrict__ Wip,  const float* __restrict__ bip,
        const float* __restrict__ bih,  const float* __restrict__ bhh,
        const float* __restrict__ Wdyn, const float* __restrict__ bdyn,
        const float* __restrict__ Wnbr, const float* __restrict__ bnbr,
        const float* __restrict__ bih_d,const float* __restrict__ bhh_d,
        const float* __restrict__ Wop,  const float* __restrict__ bop,
        const int* __restrict__ seg,    float* __restrict__ out)
{
    extern __shared__ __align__(16) float sm[];
    float* sPre = sm;              // [512][33] 16896 (dec input, persists C->dec)
    float* sMax = sm + 16896;      // [32][64] 2048
    float* sHT  = sMax + 2048;     // [64][33] 2112 (final enc h)
    float* sWk  = sHT + 2112;      // 2112 overlay: Wnbr+bnbr / WdynT
    float* sEnc = sWk + 2112;      // 2048
    float* sBb  = sEnc + 2048;     // 10240: encB 2x3840 | decB 2x5120
    float* sHf  = sBb + 10240;     // [2][32][130] 8320
    float* sWop = sHf + 8320;      // 256

    int tid = threadIdx.x;
    int b0 = blockIdx.x * FHL;
    int warp = tid >> 5, lane = tid & 31;
    int gr = lane >> 2, ct = lane & 3;
    int jx = gr & 1, ul = gr >> 1;

    // ---------------- Phase A: neighbor MLP + segment max ----------------
    for (int i = tid; i < 2112; i += 512) sWk[i] = (i < 2048) ? Wnbr[i] : bnbr[i - 2048];
    __syncthreads();
#pragma unroll
    for (int p = 0; p < 2; ++p) {
        int hero = warp + p*16;
        int n = (b0 + hero)*KN + lane;
        int sgid = seg[n];
        u64 xp[16];
#pragma unroll
        for (int t = 0; t < T_IN; ++t) {
            float2 hv = *(const float2*)(hist + ((size_t)t*NB + sgid)*2);
            float2 nv = *(const float2*)(nbrs + ((size_t)t*NNBR + n)*2);
            xp[t] = packf2(hv.x - nv.x, hv.y - nv.y);
        }
#pragma unroll 4
        for (int g = 0; g < ENC; ++g) {
            u64 a2 = lo2(sWk[2048 + g]);
            const ulonglong2* w = (const ulonglong2*)(sWk + g*32);
#pragma unroll
            for (int k = 0; k < 8; ++k) {
                ulonglong2 wv = w[k];
                fma2(a2, wv.x, xp[2*k]);
                fma2(a2, wv.y, xp[2*k+1]);
            }
            float acc = lrelu(red2(a2));
#pragma unroll
            for (int off = 16; off; off >>= 1)
                acc = fmaxf(acc, __shfl_xor_sync(0xffffffffu, acc, off));
            if (lane == 0) sMax[hero*ENC + g] = acc;
        }
    }
    __syncthreads();

    // ---------------- Phase B: HMMA encoder (2-term), shfl epilogue ----------------
    for (int i = tid; i < 7680; i += 512) sBb[i] = 0.f;
    // bias sums: warp = M-tile, unit = 4*warp + ul, items = nb (0..3)
    float bsum[4][4];
    {
        int unit = 4*warp + ul;
#pragma unroll
        for (int g = 0; g < 4; ++g) {
            float bs = __ldg(bih + g*64 + unit) + __ldg(bhh + g*64 + unit);
#pragma unroll
            for (int nb = 0; nb < 4; ++nb) bsum[g][nb] = bs;
        }
    }
    int nn = tid & 31;
    int jb = ((tid >> 5) & 7) * 4;
    float wj0[4], wj1[4], bj[4];
#pragma unroll
    for (int jj = 0; jj < 4; ++jj) {
        wj0[jj] = Wip[(jb+jj)*2]; wj1[jj] = Wip[(jb+jj)*2+1]; bj[jj] = bip[jb+jj];
    }
    float cE[4];
#pragma unroll
    for (int i = 0; i < 4; ++i) cE[i] = 0.f;
    __syncthreads();
    if (tid < 256) {
        float2 hv = *(const float2*)(hist + ((size_t)(b0 + nn))*2);
#pragma unroll
        for (int jj = 0; jj < 4; ++jj) {
            float e = lrelu(fmaf(wj0[jj], hv.x, fmaf(wj1[jj], hv.y, bj[jj])));
            bfrag_store(sBb, 64 + jb + jj, nn, e);
        }
    }
    __syncthreads();

#pragma unroll 1
    for (int t = 0; t < T_IN; ++t) {
        float* Bc = sBb + (t & 1)*3840;
        float* Bn = sBb + ((t & 1) ^ 1)*3840;
        float acc[4][4];
#pragma unroll
        for (int nb = 0; nb < 4; ++nb)
#pragma unroll
            for (int r = 0; r < 4; ++r) acc[nb][r] = 0.f;
#pragma unroll
        for (int ks = 0; ks < 6; ++ks) {
            const uint4* bp = (const uint4*)(Bc + (ks*32 + lane)*20);
            uint4 bv[4];
#pragma unroll
            for (int nb = 0; nb < 4; ++nb) bv[nb] = bp[nb];
            uint4 ahi = __ldg(&g_Ae[((warp*6 + ks)*2 + 0)*32 + lane]);
#pragma unroll
            for (int nb = 0; nb < 4; ++nb) {
                MMA(acc[nb], ahi, bv[nb].x, bv[nb].y);
                MMA(acc[nb], ahi, bv[nb].z, bv[nb].w);
            }
        }
        {
            int unit = 4*warp + ul;
#pragma unroll
            for (int nb = 0; nb < 4; ++nb) {
                float c0 = acc[nb][0], c1 = acc[nb][1];
                float c2 = acc[nb][2], c3 = acc[nb][3];
                float sAv = jx ? c0 : c1;
                float sBv = jx ? c2 : c3;
                float rA = __shfl_xor_sync(0xffffffffu, sAv, 4);
                float rB = __shfl_xor_sync(0xffffffffu, sBv, 4);
                float g0 = jx ? rA : c0;
                float g1 = jx ? c1 : rA;
                float g2 = jx ? rB : c2;
                float g3 = jx ? c3 : rB;
                float gi = g0 + bsum[0][nb];
                float gf = g1 + bsum[1][nb];
                float gg = g2 + bsum[2][nb];
                float go = g3 + bsum[3][nb];
                cE[nb] = fmaf(sig_t(gf), cE[nb], sig_t(gi)*tanha(gg));
                float hv = sig_t(go)*tanha(cE[nb]);
                int hero = 8*nb + 2*ct + jx;
                bfrag_store(Bn, unit, hero, hv);
                if (t == T_IN - 1) sHT[unit*33 + hero] = hv;
            }
        }
        if (t < T_IN - 1 && tid < 256) {
            float2 hv2 = *(const float2*)(hist + ((size_t)(t+1)*NB + b0 + nn)*2);
#pragma unroll
            for (int jj = 0; jj < 4; ++jj) {
                float e = lrelu(fmaf(wj0[jj], hv2.x, fmaf(wj1[jj], hv2.y, bj[jj])));
                bfrag_store(Bn, 64 + jb + jj, nn, e);
            }
        }
        __syncthreads();
    }

    // ---------------- Phase C: Wdyn projections + dec-input GEMM ----------------
    for (int i = tid; i < DYN*ENC; i += 512) {
        int r = i >> 6, cc = i & 63;
        sWk[cc*32 + r] = Wdyn[i];
    }
    __syncthreads();
#pragma unroll
    for (int pass = 0; pass < 4; ++pass) {
        int it = tid + pass*512;          // 2048 items = 32 heroes x 64 outputs
        int hero = it >> 6, o = it & 63;
        int row = o & 31;
        float a = __ldg(bdyn + row);
        if (o < 32) {
#pragma unroll 8
            for (int k = 0; k < 64; ++k) a = fmaf(sWk[k*32 + row], sHT[k*33 + hero], a);
        } else {
#pragma unroll 8
            for (int k = 0; k < 64; ++k) a = fmaf(sWk[k*32 + row], sMax[hero*64 + k], a);
        }
        sEnc[hero*64 + o] = lrelu(a);
    }
    __syncthreads();
    {
        int r = tid;
        float bs = __ldg(bih_d + r) + __ldg(bhh_d + r);
#pragma unroll
        for (int hp = 0; hp < 2; ++hp) {
            u64 acc2[16];
#pragma unroll
            for (int hl = 0; hl < 16; ++hl) acc2[hl] = lo2(bs);
#pragma unroll 4
            for (int k4 = 0; k4 < 16; ++k4) {
                ulonglong2 w = *(const ulonglong2*)(g_Wd4 + ((size_t)k4*512 + r)*4);
#pragma unroll
                for (int hl = 0; hl < 16; ++hl) {
                    ulonglong2 e = *(const ulonglong2*)(sEnc + (hp*16 + hl)*64 + k4*4);
                    fma2(acc2[hl], w.x, e.x);
                    fma2(acc2[hl], w.y, e.y);
                }
            }
#pragma unroll
            for (int hl = 0; hl < 16; ++hl)
                sPre[r*33 + hp*16 + hl] = red2(acc2[hl]);
        }
    }
    // zero dec B buffers (enc B data dead), load Wop
    for (int i = tid; i < 10240; i += 512) sBb[i] = 0.f;
    if (tid < 256) sWop[tid] = Wop[tid];
    __syncthreads();

    // ---------------- Dec phase: HMMA decoder (1-term), shfl epilogue ----------------
    float pre[4][8];
#pragma unroll
    for (int m = 0; m < 2; ++m) {
        int unit = 4*(warp + 16*m) + ul;
#pragma unroll
        for (int nb = 0; nb < 4; ++nb) {
            int hero = 8*nb + 2*ct + jx;
#pragma unroll
            for (int g = 0; g < 4; ++g)
                pre[g][m*4+nb] = sPre[(g*128 + unit)*33 + hero];
        }
    }
    float c[8];
#pragma unroll
    for (int i = 0; i < 8; ++i) c[i] = 0.f;
    __syncthreads();

    for (int t = 0; t < T_OUT; ++t) {
        const float* Bc = sBb + (t & 1)*5120;
        float* Bn = sBb + ((t & 1) ^ 1)*5120;
        float* sHfW = sHf + (t & 1)*4160;

        float acc[2][4][4];
#pragma unroll
        for (int m = 0; m < 2; ++m)
#pragma unroll
            for (int nb = 0; nb < 4; ++nb)
#pragma unroll
                for (int r = 0; r < 4; ++r) acc[m][nb][r] = 0.f;

#pragma unroll
        for (int ks = 0; ks < 8; ++ks) {
            const float* bbase = Bc + (ks*32 + lane)*20;
            uint2 bv[4];
#pragma unroll
            for (int nb = 0; nb < 4; ++nb) bv[nb] = *(const uint2*)(bbase + nb*4);
#pragma unroll
            for (int m = 0; m < 2; ++m) {
                int mt = warp + 16*m;
                uint4 ahi = __ldg(&g_A[((mt*8 + ks)*2 + 0)*32 + lane]);
#pragma unroll
                for (int nb = 0; nb < 4; ++nb)
                    MMA(acc[m][nb], ahi, bv[nb].x, bv[nb].y);
            }
        }
#pragma unroll
        for (int m = 0; m < 2; ++m) {
            int unit = 4*(warp + 16*m) + ul;
#pragma unroll
            for (int nb = 0; nb < 4; ++nb) {
                float c0 = acc[m][nb][0], c1 = acc[m][nb][1];
                float c2 = acc[m][nb][2], c3 = acc[m][nb][3];
                float sAv = jx ? c0 : c1;
                float sBv = jx ? c2 : c3;
                float rA = __shfl_xor_sync(0xffffffffu, sAv, 4);
                float rB = __shfl_xor_sync(0xffffffffu, sBv, 4);
                float g0 = jx ? rA : c0;
                float g1 = jx ? c1 : rA;
                float g2 = jx ? rB : c2;
                float g3 = jx ? c3 : rB;
                int it = m*4 + nb;
                float gi = g0 + pre[0][it];
                float gf = g1 + pre[1][it];
                float gg = g2 + pre[2][it];
                float go = g3 + pre[3][it];
                c[it] = fmaf(sig_t(gf), c[it], sig_t(gi)*tanha(gg));
                float hv = sig_t(go)*tanha(c[it]);
                int hero = 8*nb + 2*ct + jx;
                sHfW[hero*130 + unit] = hv;
                bfrag_store_hi(Bn, unit, hero, hv);
            }
        }
        __syncthreads();
        if (tid < 64) {
            int hero = tid >> 1, d = tid & 1;
            u64 a2 = lo2(__ldg(bop + d));
            const u64* wo = (const u64*)(sWop + d*128);
            const u64* hr = (const u64*)(sHfW + hero*130);
#pragma unroll
            for (int k2 = 0; k2 < 64; ++k2) fma2(a2, wo[k2], hr[k2]);
            out[(size_t)t*NB*2 + (size_t)(b0 + hero)*2 + d] = red2(a2);
        }
    }
}

// ============================================================
extern "C" void kernel_launch(void* const* d_in, const int* in_sizes, int n_in,
                              void* d_out, int out_size)
{
    const float* hist  = (const float*)d_in[0];
    const float* nbrs  = (const float*)d_in[1];
    const float* Wip   = (const float*)d_in[2];
    const float* bip   = (const float*)d_in[3];
    const float* Wih_e = (const float*)d_in[4];
    const float* Whh_e = (const float*)d_in[5];
    const float* bih_e = (const float*)d_in[6];
    const float* bhh_e = (const float*)d_in[7];
    const float* Wdyn  = (const float*)d_in[8];
    const float* bdyn  = (const float*)d_in[9];
    const float* Wnbr  = (const float*)d_in[10];
    const float* bnbr  = (const float*)d_in[11];
    const float* Wih_d = (const float*)d_in[12];
    const float* Whh_d = (const float*)d_in[13];
    const float* bih_d = (const float*)d_in[14];
    const float* bhh_d = (const float*)d_in[15];
    const float* Wop   = (const float*)d_in[16];
    const float* bop   = (const float*)d_in[17];
    const int*   seg   = (const int*)d_in[18];
    float* out = (float*)d_out;

    constexpr int FUSED_SMEM = 44032 * (int)sizeof(float);   // 176128 B
    cudaFuncSetAttribute(fused_kernel, cudaFuncAttributeMaxDynamicSharedMemorySize, FUSED_SMEM);

    prep_kernel<<<120, 256>>>(Whh_d, Wih_d, Whh_e, Wih_e);
    fused_kernel<<<NB/FHL, 512, FUSED_SMEM>>>(hist, nbrs, Wip, bip,
                                              bih_e, bhh_e, Wdyn, bdyn, Wnbr, bnbr,
                                              bih_d, bhh_d, Wop, bop, seg, out);
}

// round 15
// speedup vs baseline: 5.9581x; 1.0029x over previous
#include <cuda_runtime.h>
#include <cuda_fp16.h>
#include <cstdint>

#define T_IN 16
#define T_OUT 25
#define NB 4096
#define KN 32
#define NNBR (NB*KN)
#define ENC 64
#define DEC 128
#define DYN 32
#define EMB 32
#define FHL 32

typedef unsigned long long u64;

// -------- scratch --------
__device__ __align__(16) float g_Wd4[4*DEC*(2*DYN)];        // quad-transposed Wih_d
__device__ __align__(16) uint4 g_A[32*8*2*32];              // dec Whh_d frags (hi/lo)
__device__ __align__(16) uint4 g_Ae[16*6*2*32];             // enc [Whh_e|Wih_e] frags (hi/lo)

__device__ __forceinline__ float lrelu(float x){ return x >= 0.f ? x : 0.1f*x; }
__device__ __forceinline__ float tanha(float x){
    float r; asm("tanh.approx.f32 %0, %1;" : "=f"(r) : "f"(x)); return r;
}
__device__ __forceinline__ float sig_t(float x){ return fmaf(0.5f, tanha(0.5f*x), 0.5f); }

__device__ __forceinline__ void fma2(u64& d, u64 a, u64 b){
    asm("fma.rn.f32x2 %0, %1, %2, %0;" : "+l"(d) : "l"(a), "l"(b));
}
__device__ __forceinline__ u64 packf2(float x, float y){
    u64 r; asm("mov.b64 %0, {%1,%2};" : "=l"(r) : "f"(x), "f"(y)); return r;
}
__device__ __forceinline__ float red2(u64 a){
    float x, y; asm("mov.b64 {%0,%1}, %2;" : "=f"(x), "=f"(y) : "l"(a)); return x + y;
}
__device__ __forceinline__ u64 lo2(float x){ return (u64)__float_as_uint(x); }

#define MMA(d, a, bx, by) \
    asm volatile("mma.sync.aligned.m16n8k16.row.col.f32.f16.f16.f32 " \
        "{%0,%1,%2,%3},{%4,%5,%6,%7},{%8,%9},{%0,%1,%2,%3};" \
        : "+f"((d)[0]), "+f"((d)[1]), "+f"((d)[2]), "+f"((d)[3]) \
        : "r"((a).x), "r"((a).y), "r"((a).z), "r"((a).w), "r"(bx), "r"(by))

__device__ __forceinline__ unsigned ph2(float a, float b, int hl){
    __half ah = __float2half_rn(a), bh = __float2half_rn(b);
    __half x = hl ? __float2half_rn(a - __half2float(ah)) : ah;
    __half y = hl ? __float2half_rn(b - __half2float(bh)) : bh;
    return (unsigned)__half_as_ushort(x) | ((unsigned)__half_as_ushort(y) << 16);
}

// encoder B store (hi+lo, 20-float row stride; uint4 loads are conflict-free)
__device__ __forceinline__ void bfrag_store(float* Bn, int k, int n, float v){
    __half hhi = __float2half_rn(v);
    __half hlo = __float2half_rn(v - __half2float(hhi));
    int ks2 = k >> 4, kk = k & 15;
    int rg = kk >> 3, ctq = (kk & 7) >> 1, dl = kk & 1;
    int lp = (n & 7)*4 + ctq, nbl = n >> 3;
    char* bptr = (char*)(Bn + (ks2*32 + lp)*20) + nbl*16 + rg*4 + dl*2;
    *(__half*)bptr = hhi;
    *(__half*)(bptr + 8) = hlo;
}
// decoder B store (hi-only, COMPACT 12-float row stride -> conflict-free uint4 loads)
__device__ __forceinline__ void bfrag_store_hi(float* Bn, int k, int n, float v){
    __half hhi = __float2half_rn(v);
    int ks2 = k >> 4, kk = k & 15;
    int rg = kk >> 3, ctq = (kk & 7) >> 1, dl = kk & 1;
    int lp = (n & 7)*4 + ctq, nbl = n >> 3;
    char* bptr = (char*)(Bn + (ks2*32 + lp)*12 + nbl*2 + rg) + dl*2;
    *(__half*)bptr = hhi;
}

// ============================================================
// Kernel 0: fragment weights, gate-pair interleave (unchanged).
// ============================================================
__global__ void prep_kernel(const float* __restrict__ WhhD, const float* __restrict__ WihD,
                            const float* __restrict__ WhhE, const float* __restrict__ WihE)
{
    int idx = blockIdx.x*256 + threadIdx.x;
    if (idx < 16384) {
        int mt = idx >> 9, ks = (idx >> 6) & 7, hl = (idx >> 5) & 1, l = idx & 31;
        int gr = l >> 2, ct = l & 3;
        int unit = 4*mt + (gr >> 1);
        int r0 = (gr & 1)*128 + unit;
        int r1 = r0 + 256;
        int k0 = 16*ks + 2*ct;
        uint4 v;
        v.x = ph2(WhhD[r0*128 + k0],     WhhD[r0*128 + k0 + 1], hl);
        v.y = ph2(WhhD[r1*128 + k0],     WhhD[r1*128 + k0 + 1], hl);
        v.z = ph2(WhhD[r0*128 + k0 + 8], WhhD[r0*128 + k0 + 9], hl);
        v.w = ph2(WhhD[r1*128 + k0 + 8], WhhD[r1*128 + k0 + 9], hl);
        g_A[((mt*8 + ks)*2 + hl)*32 + l] = v;
    } else if (idx < 24576) {
        int j = idx - 16384;
        int k4 = j >> 9, r = j & 511;
        float4 v = *(const float4*)(WihD + r*(2*DYN) + k4*4);
        *(float4*)(g_Wd4 + ((size_t)k4*512 + r)*4) = v;
    } else {
        int j2 = idx - 24576;
        int mt = j2 / 384;
        int rem = j2 - mt*384;
        int ks = rem >> 6, hl = (rem >> 5) & 1, l = rem & 31;
        int gr = l >> 2, ct = l & 3;
        int unit = 4*mt + (gr >> 1);
        int g0 = gr & 1, g1 = g0 + 2;
        int k0 = 16*ks + 2*ct;
        auto W = [&](int gate, int k) -> float {
            int row = gate*64 + unit;
            return (k < 64) ? WhhE[row*64 + k] : WihE[row*32 + (k - 64)];
        };
        uint4 v;
        v.x = ph2(W(g0,k0),   W(g0,k0+1), hl);
        v.y = ph2(W(g1,k0),   W(g1,k0+1), hl);
        v.z = ph2(W(g0,k0+8), W(g0,k0+9), hl);
        v.w = ph2(W(g1,k0+8), W(g1,k0+9), hl);
        g_Ae[((mt*6 + ks)*2 + hl)*32 + l] = v;
    }
}

// ============================================================
// FUSED kernel. 32 heroes/block, 512 threads, grid 128. smem 166 KB.
// ============================================================
__global__ void __launch_bounds__(512, 1) fused_kernel(
        const float* __restrict__ hist, const float* __restrict__ nbrs,
        const float* __restrict__ Wip,  const float* __restrict__ bip,
        const float* __restrict__ bih,  const float* __restrict__ bhh,
        const float* __restrict__ Wdyn, const float* __restrict__ bdyn,
        const float* __restrict__ Wnbr, const float* __restrict__ bnbr,
        const float* __restrict__ bih_d,const float* __restrict__ bhh_d,
        const float* __restrict__ Wop,  const float* __restrict__ bop,
        const int* __restrict__ seg,    float* __restrict__ out)
{
    extern __shared__ __align__(16) float sm[];
    float* sPre = sm;              // [512][33] 16896
    float* sMax = sm + 16896;      // [32][64] 2048
    float* sHT  = sMax + 2048;     // [64][33] 2112
    float* sWk  = sHT + 2112;      // 2112 overlay
    float* sEnc = sWk + 2112;      // 2048
    float* sBb  = sEnc + 2048;     // 7680: encB 2x3840 | decB 2x3072
    float* sHf  = sBb + 7680;      // [2][32][130] 8320
    float* sWop = sHf + 8320;      // 256

    int tid = threadIdx.x;
    int b0 = blockIdx.x * FHL;
    int warp = tid >> 5, lane = tid & 31;
    int gr = lane >> 2, ct = lane & 3;
    int jx = gr & 1, ul = gr >> 1;

    // ---------------- Phase A: neighbor MLP + segment max ----------------
    for (int i = tid; i < 2112; i += 512) sWk[i] = (i < 2048) ? Wnbr[i] : bnbr[i - 2048];
    __syncthreads();
#pragma unroll
    for (int p = 0; p < 2; ++p) {
        int hero = warp + p*16;
        int n = (b0 + hero)*KN + lane;
        int sgid = seg[n];
        u64 xp[16];
#pragma unroll
        for (int t = 0; t < T_IN; ++t) {
            float2 hv = *(const float2*)(hist + ((size_t)t*NB + sgid)*2);
            float2 nv = *(const float2*)(nbrs + ((size_t)t*NNBR + n)*2);
            xp[t] = packf2(hv.x - nv.x, hv.y - nv.y);
        }
#pragma unroll 4
        for (int g = 0; g < ENC; ++g) {
            u64 a2 = lo2(sWk[2048 + g]);
            const ulonglong2* w = (const ulonglong2*)(sWk + g*32);
#pragma unroll
            for (int k = 0; k < 8; ++k) {
                ulonglong2 wv = w[k];
                fma2(a2, wv.x, xp[2*k]);
                fma2(a2, wv.y, xp[2*k+1]);
            }
            float acc = lrelu(red2(a2));
#pragma unroll
            for (int off = 16; off; off >>= 1)
                acc = fmaxf(acc, __shfl_xor_sync(0xffffffffu, acc, off));
            if (lane == 0) sMax[hero*ENC + g] = acc;
        }
    }
    __syncthreads();

    // ---------------- Phase B: HMMA encoder (2-term), shfl epilogue ----------------
    for (int i = tid; i < 7680; i += 512) sBb[i] = 0.f;
    float bsum[4][4];
    {
        int unit = 4*warp + ul;
#pragma unroll
        for (int g = 0; g < 4; ++g) {
            float bs = __ldg(bih + g*64 + unit) + __ldg(bhh + g*64 + unit);
#pragma unroll
            for (int nb = 0; nb < 4; ++nb) bsum[g][nb] = bs;
        }
    }
    int nn = tid & 31;
    int jb = ((tid >> 5) & 7) * 4;
    float wj0[4], wj1[4], bj[4];
#pragma unroll
    for (int jj = 0; jj < 4; ++jj) {
        wj0[jj] = Wip[(jb+jj)*2]; wj1[jj] = Wip[(jb+jj)*2+1]; bj[jj] = bip[jb+jj];
    }
    float cE[4];
#pragma unroll
    for (int i = 0; i < 4; ++i) cE[i] = 0.f;
    __syncthreads();
    if (tid < 256) {
        float2 hv = *(const float2*)(hist + ((size_t)(b0 + nn))*2);
#pragma unroll
        for (int jj = 0; jj < 4; ++jj) {
            float e = lrelu(fmaf(wj0[jj], hv.x, fmaf(wj1[jj], hv.y, bj[jj])));
            bfrag_store(sBb, 64 + jb + jj, nn, e);
        }
    }
    __syncthreads();

#pragma unroll 1
    for (int t = 0; t < T_IN; ++t) {
        float* Bc = sBb + (t & 1)*3840;
        float* Bn = sBb + ((t & 1) ^ 1)*3840;
        float acc[4][4];
#pragma unroll
        for (int nb = 0; nb < 4; ++nb)
#pragma unroll
            for (int r = 0; r < 4; ++r) acc[nb][r] = 0.f;
#pragma unroll
        for (int ks = 0; ks < 6; ++ks) {
            const uint4* bp = (const uint4*)(Bc + (ks*32 + lane)*20);
            uint4 bv[4];
#pragma unroll
            for (int nb = 0; nb < 4; ++nb) bv[nb] = bp[nb];
            uint4 ahi = __ldg(&g_Ae[((warp*6 + ks)*2 + 0)*32 + lane]);
#pragma unroll
            for (int nb = 0; nb < 4; ++nb) {
                MMA(acc[nb], ahi, bv[nb].x, bv[nb].y);
                MMA(acc[nb], ahi, bv[nb].z, bv[nb].w);
            }
        }
        {
            int unit = 4*warp + ul;
#pragma unroll
            for (int nb = 0; nb < 4; ++nb) {
                float c0 = acc[nb][0], c1 = acc[nb][1];
                float c2 = acc[nb][2], c3 = acc[nb][3];
                float sAv = jx ? c0 : c1;
                float sBv = jx ? c2 : c3;
                float rA = __shfl_xor_sync(0xffffffffu, sAv, 4);
                float rB = __shfl_xor_sync(0xffffffffu, sBv, 4);
                float g0 = jx ? rA : c0;
                float g1 = jx ? c1 : rA;
                float g2 = jx ? rB : c2;
                float g3 = jx ? c3 : rB;
                float gi = g0 + bsum[0][nb];
                float gf = g1 + bsum[1][nb];
                float gg = g2 + bsum[2][nb];
                float go = g3 + bsum[3][nb];
                cE[nb] = fmaf(sig_t(gf), cE[nb], sig_t(gi)*tanha(gg));
                float hv = sig_t(go)*tanha(cE[nb]);
                int hero = 8*nb + 2*ct + jx;
                bfrag_store(Bn, unit, hero, hv);
                if (t == T_IN - 1) sHT[unit*33 + hero] = hv;
            }
        }
        if (t < T_IN - 1 && tid < 256) {
            float2 hv2 = *(const float2*)(hist + ((size_t)(t+1)*NB + b0 + nn)*2);
#pragma unroll
            for (int jj = 0; jj < 4; ++jj) {
                float e = lrelu(fmaf(wj0[jj], hv2.x, fmaf(wj1[jj], hv2.y, bj[jj])));
                bfrag_store(Bn, 64 + jb + jj, nn, e);
            }
        }
        __syncthreads();
    }

    // ---------------- Phase C: Wdyn projections + dec-input GEMM ----------------
    for (int i = tid; i < DYN*ENC; i += 512) {
        int r = i >> 6, cc = i & 63;
        sWk[cc*32 + r] = Wdyn[i];
    }
    __syncthreads();
#pragma unroll
    for (int pass = 0; pass < 4; ++pass) {
        int it = tid + pass*512;
        int hero = it >> 6, o = it & 63;
        int row = o & 31;
        float a = __ldg(bdyn + row);
        if (o < 32) {
#pragma unroll 8
            for (int k = 0; k < 64; ++k) a = fmaf(sWk[k*32 + row], sHT[k*33 + hero], a);
        } else {
#pragma unroll 8
            for (int k = 0; k < 64; ++k) a = fmaf(sWk[k*32 + row], sMax[hero*64 + k], a);
        }
        sEnc[hero*64 + o] = lrelu(a);
    }
    __syncthreads();
    {
        int r = tid;
        float bs = __ldg(bih_d + r) + __ldg(bhh_d + r);
#pragma unroll
        for (int hp = 0; hp < 2; ++hp) {
            u64 acc2[16];
#pragma unroll
            for (int hl = 0; hl < 16; ++hl) acc2[hl] = lo2(bs);
#pragma unroll 4
            for (int k4 = 0; k4 < 16; ++k4) {
                ulonglong2 w = *(const ulonglong2*)(g_Wd4 + ((size_t)k4*512 + r)*4);
#pragma unroll
                for (int hl = 0; hl < 16; ++hl) {
                    ulonglong2 e = *(const ulonglong2*)(sEnc + (hp*16 + hl)*64 + k4*4);
                    fma2(acc2[hl], w.x, e.x);
                    fma2(acc2[hl], w.y, e.y);
                }
            }
#pragma unroll
            for (int hl = 0; hl < 16; ++hl)
                sPre[r*33 + hp*16 + hl] = red2(acc2[hl]);
        }
    }
    // zero dec B buffers (2 x 3072), load Wop
    for (int i = tid; i < 6144; i += 512) sBb[i] = 0.f;
    if (tid < 256) sWop[tid] = Wop[tid];
    __syncthreads();

    // ---------------- Dec phase: HMMA decoder (1-term), shfl epilogue ----------------
    float pre[4][8];
#pragma unroll
    for (int m = 0; m < 2; ++m) {
        int unit = 4*(warp + 16*m) + ul;
#pragma unroll
        for (int nb = 0; nb < 4; ++nb) {
            int hero = 8*nb + 2*ct + jx;
#pragma unroll
            for (int g = 0; g < 4; ++g)
                pre[g][m*4+nb] = sPre[(g*128 + unit)*33 + hero];
        }
    }
    float c[8];
#pragma unroll
    for (int i = 0; i < 8; ++i) c[i] = 0.f;
    __syncthreads();

    for (int t = 0; t < T_OUT; ++t) {
        const float* Bc = sBb + (t & 1)*3072;
        float* Bn = sBb + ((t & 1) ^ 1)*3072;
        float* sHfW = sHf + (t & 1)*4160;

        float acc[2][4][4];
#pragma unroll
        for (int m = 0; m < 2; ++m)
#pragma unroll
            for (int nb = 0; nb < 4; ++nb)
#pragma unroll
                for (int r = 0; r < 4; ++r) acc[m][nb][r] = 0.f;

#pragma unroll
        for (int ks = 0; ks < 8; ++ks) {
            const float* bbase = Bc + (ks*32 + lane)*12;
            uint4 q0 = *(const uint4*)(bbase);       // nb0, nb1
            uint4 q1 = *(const uint4*)(bbase + 4);   // nb2, nb3
            uint2 bv[4];
            bv[0] = make_uint2(q0.x, q0.y);
            bv[1] = make_uint2(q0.z, q0.w);
            bv[2] = make_uint2(q1.x, q1.y);
            bv[3] = make_uint2(q1.z, q1.w);
#pragma unroll
            for (int m = 0; m < 2; ++m) {
                int mt = warp + 16*m;
                uint4 ahi = __ldg(&g_A[((mt*8 + ks)*2 + 0)*32 + lane]);
#pragma unroll
                for (int nb = 0; nb < 4; ++nb)
                    MMA(acc[m][nb], ahi, bv[nb].x, bv[nb].y);
            }
        }
#pragma unroll
        for (int m = 0; m < 2; ++m) {
            int unit = 4*(warp + 16*m) + ul;
#pragma unroll
            for (int nb = 0; nb < 4; ++nb) {
                float c0 = acc[m][nb][0], c1 = acc[m][nb][1];
                float c2 = acc[m][nb][2], c3 = acc[m][nb][3];
                float sAv = jx ? c0 : c1;
                float sBv = jx ? c2 : c3;
                float rA = __shfl_xor_sync(0xffffffffu, sAv, 4);
                float rB = __shfl_xor_sync(0xffffffffu, sBv, 4);
                float g0 = jx ? rA : c0;
                float g1 = jx ? c1 : rA;
                float g2 = jx ? rB : c2;
                float g3 = jx ? c3 : rB;
                int it = m*4 + nb;
                float gi = g0 + pre[0][it];
                float gf = g1 + pre[1][it];
                float gg = g2 + pre[2][it];
                float go = g3 + pre[3][it];
                c[it] = fmaf(sig_t(gf), c[it], sig_t(gi)*tanha(gg));
                float hv = sig_t(go)*tanha(c[it]);
                int hero = 8*nb + 2*ct + jx;
                sHfW[hero*130 + unit] = hv;
                bfrag_store_hi(Bn, unit, hero, hv);
            }
        }
        __syncthreads();
        if (tid < 64) {
            int hero = tid >> 1, d = tid & 1;
            u64 a2 = lo2(__ldg(bop + d));
            const u64* wo = (const u64*)(sWop + d*128);
            const u64* hr = (const u64*)(sHfW + hero*130);
#pragma unroll
            for (int k2 = 0; k2 < 64; ++k2) fma2(a2, wo[k2], hr[k2]);
            out[(size_t)t*NB*2 + (size_t)(b0 + hero)*2 + d] = red2(a2);
        }
    }
}

// ============================================================
extern "C" void kernel_launch(void* const* d_in, const int* in_sizes, int n_in,
                              void* d_out, int out_size)
{
    const float* hist  = (const float*)d_in[0];
    const float* nbrs  = (const float*)d_in[1];
    const float* Wip   = (const float*)d_in[2];
    const float* bip   = (const float*)d_in[3];
    const float* Wih_e = (const float*)d_in[4];
    const float* Whh_e = (const float*)d_in[5];
    const float* bih_e = (const float*)d_in[6];
    const float* bhh_e = (const float*)d_in[7];
    const float* Wdyn  = (const float*)d_in[8];
    const float* bdyn  = (const float*)d_in[9];
    const float* Wnbr  = (const float*)d_in[10];
    const float* bnbr  = (const float*)d_in[11];
    const float* Wih_d = (const float*)d_in[12];
    const float* Whh_d = (const float*)d_in[13];
    const float* bih_d = (const float*)d_in[14];
    const float* bhh_d = (const float*)d_in[15];
    const float* Wop   = (const float*)d_in[16];
    const float* bop   = (const float*)d_in[17];
    const int*   seg   = (const int*)d_in[18];
    float* out = (float*)d_out;

    constexpr int FUSED_SMEM = (16896 + 2048 + 2112 + 2112 + 2048 + 7680 + 8320 + 256)
                               * (int)sizeof(float);   // 165888 B
    cudaFuncSetAttribute(fused_kernel, cudaFuncAttributeMaxDynamicSharedMemorySize, FUSED_SMEM);

    prep_kernel<<<120, 256>>>(Whh_d, Wih_d, Whh_e, Wih_e);
    fused_kernel<<<NB/FHL, 512, FUSED_SMEM>>>(hist, nbrs, Wip, bip,
                                              bih_e, bhh_e, Wdyn, bdyn, Wnbr, bnbr,
                                              bih_d, bhh_d, Wop, bop, seg, out);
}